// round 2
// baseline (speedup 1.0000x reference)
#include <cuda_runtime.h>
#include <cuda_bf16.h>

// ---------------------------------------------------------------------------
// Problem constants
//   B=16, S=2048, N=256 (nodes incl. 0 => 257), E=4096, H=512, LD=16, ETR=768
//   D = 528, C1=3, GL=2, NLBL=15
// ---------------------------------------------------------------------------
#define BB    16
#define SS    2048
#define NN1   257          // N+1 nodes
#define NN1P  260          // padded row stride for adjacency (16B-aligned rows)
#define EE    4096
#define HH    512
#define LDD   16
#define ETRD  768
#define DD    528
#define NCLS  3
#define NLAY  2

#define XSZ   (BB*NN1*DD)           // 2,171,136
#define ASZ   (NCLS*BB*NN1*NN1P)    // padded adjacency
#define DEGSZ (NCLS*BB*NN1)         // 12,336

// ---------------------------------------------------------------------------
// Device scratch (static — no allocation allowed in kernel_launch)
// ---------------------------------------------------------------------------
__device__ float g_x0 [XSZ];
__device__ float g_h  [XSZ];
__device__ float g_xb [XSZ];
__device__ float g_res[XSZ];
__device__ float g_A  [ASZ];
__device__ float g_deg[DEGSZ];
__device__ float g_Who[DD*3];
__device__ float g_Wto[DD*3];
__device__ float g_bho[3];
__device__ float g_bto[3];
__device__ float g_hW [BB*NN1*3];
__device__ float g_hT [BB*NN1*3];

// ---------------------------------------------------------------------------
// Small helper kernels
// ---------------------------------------------------------------------------
__global__ void k_fill(float* __restrict__ p, int n, float v) {
    int i = blockIdx.x * blockDim.x + threadIdx.x;
    if (i < n) p[i] = v;
}

// label part: x0[b, i, 0:16]
__global__ void k_labels(float* __restrict__ x0,
                         const int* __restrict__ entLab,
                         const float* __restrict__ tbl) {
    int t = blockIdx.x * blockDim.x + threadIdx.x;     // 16*257*16
    if (t >= BB*NN1*LDD) return;
    int d = t & 15;
    int i = (t >> 4) % NN1;
    int b = t / (NN1*LDD);
    float v;
    if (i == 0) v = tbl[d];
    else {
        int lbl = entLab[b*(NN1-1) + i - 1];
        v = lbl ? tbl[lbl*LDD + d] : 0.f;
    }
    x0[((long long)(b*NN1 + i))*DD + d] = v;
}

// deg[c][b][dst] += 1 (init 1.0 => +1 self-loop already folded in)
__global__ void k_deg(float* __restrict__ deg,
                      const int* __restrict__ ei,
                      const int* __restrict__ ea) {
    int t = blockIdx.x * blockDim.x + threadIdx.x;     // 16*4096
    if (t >= BB*EE) return;
    int b = t >> 12, e = t & (EE-1);
    int dst = ei[b*2*EE + EE + e];
    int a   = ea[b*EE + e];
    atomicAdd(&deg[(a*BB + b)*NN1 + dst], 1.f);
}

// A[c][b][dst][src] += rsqrt(deg[src])*rsqrt(deg[dst])   (padded stride NN1P)
__global__ void k_adj(float* __restrict__ Am,
                      const float* __restrict__ deg,
                      const int* __restrict__ ei,
                      const int* __restrict__ ea) {
    int t = blockIdx.x * blockDim.x + threadIdx.x;
    if (t >= BB*EE) return;
    int b = t >> 12, e = t & (EE-1);
    int src = ei[b*2*EE + e];
    int dst = ei[b*2*EE + EE + e];
    int a   = ea[b*EE + e];
    const float* dg = deg + (a*BB + b)*NN1;
    float coef = rsqrtf(dg[src]) * rsqrtf(dg[dst]);
    atomicAdd(&Am[((long long)(a*BB + b)*NN1 + dst)*NN1P + src], coef);
}

// ---------------------------------------------------------------------------
// Big GEMM: red = emb @ W_red + b_red, fused relu + segment-max scatter.
// M=32768, K=768, N=512. All dims divisible by tile sizes -> no guards.
// ---------------------------------------------------------------------------
__global__ void __launch_bounds__(256) k_gemm_red(
    const float* __restrict__ A,      // emb  (32768 x 768)
    const float* __restrict__ Bm,     // W_red (768 x 512)
    const float* __restrict__ bias,   // b_red (512)
    const int*   __restrict__ entIdx, // (32768)
    float*       __restrict__ x0)     // (16,257,528)
{
    const int N = HH, K = ETRD;
    __shared__ float As[16][64];
    __shared__ float Bs[16][64];

    int tid  = threadIdx.x;
    int row0 = blockIdx.y * 64;
    int col0 = blockIdx.x * 64;
    int tm = (tid >> 4) << 2;
    int tn = (tid & 15) << 2;

    float acc[4][4];
    #pragma unroll
    for (int i = 0; i < 4; i++)
        #pragma unroll
        for (int j = 0; j < 4; j++) acc[i][j] = 0.f;

    int arow = tid >> 2, ak = (tid & 3) << 2;
    int brow = tid >> 4, bn = (tid & 15) << 2;

    for (int k0 = 0; k0 < K; k0 += 16) {
        float4 av = *(const float4*)(A + (long long)(row0 + arow)*K + k0 + ak);
        As[ak  ][arow] = av.x;
        As[ak+1][arow] = av.y;
        As[ak+2][arow] = av.z;
        As[ak+3][arow] = av.w;
        *(float4*)&Bs[brow][bn] =
            *(const float4*)(Bm + (long long)(k0 + brow)*N + col0 + bn);
        __syncthreads();
        #pragma unroll
        for (int kk = 0; kk < 16; kk++) {
            float4 a4 = *(const float4*)&As[kk][tm];
            float4 b4 = *(const float4*)&Bs[kk][tn];
            float aa[4] = {a4.x, a4.y, a4.z, a4.w};
            float bb[4] = {b4.x, b4.y, b4.z, b4.w};
            #pragma unroll
            for (int i = 0; i < 4; i++)
                #pragma unroll
                for (int j = 0; j < 4; j++) acc[i][j] += aa[i]*bb[j];
        }
        __syncthreads();
    }

    #pragma unroll
    for (int i = 0; i < 4; i++) {
        int gm = row0 + tm + i;
        int node = entIdx[gm];
        if (node == 0) continue;                 // segment 0 forced to zero
        int b = gm >> 11;                        // gm / 2048
        float* base = x0 + ((long long)(b*NN1 + node))*DD + LDD;
        #pragma unroll
        for (int j = 0; j < 4; j++) {
            int gn = col0 + tn + j;
            float v = fmaxf(acc[i][j] + bias[gn], 0.f);   // relu folded into max
            atomicMax((int*)(base + gn), __float_as_int(v)); // nonneg: int order==float order
        }
    }
}

// ---------------------------------------------------------------------------
// Generic batched SGEMM, 64x64x16 tile, 4x4 per thread, bounds-guarded,
// explicit leading dimensions (lda must make rows 16B-aligned or fall to
// the scalar path via guards — adjacency uses padded lda=260).
// mode 0: C = A@B
// mode 1: C = A@B + B[m,:]*(1/deg[b,m]) + bias[:]   (GCN epilogue; B is h, K==M)
//         optionally res += C
// ---------------------------------------------------------------------------
__global__ void __launch_bounds__(256) k_sgemm(
    const float* __restrict__ Abase, const float* __restrict__ Bbase,
    float* __restrict__ Cbase,
    int M, int N, int K,
    int lda, int ldb, int ldc,
    long long sA, long long sB, long long sC,
    int mode,
    const float* __restrict__ degBase,  // mode1: + b*257
    const float* __restrict__ bias,     // mode1
    float*       __restrict__ resBase)  // mode1, may be null
{
    int b = blockIdx.z;
    const float* A  = Abase + (long long)b*sA;
    const float* Bm = Bbase + (long long)b*sB;
    float* C = Cbase + (long long)b*sC;

    __shared__ float As[16][64];
    __shared__ float Bs[16][64];

    int tid  = threadIdx.x;
    int row0 = blockIdx.y * 64;
    int col0 = blockIdx.x * 64;
    int tm = (tid >> 4) << 2;
    int tn = (tid & 15) << 2;

    float acc[4][4];
    #pragma unroll
    for (int i = 0; i < 4; i++)
        #pragma unroll
        for (int j = 0; j < 4; j++) acc[i][j] = 0.f;

    int arow = tid >> 2, ak = (tid & 3) << 2;
    int brow = tid >> 4, bn = (tid & 15) << 2;

    for (int k0 = 0; k0 < K; k0 += 16) {
        int gm = row0 + arow, gk = k0 + ak;
        if (gm < M && gk + 3 < K) {
            float4 v = *(const float4*)(A + (long long)gm*lda + gk);
            As[ak  ][arow] = v.x;
            As[ak+1][arow] = v.y;
            As[ak+2][arow] = v.z;
            As[ak+3][arow] = v.w;
        } else {
            #pragma unroll
            for (int u = 0; u < 4; u++)
                As[ak+u][arow] = (gm < M && gk + u < K)
                               ? A[(long long)gm*lda + gk + u] : 0.f;
        }
        int gkb = k0 + brow, gn = col0 + bn;
        float4 bv = make_float4(0.f, 0.f, 0.f, 0.f);
        if (gkb < K && gn + 3 < N)
            bv = *(const float4*)(Bm + (long long)gkb*ldb + gn);
        else if (gkb < K) {
            float tmp[4];
            #pragma unroll
            for (int u = 0; u < 4; u++)
                tmp[u] = (gn + u < N) ? Bm[(long long)gkb*ldb + gn + u] : 0.f;
            bv = make_float4(tmp[0], tmp[1], tmp[2], tmp[3]);
        }
        *(float4*)&Bs[brow][bn] = bv;
        __syncthreads();
        #pragma unroll
        for (int kk = 0; kk < 16; kk++) {
            float4 a4 = *(const float4*)&As[kk][tm];
            float4 b4 = *(const float4*)&Bs[kk][tn];
            float aa[4] = {a4.x, a4.y, a4.z, a4.w};
            float bb[4] = {b4.x, b4.y, b4.z, b4.w};
            #pragma unroll
            for (int i = 0; i < 4; i++)
                #pragma unroll
                for (int j = 0; j < 4; j++) acc[i][j] += aa[i]*bb[j];
        }
        __syncthreads();
    }

    #pragma unroll
    for (int i = 0; i < 4; i++) {
        int gm = row0 + tm + i;
        if (gm >= M) continue;
        float dinv = 0.f;
        if (mode == 1) dinv = 1.f / degBase[b*NN1 + gm];
        #pragma unroll
        for (int j = 0; j < 4; j++) {
            int gn = col0 + tn + j;
            if (gn >= N) continue;
            long long idx = (long long)gm*ldc + gn;
            float v = acc[i][j];
            if (mode == 1) {
                v += Bm[(long long)gm*ldb + gn] * dinv + bias[gn]; // h[m,n]/deg[m] + b[n]
                C[idx] = v;
                if (resBase) resBase[(long long)b*sC + idx] += v;
            } else {
                C[idx] = v;
            }
        }
    }
}

// ---------------------------------------------------------------------------
// Collapsed head/tail projection: Who = W_head @ W_out (528x3), bho = b_head@W_out
// ---------------------------------------------------------------------------
__global__ void k_ho(const float* __restrict__ W_head, const float* __restrict__ W_tail,
                     const float* __restrict__ W_out,
                     const float* __restrict__ b_head, const float* __restrict__ b_tail,
                     float* __restrict__ Who, float* __restrict__ Wto,
                     float* __restrict__ bho, float* __restrict__ bto) {
    int t = blockIdx.x * blockDim.x + threadIdx.x;
    if (t < 2*DD*3) {
        int which = t / (DD*3), rc = t % (DD*3), r = rc / 3, c = rc % 3;
        const float* W = which ? W_tail : W_head;
        float acc = 0.f;
        for (int j = 0; j < DD; j++) acc += W[r*DD + j] * W_out[j*3 + c];
        (which ? Wto : Who)[r*3 + c] = acc;
    } else if (t < 2*DD*3 + 6) {
        int u = t - 2*DD*3, which = u / 3, c = u % 3;
        const float* bb = which ? b_tail : b_head;
        float acc = 0.f;
        for (int j = 0; j < DD; j++) acc += bb[j] * W_out[j*3 + c];
        (which ? bto : bho)[c] = acc;
    }
}

// hW[b,i,c] = (res[b,i,:]/3) @ Who[:,c] + bho[c]; same for tail
__global__ void k_hw(const float* __restrict__ res,
                     const float* __restrict__ Who, const float* __restrict__ Wto,
                     const float* __restrict__ bho, const float* __restrict__ bto,
                     float* __restrict__ hW, float* __restrict__ hT) {
    int t = blockIdx.x * blockDim.x + threadIdx.x;
    if (t >= 2*BB*NN1*3) return;
    int which = t / (BB*NN1*3);
    int rem = t % (BB*NN1*3);
    int bi = rem / 3, c = rem % 3;
    const float* row = res + (long long)bi*DD;
    const float* W   = which ? Wto : Who;
    float acc = 0.f;
    for (int k = 0; k < DD; k++) acc += row[k] * W[k*3 + c];
    acc = acc * (1.f/3.f) + (which ? bto[c] : bho[c]);
    (which ? hT : hW)[bi*3 + c] = acc;
}

// logits[b,i,j,c] = (hW[b,i,c]+hT[b,j+1,c]) * cands[b,i,j+1] + b_out[c]
__global__ void k_logits(const int* __restrict__ cands,
                         const float* __restrict__ hW, const float* __restrict__ hT,
                         const float* __restrict__ b_out,
                         float* __restrict__ out) {
    int t = blockIdx.x * blockDim.x + threadIdx.x;
    const int TOT = BB*NN1*(NN1-1)*3;
    if (t >= TOT) return;
    int c = t % 3;
    int j = (t / 3) & 255;
    int i = (t / (3*256)) % NN1;
    int b = t / (3*256*NN1);
    int m = cands[((long long)(b*NN1 + i))*NN1 + j + 1];  // nonzero test works for int32 or f32 bits
    float v = b_out[c];
    if (m) v += hW[(b*NN1 + i)*3 + c] + hT[(b*NN1 + j + 1)*3 + c];
    out[t] = v;
}

// ---------------------------------------------------------------------------
// Launch
// ---------------------------------------------------------------------------
extern "C" void kernel_launch(void* const* d_in, const int* in_sizes, int n_in,
                              void* d_out, int out_size) {
    const float* emb     = (const float*)d_in[0];
    const int*   entIdx  = (const int*)  d_in[1];
    const int*   entLab  = (const int*)  d_in[2];
    const int*   edgeIdx = (const int*)  d_in[3];
    const int*   edgeAttr= (const int*)  d_in[4];
    const int*   cands   = (const int*)  d_in[5];
    const float* W_red   = (const float*)d_in[6];
    const float* b_red   = (const float*)d_in[7];
    const float* tbl     = (const float*)d_in[8];
    const float* W_gcn   = (const float*)d_in[9];
    const float* b_gcn   = (const float*)d_in[10];
    const float* W_head  = (const float*)d_in[11];
    const float* b_head  = (const float*)d_in[12];
    const float* W_tail  = (const float*)d_in[13];
    const float* b_tail  = (const float*)d_in[14];
    const float* W_out   = (const float*)d_in[15];
    const float* b_out   = (const float*)d_in[16];
    float* out = (float*)d_out;

    static float *px0=nullptr, *ph, *pxb, *pres, *pA, *pdeg,
                 *pWho, *pWto, *pbho, *pbto, *phW, *phT;
    if (!px0) {
        cudaGetSymbolAddress((void**)&px0,  g_x0);
        cudaGetSymbolAddress((void**)&ph,   g_h);
        cudaGetSymbolAddress((void**)&pxb,  g_xb);
        cudaGetSymbolAddress((void**)&pres, g_res);
        cudaGetSymbolAddress((void**)&pA,   g_A);
        cudaGetSymbolAddress((void**)&pdeg, g_deg);
        cudaGetSymbolAddress((void**)&pWho, g_Who);
        cudaGetSymbolAddress((void**)&pWto, g_Wto);
        cudaGetSymbolAddress((void**)&pbho, g_bho);
        cudaGetSymbolAddress((void**)&pbto, g_bto);
        cudaGetSymbolAddress((void**)&phW,  g_hW);
        cudaGetSymbolAddress((void**)&phT,  g_hT);
    }

    auto blocks = [](int n) { return (n + 255) / 256; };

    // init scratch
    k_fill<<<blocks(XSZ), 256>>>(px0,  XSZ, 0.f);
    k_fill<<<blocks(XSZ), 256>>>(pres, XSZ, 0.f);
    k_fill<<<blocks(ASZ), 256>>>(pA,   ASZ, 0.f);
    k_fill<<<blocks(DEGSZ), 256>>>(pdeg, DEGSZ, 1.f);

    // labels + graph structure
    k_labels<<<blocks(BB*NN1*LDD), 256>>>(px0, entLab, tbl);
    k_deg   <<<blocks(BB*EE), 256>>>(pdeg, edgeIdx, edgeAttr);
    k_adj   <<<blocks(BB*EE), 256>>>(pA, pdeg, edgeIdx, edgeAttr);

    // big GEMM + fused relu/segmax scatter into x0 hidden part
    {
        dim3 g(HH/64, (BB*SS)/64, 1);   // (8, 512)
        k_gemm_red<<<g, 256>>>(emb, W_red, b_red, entIdx, px0);
    }

    // GCN: per class, 2 layers; dense adjacency matmul
    {
        dim3 g2((DD+63)/64, (NN1+63)/64, BB);   // (9, 5, 16)
        const long long sX = (long long)NN1*DD;
        const long long sAcls = (long long)NN1*NN1P;
        for (int c = 0; c < NCLS; c++) {
            for (int l = 0; l < NLAY; l++) {
                const float* in = (l == 0) ? px0 : pxb;
                const float* W  = W_gcn + (long long)(c*NLAY + l)*DD*DD;
                const float* bg = b_gcn + (c*NLAY + l)*DD;
                // h = in @ W
                k_sgemm<<<g2, 256>>>(in, W, ph, NN1, DD, DD,
                                     DD, DD, DD,
                                     sX, 0LL, sX, 0, nullptr, nullptr, nullptr);
                // xb = A_c @ h + h/deg + b ; last layer also accumulates result
                k_sgemm<<<g2, 256>>>(pA + (long long)c*BB*NN1*NN1P, ph, pxb,
                                     NN1, DD, NN1,
                                     NN1P, DD, DD,
                                     sAcls, sX, sX, 1,
                                     pdeg + c*BB*NN1, bg,
                                     (l == NLAY-1) ? pres : nullptr);
            }
        }
    }

    // collapsed head/tail + tiny projections + final logits
    k_ho<<<blocks(2*DD*3 + 6), 256>>>(W_head, W_tail, W_out, b_head, b_tail,
                                      pWho, pWto, pbho, pbto);
    k_hw<<<blocks(2*BB*NN1*3), 256>>>(pres, pWho, pWto, pbho, pbto, phW, phT);
    k_logits<<<blocks(BB*NN1*(NN1-1)*3), 256>>>(cands, phW, phT, b_out, out);
}

// round 4
// speedup vs baseline: 1.4267x; 1.4267x over previous
#include <cuda_runtime.h>
#include <cuda_bf16.h>
#include <cstdint>

// ---------------------------------------------------------------------------
// Problem constants
// ---------------------------------------------------------------------------
#define BB    16
#define SS    2048
#define NN1   257
#define NN1P  260
#define EE    4096
#define HH    512
#define LDD   16
#define ETRD  768
#define DD    528
#define NCLS  3
#define NLAY  2

#define XSZ   (BB*NN1*DD)
#define ASZ   (NCLS*BB*NN1*NN1P)
#define DEGSZ (NCLS*BB*NN1)

// ---------------------------------------------------------------------------
// Device scratch
// ---------------------------------------------------------------------------
__device__ float g_x0 [XSZ];
__device__ float g_h  [XSZ];
__device__ float g_xb [XSZ];
__device__ float g_res[XSZ];
__device__ float g_A  [ASZ];
__device__ float g_deg[DEGSZ];
__device__ float g_Wr [ETRD*HH];     // W_red tf32-rounded (same layout)
__device__ float g_Who[DD*3];
__device__ float g_Wto[DD*3];
__device__ float g_bho[3];
__device__ float g_bto[3];
__device__ float g_hW [BB*NN1*3];
__device__ float g_hT [BB*NN1*3];

__device__ __forceinline__ uint32_t f2tf32(float f) {
    uint32_t r;
    asm("cvt.rna.tf32.f32 %0, %1;" : "=r"(r) : "f"(f));
    return r;
}

// ---------------------------------------------------------------------------
// Small helper kernels
// ---------------------------------------------------------------------------
__global__ void k_fill(float* __restrict__ p, int n, float v) {
    int i = blockIdx.x * blockDim.x + threadIdx.x;
    if (i < n) p[i] = v;
}

__global__ void k_labels(float* __restrict__ x0,
                         const int* __restrict__ entLab,
                         const float* __restrict__ tbl) {
    int t = blockIdx.x * blockDim.x + threadIdx.x;
    if (t >= BB*NN1*LDD) return;
    int d = t & 15;
    int i = (t >> 4) % NN1;
    int b = t / (NN1*LDD);
    float v;
    if (i == 0) v = tbl[d];
    else {
        int lbl = entLab[b*(NN1-1) + i - 1];
        v = lbl ? tbl[lbl*LDD + d] : 0.f;
    }
    x0[((long long)(b*NN1 + i))*DD + d] = v;
}

__global__ void k_deg(float* __restrict__ deg,
                      const int* __restrict__ ei,
                      const int* __restrict__ ea) {
    int t = blockIdx.x * blockDim.x + threadIdx.x;
    if (t >= BB*EE) return;
    int b = t >> 12, e = t & (EE-1);
    int dst = ei[b*2*EE + EE + e];
    int a   = ea[b*EE + e];
    atomicAdd(&deg[(a*BB + b)*NN1 + dst], 1.f);
}

__global__ void k_adj(float* __restrict__ Am,
                      const float* __restrict__ deg,
                      const int* __restrict__ ei,
                      const int* __restrict__ ea) {
    int t = blockIdx.x * blockDim.x + threadIdx.x;
    if (t >= BB*EE) return;
    int b = t >> 12, e = t & (EE-1);
    int src = ei[b*2*EE + e];
    int dst = ei[b*2*EE + EE + e];
    int a   = ea[b*EE + e];
    const float* dg = deg + (a*BB + b)*NN1;
    float coef = rsqrtf(dg[src]) * rsqrtf(dg[dst]);
    atomicAdd(&Am[((long long)(a*BB + b)*NN1 + dst)*NN1P + src], coef);
}

// elementwise tf32 rounding of W_red (768x512 row-major, layout unchanged)
__global__ void k_wr(const float* __restrict__ W, float* __restrict__ Wr, int n) {
    int i = blockIdx.x * blockDim.x + threadIdx.x;
    if (i < n) Wr[i] = __uint_as_float(f2tf32(W[i]));
}

// ---------------------------------------------------------------------------
// Tensor-core GEMM via mma.sync (tf32): red = emb @ W_red (+bias, relu,
// segment-max atomic scatter). M=32768, N=512, K=768.
// CTA tile 128x128, 8 warps of 64x32, K chunks of 32, double-buffered SMEM.
//   As: [128][36] pad -> frag-load bank (4m+k)%32 all-distinct
//   Bs: [32][136] pad -> frag-load bank (8k+n)%32 all-distinct
// ---------------------------------------------------------------------------
#define SA_LD 36
#define SB_LD 136
#define SA_SZ (128*SA_LD)          // 4608 floats
#define SB_SZ (32*SB_LD)           // 4352 floats
#define SMEM_FLOATS (2*SA_SZ + 2*SB_SZ)
#define SMEM_BYTES  (SMEM_FLOATS*4)

__device__ __forceinline__ void mma_tf32(float* c, const uint32_t* a, const uint32_t* b) {
    asm volatile(
        "mma.sync.aligned.m16n8k8.row.col.f32.tf32.tf32.f32 "
        "{%0,%1,%2,%3}, {%4,%5,%6,%7}, {%8,%9}, {%0,%1,%2,%3};"
        : "+f"(c[0]), "+f"(c[1]), "+f"(c[2]), "+f"(c[3])
        : "r"(a[0]), "r"(a[1]), "r"(a[2]), "r"(a[3]), "r"(b[0]), "r"(b[1]));
}

__global__ void __launch_bounds__(256, 1) k_mma_red(
    const float* __restrict__ A,      // emb (32768 x 768)
    const float* __restrict__ Bw,     // W_red tf32-rounded (768 x 512)
    const float* __restrict__ bias,
    const int*   __restrict__ entIdx,
    float*       __restrict__ x0)
{
    extern __shared__ float sm[];
    float* sAb[2] = { sm,            sm + SA_SZ };
    float* sBb[2] = { sm + 2*SA_SZ,  sm + 2*SA_SZ + SB_SZ };

    const int tid  = threadIdx.x;
    const int lane = tid & 31;
    const int wid  = tid >> 5;
    const int gr   = lane >> 2;     // group id (0..7)
    const int kq   = lane & 3;      // thread-in-group
    const int wm   = wid & 1;       // warp m index (0..1) -> 64 rows
    const int wn   = wid >> 1;      // warp n index (0..3) -> 32 cols
    const int row0 = blockIdx.y * 128;
    const int col0 = blockIdx.x * 128;

    // global-load staging indices
    const int am  = tid >> 3;       // 0..31 (+32 per pass), A row
    const int akv = tid & 7;        // float4 index within 32-k row
    const int bk  = tid >> 5;       // 0..7 (+8 per pass), B k-row
    const int bnv = tid & 31;       // float4 index within 128-n row

    float acc[4][4][4];
    #pragma unroll
    for (int i = 0; i < 4; i++)
        #pragma unroll
        for (int j = 0; j < 4; j++)
            #pragma unroll
            for (int u = 0; u < 4; u++) acc[i][j][u] = 0.f;

    float4 ra[4], rb[4];

    auto ldchunk = [&](int k0) {
        #pragma unroll
        for (int p = 0; p < 4; p++)
            ra[p] = *(const float4*)(A + (size_t)(row0 + am + p*32)*ETRD + k0 + akv*4);
        #pragma unroll
        for (int p = 0; p < 4; p++)
            rb[p] = *(const float4*)(Bw + (size_t)(k0 + bk + p*8)*HH + col0 + bnv*4);
    };
    auto stchunk = [&](int buf) {
        #pragma unroll
        for (int p = 0; p < 4; p++) {
            float4 v = ra[p];
            v.x = __uint_as_float(f2tf32(v.x));
            v.y = __uint_as_float(f2tf32(v.y));
            v.z = __uint_as_float(f2tf32(v.z));
            v.w = __uint_as_float(f2tf32(v.w));
            *(float4*)(sAb[buf] + (am + p*32)*SA_LD + akv*4) = v;
        }
        #pragma unroll
        for (int p = 0; p < 4; p++)
            *(float4*)(sBb[buf] + (bk + p*8)*SB_LD + bnv*4) = rb[p];
    };
    auto compute = [&](int buf) {
        const uint32_t* uA = (const uint32_t*)sAb[buf];
        const uint32_t* uB = (const uint32_t*)sBb[buf];
        #pragma unroll
        for (int ks = 0; ks < 4; ks++) {
            uint32_t af[4][4], bf[4][2];
            #pragma unroll
            for (int mi = 0; mi < 4; mi++) {
                int r = wm*64 + mi*16 + gr;
                af[mi][0] = uA[(size_t)r*SA_LD       + ks*8 + kq];
                af[mi][1] = uA[(size_t)(r+8)*SA_LD   + ks*8 + kq];
                af[mi][2] = uA[(size_t)r*SA_LD       + ks*8 + kq + 4];
                af[mi][3] = uA[(size_t)(r+8)*SA_LD   + ks*8 + kq + 4];
            }
            #pragma unroll
            for (int ni = 0; ni < 4; ni++) {
                int c = wn*32 + ni*8 + gr;
                bf[ni][0] = uB[(size_t)(ks*8 + kq)*SB_LD     + c];
                bf[ni][1] = uB[(size_t)(ks*8 + kq + 4)*SB_LD + c];
            }
            #pragma unroll
            for (int mi = 0; mi < 4; mi++)
                #pragma unroll
                for (int ni = 0; ni < 4; ni++)
                    mma_tf32(acc[mi][ni], af[mi], bf[ni]);
        }
    };

    ldchunk(0);
    stchunk(0);
    __syncthreads();
    #pragma unroll 1
    for (int ch = 0; ch < ETRD/32; ch++) {
        int buf = ch & 1;
        if (ch < ETRD/32 - 1) ldchunk((ch + 1)*32);
        compute(buf);
        __syncthreads();
        if (ch < ETRD/32 - 1) {
            stchunk(buf ^ 1);
            __syncthreads();
        }
    }

    // Epilogue: fused bias + relu + segment-max scatter (atomicMax on
    // non-negative floats == float max via int compare).
    int    nodev[4][2];
    float* basep[4][2];
    #pragma unroll
    for (int mi = 0; mi < 4; mi++)
        #pragma unroll
        for (int h = 0; h < 2; h++) {
            int r  = row0 + wm*64 + mi*16 + gr + h*8;
            int nd = entIdx[r];
            nodev[mi][h] = nd;
            int b = r >> 11;
            basep[mi][h] = x0 + ((size_t)(b*NN1 + nd))*DD + LDD;
        }
    #pragma unroll
    for (int ni = 0; ni < 4; ni++) {
        int c = col0 + wn*32 + ni*8 + kq*2;
        float b0 = __ldg(bias + c), b1 = __ldg(bias + c + 1);
        #pragma unroll
        for (int mi = 0; mi < 4; mi++) {
            #pragma unroll
            for (int h = 0; h < 2; h++) {
                if (nodev[mi][h] == 0) continue;
                float v0 = fmaxf(acc[mi][ni][2*h    ] + b0, 0.f);
                float v1 = fmaxf(acc[mi][ni][2*h + 1] + b1, 0.f);
                atomicMax((int*)(basep[mi][h] + c),     __float_as_int(v0));
                atomicMax((int*)(basep[mi][h] + c + 1), __float_as_int(v1));
            }
        }
    }
}

// ---------------------------------------------------------------------------
// Generic SGEMM (fp32), 64x64x16 tile, explicit ld, guards.
// mode 0: C = A@B    mode 1: GCN epilogue
// ---------------------------------------------------------------------------
__global__ void __launch_bounds__(256) k_sgemm(
    const float* __restrict__ Abase, const float* __restrict__ Bbase,
    float* __restrict__ Cbase,
    int M, int N, int K,
    int lda, int ldb, int ldc,
    long long sA, long long sB, long long sC,
    int mode,
    const float* __restrict__ degBase,
    const float* __restrict__ bias,
    float*       __restrict__ resBase)
{
    int b = blockIdx.z;
    const float* A  = Abase + (long long)b*sA;
    const float* Bm = Bbase + (long long)b*sB;
    float* C = Cbase + (long long)b*sC;

    __shared__ float As[16][64];
    __shared__ float Bs[16][64];

    int tid  = threadIdx.x;
    int row0 = blockIdx.y * 64;
    int col0 = blockIdx.x * 64;
    int tm = (tid >> 4) << 2;
    int tn = (tid & 15) << 2;

    float acc[4][4];
    #pragma unroll
    for (int i = 0; i < 4; i++)
        #pragma unroll
        for (int j = 0; j < 4; j++) acc[i][j] = 0.f;

    int arow = tid >> 2, ak = (tid & 3) << 2;
    int brow = tid >> 4, bn = (tid & 15) << 2;

    for (int k0 = 0; k0 < K; k0 += 16) {
        int gm = row0 + arow, gk = k0 + ak;
        if (gm < M && gk + 3 < K) {
            float4 v = *(const float4*)(A + (long long)gm*lda + gk);
            As[ak  ][arow] = v.x;
            As[ak+1][arow] = v.y;
            As[ak+2][arow] = v.z;
            As[ak+3][arow] = v.w;
        } else {
            #pragma unroll
            for (int u = 0; u < 4; u++)
                As[ak+u][arow] = (gm < M && gk + u < K)
                               ? A[(long long)gm*lda + gk + u] : 0.f;
        }
        int gkb = k0 + brow, gn = col0 + bn;
        float4 bv = make_float4(0.f, 0.f, 0.f, 0.f);
        if (gkb < K && gn + 3 < N)
            bv = *(const float4*)(Bm + (long long)gkb*ldb + gn);
        else if (gkb < K) {
            float tmp[4];
            #pragma unroll
            for (int u = 0; u < 4; u++)
                tmp[u] = (gn + u < N) ? Bm[(long long)gkb*ldb + gn + u] : 0.f;
            bv = make_float4(tmp[0], tmp[1], tmp[2], tmp[3]);
        }
        *(float4*)&Bs[brow][bn] = bv;
        __syncthreads();
        #pragma unroll
        for (int kk = 0; kk < 16; kk++) {
            float4 a4 = *(const float4*)&As[kk][tm];
            float4 b4 = *(const float4*)&Bs[kk][tn];
            float aa[4] = {a4.x, a4.y, a4.z, a4.w};
            float bb[4] = {b4.x, b4.y, b4.z, b4.w};
            #pragma unroll
            for (int i = 0; i < 4; i++)
                #pragma unroll
                for (int j = 0; j < 4; j++) acc[i][j] += aa[i]*bb[j];
        }
        __syncthreads();
    }

    #pragma unroll
    for (int i = 0; i < 4; i++) {
        int gm = row0 + tm + i;
        if (gm >= M) continue;
        float dinv = 0.f;
        if (mode == 1) dinv = 1.f / degBase[b*NN1 + gm];
        #pragma unroll
        for (int j = 0; j < 4; j++) {
            int gn = col0 + tn + j;
            if (gn >= N) continue;
            long long idx = (long long)gm*ldc + gn;
            float v = acc[i][j];
            if (mode == 1) {
                v += Bm[(long long)gm*ldb + gn] * dinv + bias[gn];
                C[idx] = v;
                if (resBase) resBase[(long long)b*sC + idx] += v;
            } else {
                C[idx] = v;
            }
        }
    }
}

// ---------------------------------------------------------------------------
// Collapsed head/tail + logits
// ---------------------------------------------------------------------------
__global__ void k_ho(const float* __restrict__ W_head, const float* __restrict__ W_tail,
                     const float* __restrict__ W_out,
                     const float* __restrict__ b_head, const float* __restrict__ b_tail,
                     float* __restrict__ Who, float* __restrict__ Wto,
                     float* __restrict__ bho, float* __restrict__ bto) {
    int t = blockIdx.x * blockDim.x + threadIdx.x;
    if (t < 2*DD*3) {
        int which = t / (DD*3), rc = t % (DD*3), r = rc / 3, c = rc % 3;
        const float* W = which ? W_tail : W_head;
        float acc = 0.f;
        for (int j = 0; j < DD; j++) acc += W[r*DD + j] * W_out[j*3 + c];
        (which ? Wto : Who)[r*3 + c] = acc;
    } else if (t < 2*DD*3 + 6) {
        int u = t - 2*DD*3, which = u / 3, c = u % 3;
        const float* bb = which ? b_tail : b_head;
        float acc = 0.f;
        for (int j = 0; j < DD; j++) acc += bb[j] * W_out[j*3 + c];
        (which ? bto : bho)[c] = acc;
    }
}

__global__ void k_hw(const float* __restrict__ res,
                     const float* __restrict__ Who, const float* __restrict__ Wto,
                     const float* __restrict__ bho, const float* __restrict__ bto,
                     float* __restrict__ hW, float* __restrict__ hT) {
    int t = blockIdx.x * blockDim.x + threadIdx.x;
    if (t >= 2*BB*NN1*3) return;
    int which = t / (BB*NN1*3);
    int rem = t % (BB*NN1*3);
    int bi = rem / 3, c = rem % 3;
    const float* row = res + (long long)bi*DD;
    const float* W   = which ? Wto : Who;
    float acc = 0.f;
    for (int k = 0; k < DD; k++) acc += row[k] * W[k*3 + c];
    acc = acc * (1.f/3.f) + (which ? bto[c] : bho[c]);
    (which ? hT : hW)[bi*3 + c] = acc;
}

__global__ void k_logits(const int* __restrict__ cands,
                         const float* __restrict__ hW, const float* __restrict__ hT,
                         const float* __restrict__ b_out,
                         float* __restrict__ out) {
    int t = blockIdx.x * blockDim.x + threadIdx.x;
    const int TOT = BB*NN1*(NN1-1)*3;
    if (t >= TOT) return;
    int c = t % 3;
    int j = (t / 3) & 255;
    int i = (t / (3*256)) % NN1;
    int b = t / (3*256*NN1);
    int m = cands[((long long)(b*NN1 + i))*NN1 + j + 1];
    float v = b_out[c];
    if (m) v += hW[(b*NN1 + i)*3 + c] + hT[(b*NN1 + j + 1)*3 + c];
    out[t] = v;
}

// ---------------------------------------------------------------------------
// Launch
// ---------------------------------------------------------------------------
extern "C" void kernel_launch(void* const* d_in, const int* in_sizes, int n_in,
                              void* d_out, int out_size) {
    const float* emb     = (const float*)d_in[0];
    const int*   entIdx  = (const int*)  d_in[1];
    const int*   entLab  = (const int*)  d_in[2];
    const int*   edgeIdx = (const int*)  d_in[3];
    const int*   edgeAttr= (const int*)  d_in[4];
    const int*   cands   = (const int*)  d_in[5];
    const float* W_red   = (const float*)d_in[6];
    const float* b_red   = (const float*)d_in[7];
    const float* tbl     = (const float*)d_in[8];
    const float* W_gcn   = (const float*)d_in[9];
    const float* b_gcn   = (const float*)d_in[10];
    const float* W_head  = (const float*)d_in[11];
    const float* b_head  = (const float*)d_in[12];
    const float* W_tail  = (const float*)d_in[13];
    const float* b_tail  = (const float*)d_in[14];
    const float* W_out   = (const float*)d_in[15];
    const float* b_out   = (const float*)d_in[16];
    float* out = (float*)d_out;

    static float *px0=nullptr, *ph, *pxb, *pres, *pA, *pdeg, *pWr,
                 *pWho, *pWto, *pbho, *pbto, *phW, *phT;
    static bool attr_set = false;
    if (!px0) {
        cudaGetSymbolAddress((void**)&px0,  g_x0);
        cudaGetSymbolAddress((void**)&ph,   g_h);
        cudaGetSymbolAddress((void**)&pxb,  g_xb);
        cudaGetSymbolAddress((void**)&pres, g_res);
        cudaGetSymbolAddress((void**)&pA,   g_A);
        cudaGetSymbolAddress((void**)&pdeg, g_deg);
        cudaGetSymbolAddress((void**)&pWr,  g_Wr);
        cudaGetSymbolAddress((void**)&pWho, g_Who);
        cudaGetSymbolAddress((void**)&pWto, g_Wto);
        cudaGetSymbolAddress((void**)&pbho, g_bho);
        cudaGetSymbolAddress((void**)&pbto, g_bto);
        cudaGetSymbolAddress((void**)&phW,  g_hW);
        cudaGetSymbolAddress((void**)&phT,  g_hT);
    }
    if (!attr_set) {
        cudaFuncSetAttribute(k_mma_red, cudaFuncAttributeMaxDynamicSharedMemorySize, SMEM_BYTES);
        attr_set = true;
    }

    auto blocks = [](int n) { return (n + 255) / 256; };

    // init scratch
    k_fill<<<blocks(XSZ), 256>>>(px0,  XSZ, 0.f);
    k_fill<<<blocks(XSZ), 256>>>(pres, XSZ, 0.f);
    k_fill<<<blocks(ASZ), 256>>>(pA,   ASZ, 0.f);
    k_fill<<<blocks(DEGSZ), 256>>>(pdeg, DEGSZ, 1.f);

    // labels + graph structure + weight rounding
    k_labels<<<blocks(BB*NN1*LDD), 256>>>(px0, entLab, tbl);
    k_deg   <<<blocks(BB*EE), 256>>>(pdeg, edgeIdx, edgeAttr);
    k_adj   <<<blocks(BB*EE), 256>>>(pA, pdeg, edgeIdx, edgeAttr);
    k_wr    <<<blocks(ETRD*HH), 256>>>(W_red, pWr, ETRD*HH);

    // big GEMM on tensor cores (tf32 mma.sync) + fused relu/segmax scatter
    {
        dim3 g(HH/128, (BB*SS)/128);   // (4, 256): n fastest -> A reuse in L2
        k_mma_red<<<g, 256, SMEM_BYTES>>>(emb, pWr, b_red, entIdx, px0);
    }

    // GCN: per class, 2 layers
    {
        dim3 gx((DD+63)/64, (BB*NN1+63)/64, 1);    // xW merged over batches
        dim3 ga((DD+63)/64, (NN1+63)/64, BB);      // adjacency per batch
        const long long sX = (long long)NN1*DD;
        const long long sAcls = (long long)NN1*NN1P;
        for (int c = 0; c < NCLS; c++) {
            for (int l = 0; l < NLAY; l++) {
                const float* in = (l == 0) ? px0 : pxb;
                const float* W  = W_gcn + (long long)(c*NLAY + l)*DD*DD;
                const float* bg = b_gcn + (c*NLAY + l)*DD;
                k_sgemm<<<gx, 256>>>(in, W, ph, BB*NN1, DD, DD,
                                     DD, DD, DD,
                                     0LL, 0LL, 0LL, 0, nullptr, nullptr, nullptr);
                k_sgemm<<<ga, 256>>>(pA + (long long)c*BB*NN1*NN1P, ph, pxb,
                                     NN1, DD, NN1,
                                     NN1P, DD, DD,
                                     sAcls, sX, sX, 1,
                                     pdeg + c*BB*NN1, bg,
                                     (l == NLAY-1) ? pres : nullptr);
            }
        }
    }

    // collapsed head/tail + logits
    k_ho<<<blocks(2*DD*3 + 6), 256>>>(W_head, W_tail, W_out, b_head, b_tail,
                                      pWho, pWto, pbho, pbto);
    k_hw<<<blocks(2*BB*NN1*3), 256>>>(pres, pWho, pWto, pbho, pbto, phW, phT);
    k_logits<<<blocks(BB*NN1*(NN1-1)*3), 256>>>(cands, phW, phT, b_out, out);
}

// round 5
// speedup vs baseline: 1.8147x; 1.2719x over previous
#include <cuda_runtime.h>
#include <cuda_bf16.h>
#include <cstdint>

// ---------------------------------------------------------------------------
// Problem constants
// ---------------------------------------------------------------------------
#define BB    16
#define SS    2048
#define NN1   257
#define EE    4096
#define HH    512
#define LDD   16
#define ETRD  768
#define DD    528
#define NCLS  3
#define NLAY  2

#define XSZ   (BB*NN1*DD)
#define DEGSZ (NCLS*BB*NN1)
#define CBSZ  (NCLS*BB)

// ---------------------------------------------------------------------------
// Device scratch
// ---------------------------------------------------------------------------
__device__ float g_x0 [XSZ];
__device__ float g_h  [XSZ];
__device__ float g_xb [XSZ];
__device__ float g_res[XSZ];
__device__ float g_deg[DEGSZ];
__device__ int   g_off[CBSZ*(NN1+1)];
__device__ int   g_cur[CBSZ*NN1];
__device__ int   g_esrc[CBSZ*EE];
__device__ float g_ecoef[CBSZ*EE];
__device__ float g_Wr [ETRD*HH];     // W_red tf32-rounded
__device__ float g_Who[DD*3];
__device__ float g_Wto[DD*3];
__device__ float g_bho[3];
__device__ float g_bto[3];
__device__ float g_hW [BB*NN1*3];
__device__ float g_hT [BB*NN1*3];

__device__ __forceinline__ uint32_t f2tf32(float f) {
    uint32_t r;
    asm("cvt.rna.tf32.f32 %0, %1;" : "=r"(r) : "f"(f));
    return r;
}

// ---------------------------------------------------------------------------
// Small helper kernels
// ---------------------------------------------------------------------------
__global__ void k_fill(float* __restrict__ p, int n, float v) {
    int i = blockIdx.x * blockDim.x + threadIdx.x;
    if (i < n) p[i] = v;
}

__global__ void k_labels(float* __restrict__ x0,
                         const int* __restrict__ entLab,
                         const float* __restrict__ tbl) {
    int t = blockIdx.x * blockDim.x + threadIdx.x;
    if (t >= BB*NN1*LDD) return;
    int d = t & 15;
    int i = (t >> 4) % NN1;
    int b = t / (NN1*LDD);
    float v;
    if (i == 0) v = tbl[d];
    else {
        int lbl = entLab[b*(NN1-1) + i - 1];
        v = lbl ? tbl[lbl*LDD + d] : 0.f;
    }
    x0[((long long)(b*NN1 + i))*DD + d] = v;
}

__global__ void k_deg(float* __restrict__ deg,
                      const int* __restrict__ ei,
                      const int* __restrict__ ea) {
    int t = blockIdx.x * blockDim.x + threadIdx.x;
    if (t >= BB*EE) return;
    int b = t >> 12, e = t & (EE-1);
    int dst = ei[b*2*EE + EE + e];
    int a   = ea[b*EE + e];
    atomicAdd(&deg[(a*BB + b)*NN1 + dst], 1.f);
}

// CSR row offsets + cursor init (one thread per (class,batch))
__global__ void k_off(const float* __restrict__ deg) {
    int t = blockIdx.x * blockDim.x + threadIdx.x;
    if (t >= CBSZ) return;
    const float* dg = deg + t*NN1;
    int* off = g_off + t*(NN1+1);
    int* cur = g_cur + t*NN1;
    int acc = 0;
    off[0] = 0;
    for (int i = 0; i < NN1; i++) {
        cur[i] = acc;
        acc += (int)dg[i] - 1;     // deg = incoming count + 1 (exact small ints)
        off[i+1] = acc;
    }
}

// scatter edges into CSR (src + normalized coefficient)
__global__ void k_scatter(const float* __restrict__ deg,
                          const int* __restrict__ ei,
                          const int* __restrict__ ea) {
    int t = blockIdx.x * blockDim.x + threadIdx.x;
    if (t >= BB*EE) return;
    int b = t >> 12, e = t & (EE-1);
    int src = ei[b*2*EE + e];
    int dst = ei[b*2*EE + EE + e];
    int a   = ea[b*EE + e];
    int cb  = a*BB + b;
    const float* dg = deg + cb*NN1;
    float coef = rsqrtf(dg[src]) * rsqrtf(dg[dst]);
    int pos = atomicAdd(&g_cur[cb*NN1 + dst], 1);
    g_esrc [cb*EE + pos] = src;
    g_ecoef[cb*EE + pos] = coef;
}

// elementwise tf32 rounding of W_red
__global__ void k_wr(const float* __restrict__ W, float* __restrict__ Wr, int n) {
    int i = blockIdx.x * blockDim.x + threadIdx.x;
    if (i < n) Wr[i] = __uint_as_float(f2tf32(W[i]));
}

// ---------------------------------------------------------------------------
// Tensor-core GEMM via mma.sync (tf32): red = emb @ W_red (+bias, relu,
// segment-max atomic scatter). M=32768, N=512, K=768.
// CTA 128x128, 8 warps 64x32, K chunks of 32, double-buffer, 1 sync/chunk.
// ---------------------------------------------------------------------------
#define SA_LD 36
#define SB_LD 136
#define SA_SZ (128*SA_LD)
#define SB_SZ (32*SB_LD)
#define SMEM_BYTES ((2*SA_SZ + 2*SB_SZ)*4)

__device__ __forceinline__ void mma_tf32(float* c, const uint32_t* a, const uint32_t* b) {
    asm volatile(
        "mma.sync.aligned.m16n8k8.row.col.f32.tf32.tf32.f32 "
        "{%0,%1,%2,%3}, {%4,%5,%6,%7}, {%8,%9}, {%0,%1,%2,%3};"
        : "+f"(c[0]), "+f"(c[1]), "+f"(c[2]), "+f"(c[3])
        : "r"(a[0]), "r"(a[1]), "r"(a[2]), "r"(a[3]), "r"(b[0]), "r"(b[1]));
}

__global__ void __launch_bounds__(256, 1) k_mma_red(
    const float* __restrict__ A,      // emb (32768 x 768)
    const float* __restrict__ Bw,     // W_red tf32-rounded (768 x 512)
    const float* __restrict__ bias,
    const int*   __restrict__ entIdx,
    float*       __restrict__ x0)
{
    extern __shared__ float sm[];
    float* sAb[2] = { sm,            sm + SA_SZ };
    float* sBb[2] = { sm + 2*SA_SZ,  sm + 2*SA_SZ + SB_SZ };

    const int tid  = threadIdx.x;
    const int lane = tid & 31;
    const int wid  = tid >> 5;
    const int gr   = lane >> 2;
    const int kq   = lane & 3;
    const int wm   = wid & 1;
    const int wn   = wid >> 1;
    const int row0 = blockIdx.y * 128;
    const int col0 = blockIdx.x * 128;

    const int am  = tid >> 3;
    const int akv = tid & 7;
    const int bk  = tid >> 5;
    const int bnv = tid & 31;

    float acc[4][4][4];
    #pragma unroll
    for (int i = 0; i < 4; i++)
        #pragma unroll
        for (int j = 0; j < 4; j++)
            #pragma unroll
            for (int u = 0; u < 4; u++) acc[i][j][u] = 0.f;

    float4 ra[4], rb[4];

    auto ldchunk = [&](int k0) {
        #pragma unroll
        for (int p = 0; p < 4; p++)
            ra[p] = *(const float4*)(A + (size_t)(row0 + am + p*32)*ETRD + k0 + akv*4);
        #pragma unroll
        for (int p = 0; p < 4; p++)
            rb[p] = *(const float4*)(Bw + (size_t)(k0 + bk + p*8)*HH + col0 + bnv*4);
    };
    auto stchunk = [&](int buf) {
        #pragma unroll
        for (int p = 0; p < 4; p++) {
            float4 v = ra[p];
            v.x = __uint_as_float(f2tf32(v.x));
            v.y = __uint_as_float(f2tf32(v.y));
            v.z = __uint_as_float(f2tf32(v.z));
            v.w = __uint_as_float(f2tf32(v.w));
            *(float4*)(sAb[buf] + (am + p*32)*SA_LD + akv*4) = v;
        }
        #pragma unroll
        for (int p = 0; p < 4; p++)
            *(float4*)(sBb[buf] + (bk + p*8)*SB_LD + bnv*4) = rb[p];
    };
    auto compute = [&](int buf) {
        const uint32_t* uA = (const uint32_t*)sAb[buf];
        const uint32_t* uB = (const uint32_t*)sBb[buf];
        #pragma unroll
        for (int ks = 0; ks < 4; ks++) {
            uint32_t af[4][4], bf[4][2];
            #pragma unroll
            for (int mi = 0; mi < 4; mi++) {
                int r = wm*64 + mi*16 + gr;
                af[mi][0] = uA[(size_t)r*SA_LD     + ks*8 + kq];
                af[mi][1] = uA[(size_t)(r+8)*SA_LD + ks*8 + kq];
                af[mi][2] = uA[(size_t)r*SA_LD     + ks*8 + kq + 4];
                af[mi][3] = uA[(size_t)(r+8)*SA_LD + ks*8 + kq + 4];
            }
            #pragma unroll
            for (int ni = 0; ni < 4; ni++) {
                int c = wn*32 + ni*8 + gr;
                bf[ni][0] = uB[(size_t)(ks*8 + kq)*SB_LD     + c];
                bf[ni][1] = uB[(size_t)(ks*8 + kq + 4)*SB_LD + c];
            }
            #pragma unroll
            for (int mi = 0; mi < 4; mi++)
                #pragma unroll
                for (int ni = 0; ni < 4; ni++)
                    mma_tf32(acc[mi][ni], af[mi], bf[ni]);
        }
    };

    ldchunk(0);
    stchunk(0);
    __syncthreads();
    #pragma unroll 1
    for (int ch = 0; ch < ETRD/32; ch++) {
        if (ch + 1 < ETRD/32) ldchunk((ch + 1)*32);
        compute(ch & 1);
        if (ch + 1 < ETRD/32) {
            stchunk((ch + 1) & 1);     // writes buffer last read 2 chunks ago
            __syncthreads();
        }
    }

    // Epilogue: fused bias + relu + segment-max scatter
    int    nodev[4][2];
    float* basep[4][2];
    #pragma unroll
    for (int mi = 0; mi < 4; mi++)
        #pragma unroll
        for (int h = 0; h < 2; h++) {
            int r  = row0 + wm*64 + mi*16 + gr + h*8;
            int nd = entIdx[r];
            nodev[mi][h] = nd;
            int b = r >> 11;
            basep[mi][h] = x0 + ((size_t)(b*NN1 + nd))*DD + LDD;
        }
    #pragma unroll
    for (int ni = 0; ni < 4; ni++) {
        int c = col0 + wn*32 + ni*8 + kq*2;
        float b0 = __ldg(bias + c), b1 = __ldg(bias + c + 1);
        #pragma unroll
        for (int mi = 0; mi < 4; mi++) {
            #pragma unroll
            for (int h = 0; h < 2; h++) {
                if (nodev[mi][h] == 0) continue;
                float v0 = fmaxf(acc[mi][ni][2*h    ] + b0, 0.f);
                float v1 = fmaxf(acc[mi][ni][2*h + 1] + b1, 0.f);
                atomicMax((int*)(basep[mi][h] + c),     __float_as_int(v0));
                atomicMax((int*)(basep[mi][h] + c + 1), __float_as_int(v1));
            }
        }
    }
}

// ---------------------------------------------------------------------------
// Generic SGEMM (fp32) for xW: C = A@B, 64x64x16 tile, guards.
// ---------------------------------------------------------------------------
__global__ void __launch_bounds__(256) k_sgemm(
    const float* __restrict__ A, const float* __restrict__ Bm,
    float* __restrict__ C,
    int M, int N, int K, int lda, int ldb, int ldc)
{
    __shared__ float As[16][64];
    __shared__ float Bs[16][64];

    int tid  = threadIdx.x;
    int row0 = blockIdx.y * 64;
    int col0 = blockIdx.x * 64;
    int tm = (tid >> 4) << 2;
    int tn = (tid & 15) << 2;

    float acc[4][4];
    #pragma unroll
    for (int i = 0; i < 4; i++)
        #pragma unroll
        for (int j = 0; j < 4; j++) acc[i][j] = 0.f;

    int arow = tid >> 2, ak = (tid & 3) << 2;
    int brow = tid >> 4, bn = (tid & 15) << 2;

    for (int k0 = 0; k0 < K; k0 += 16) {
        int gm = row0 + arow, gk = k0 + ak;
        if (gm < M && gk + 3 < K) {
            float4 v = *(const float4*)(A + (long long)gm*lda + gk);
            As[ak  ][arow] = v.x;
            As[ak+1][arow] = v.y;
            As[ak+2][arow] = v.z;
            As[ak+3][arow] = v.w;
        } else {
            #pragma unroll
            for (int u = 0; u < 4; u++)
                As[ak+u][arow] = (gm < M && gk + u < K)
                               ? A[(long long)gm*lda + gk + u] : 0.f;
        }
        int gkb = k0 + brow, gn = col0 + bn;
        float4 bv = make_float4(0.f, 0.f, 0.f, 0.f);
        if (gkb < K && gn + 3 < N)
            bv = *(const float4*)(Bm + (long long)gkb*ldb + gn);
        else if (gkb < K) {
            float tmp[4];
            #pragma unroll
            for (int u = 0; u < 4; u++)
                tmp[u] = (gn + u < N) ? Bm[(long long)gkb*ldb + gn + u] : 0.f;
            bv = make_float4(tmp[0], tmp[1], tmp[2], tmp[3]);
        }
        *(float4*)&Bs[brow][bn] = bv;
        __syncthreads();
        #pragma unroll
        for (int kk = 0; kk < 16; kk++) {
            float4 a4 = *(const float4*)&As[kk][tm];
            float4 b4 = *(const float4*)&Bs[kk][tn];
            float aa[4] = {a4.x, a4.y, a4.z, a4.w};
            float bb[4] = {b4.x, b4.y, b4.z, b4.w};
            #pragma unroll
            for (int i = 0; i < 4; i++)
                #pragma unroll
                for (int j = 0; j < 4; j++) acc[i][j] += aa[i]*bb[j];
        }
        __syncthreads();
    }

    #pragma unroll
    for (int i = 0; i < 4; i++) {
        int gm = row0 + tm + i;
        if (gm >= M) continue;
        #pragma unroll
        for (int j = 0; j < 4; j++) {
            int gn = col0 + tn + j;
            if (gn >= N) continue;
            C[(long long)gm*ldc + gn] = acc[i][j];
        }
    }
}

// ---------------------------------------------------------------------------
// Sparse GCN aggregation: xb[b,dst,:] = sum_e coef*h[b,src,:] + h[b,dst,:]/deg
//                                        + bias[:]; optionally res += xb.
// One block per (dst, b). 256 threads cover 528 cols (2-3 each).
// ---------------------------------------------------------------------------
__global__ void __launch_bounds__(256) k_spmm(
    const float* __restrict__ h,
    float* __restrict__ xb,
    const float* __restrict__ deg,       // + c*BB*NN1 pre-applied by caller
    const float* __restrict__ bias,
    float* __restrict__ res,             // may be null
    int cls)
{
    int dst = blockIdx.x;
    int b   = blockIdx.y;
    int cb  = cls*BB + b;
    int tid = threadIdx.x;

    const int* off = g_off + cb*(NN1+1);
    int e0 = off[dst], e1 = off[dst+1];
    const int*   es = g_esrc  + cb*EE;
    const float* ec = g_ecoef + cb*EE;
    const float* hb = h + (size_t)b*NN1*DD;

    int c0 = tid, c1 = tid + 256, c2 = tid + 512;
    float a0 = 0.f, a1 = 0.f, a2 = 0.f;

    for (int e = e0; e < e1; e++) {
        int   src = es[e];
        float w   = ec[e];
        const float* hr = hb + (size_t)src*DD;
        a0 += w * hr[c0];
        if (c1 < DD) a1 += w * hr[c1];
        if (c2 < DD) a2 += w * hr[c2];
    }

    float dinv = 1.f / deg[cb*NN1 + dst];
    const float* hd = hb + (size_t)dst*DD;
    float* xo = xb + ((size_t)b*NN1 + dst)*DD;
    float* ro = res ? res + ((size_t)b*NN1 + dst)*DD : nullptr;

    float v0 = a0 + hd[c0]*dinv + bias[c0];
    xo[c0] = v0;
    if (ro) ro[c0] += v0;
    if (c1 < DD) {
        float v1 = a1 + hd[c1]*dinv + bias[c1];
        xo[c1] = v1;
        if (ro) ro[c1] += v1;
    }
    if (c2 < DD) {
        float v2 = a2 + hd[c2]*dinv + bias[c2];
        xo[c2] = v2;
        if (ro) ro[c2] += v2;
    }
}

// ---------------------------------------------------------------------------
// Collapsed head/tail + logits
// ---------------------------------------------------------------------------
__global__ void k_ho(const float* __restrict__ W_head, const float* __restrict__ W_tail,
                     const float* __restrict__ W_out,
                     const float* __restrict__ b_head, const float* __restrict__ b_tail,
                     float* __restrict__ Who, float* __restrict__ Wto,
                     float* __restrict__ bho, float* __restrict__ bto) {
    int t = blockIdx.x * blockDim.x + threadIdx.x;
    if (t < 2*DD*3) {
        int which = t / (DD*3), rc = t % (DD*3), r = rc / 3, c = rc % 3;
        const float* W = which ? W_tail : W_head;
        float acc = 0.f;
        for (int j = 0; j < DD; j++) acc += W[r*DD + j] * W_out[j*3 + c];
        (which ? Wto : Who)[r*3 + c] = acc;
    } else if (t < 2*DD*3 + 6) {
        int u = t - 2*DD*3, which = u / 3, c = u % 3;
        const float* bb = which ? b_tail : b_head;
        float acc = 0.f;
        for (int j = 0; j < DD; j++) acc += bb[j] * W_out[j*3 + c];
        (which ? bto : bho)[c] = acc;
    }
}

__global__ void k_hw(const float* __restrict__ res,
                     const float* __restrict__ Who, const float* __restrict__ Wto,
                     const float* __restrict__ bho, const float* __restrict__ bto,
                     float* __restrict__ hW, float* __restrict__ hT) {
    int t = blockIdx.x * blockDim.x + threadIdx.x;
    if (t >= 2*BB*NN1*3) return;
    int which = t / (BB*NN1*3);
    int rem = t % (BB*NN1*3);
    int bi = rem / 3, c = rem % 3;
    const float* row = res + (long long)bi*DD;
    const float* W   = which ? Wto : Who;
    float acc = 0.f;
    for (int k = 0; k < DD; k++) acc += row[k] * W[k*3 + c];
    acc = acc * (1.f/3.f) + (which ? bto[c] : bho[c]);
    (which ? hT : hW)[bi*3 + c] = acc;
}

__global__ void k_logits(const int* __restrict__ cands,
                         const float* __restrict__ hW, const float* __restrict__ hT,
                         const float* __restrict__ b_out,
                         float* __restrict__ out) {
    int t = blockIdx.x * blockDim.x + threadIdx.x;
    const int TOT = BB*NN1*(NN1-1)*3;
    if (t >= TOT) return;
    int c = t % 3;
    int j = (t / 3) & 255;
    int i = (t / (3*256)) % NN1;
    int b = t / (3*256*NN1);
    int m = cands[((long long)(b*NN1 + i))*NN1 + j + 1];
    float v = b_out[c];
    if (m) v += hW[(b*NN1 + i)*3 + c] + hT[(b*NN1 + j + 1)*3 + c];
    out[t] = v;
}

// ---------------------------------------------------------------------------
// Launch
// ---------------------------------------------------------------------------
extern "C" void kernel_launch(void* const* d_in, const int* in_sizes, int n_in,
                              void* d_out, int out_size) {
    const float* emb     = (const float*)d_in[0];
    const int*   entIdx  = (const int*)  d_in[1];
    const int*   entLab  = (const int*)  d_in[2];
    const int*   edgeIdx = (const int*)  d_in[3];
    const int*   edgeAttr= (const int*)  d_in[4];
    const int*   cands   = (const int*)  d_in[5];
    const float* W_red   = (const float*)d_in[6];
    const float* b_red   = (const float*)d_in[7];
    const float* tbl     = (const float*)d_in[8];
    const float* W_gcn   = (const float*)d_in[9];
    const float* b_gcn   = (const float*)d_in[10];
    const float* W_head  = (const float*)d_in[11];
    const float* b_head  = (const float*)d_in[12];
    const float* W_tail  = (const float*)d_in[13];
    const float* b_tail  = (const float*)d_in[14];
    const float* W_out   = (const float*)d_in[15];
    const float* b_out   = (const float*)d_in[16];
    float* out = (float*)d_out;

    static float *px0=nullptr, *ph, *pxb, *pres, *pdeg, *pWr,
                 *pWho, *pWto, *pbho, *pbto, *phW, *phT;
    static bool attr_set = false;
    if (!px0) {
        cudaGetSymbolAddress((void**)&px0,  g_x0);
        cudaGetSymbolAddress((void**)&ph,   g_h);
        cudaGetSymbolAddress((void**)&pxb,  g_xb);
        cudaGetSymbolAddress((void**)&pres, g_res);
        cudaGetSymbolAddress((void**)&pdeg, g_deg);
        cudaGetSymbolAddress((void**)&pWr,  g_Wr);
        cudaGetSymbolAddress((void**)&pWho, g_Who);
        cudaGetSymbolAddress((void**)&pWto, g_Wto);
        cudaGetSymbolAddress((void**)&pbho, g_bho);
        cudaGetSymbolAddress((void**)&pbto, g_bto);
        cudaGetSymbolAddress((void**)&phW,  g_hW);
        cudaGetSymbolAddress((void**)&phT,  g_hT);
    }
    if (!attr_set) {
        cudaFuncSetAttribute(k_mma_red, cudaFuncAttributeMaxDynamicSharedMemorySize, SMEM_BYTES);
        attr_set = true;
    }

    auto blocks = [](int n) { return (n + 255) / 256; };

    // init scratch
    k_fill<<<blocks(XSZ), 256>>>(px0,  XSZ, 0.f);
    k_fill<<<blocks(XSZ), 256>>>(pres, XSZ, 0.f);
    k_fill<<<blocks(DEGSZ), 256>>>(pdeg, DEGSZ, 1.f);

    // labels + graph structure (CSR) + weight rounding
    k_labels<<<blocks(BB*NN1*LDD), 256>>>(px0, entLab, tbl);
    k_deg    <<<blocks(BB*EE), 256>>>(pdeg, edgeIdx, edgeAttr);
    k_off    <<<1, 64>>>(pdeg);
    k_scatter<<<blocks(BB*EE), 256>>>(pdeg, edgeIdx, edgeAttr);
    k_wr     <<<blocks(ETRD*HH), 256>>>(W_red, pWr, ETRD*HH);

    // big GEMM on tensor cores (tf32 mma.sync) + fused relu/segmax scatter
    {
        dim3 g(HH/128, (BB*SS)/128);   // (4, 256)
        k_mma_red<<<g, 256, SMEM_BYTES>>>(emb, pWr, b_red, entIdx, px0);
    }

    // GCN: per class, 2 layers; xW dense (merged batches) + sparse aggregation
    {
        dim3 gx((DD+63)/64, (BB*NN1+63)/64, 1);   // (9, 65)
        dim3 gs(NN1, BB);
        for (int c = 0; c < NCLS; c++) {
            for (int l = 0; l < NLAY; l++) {
                const float* in = (l == 0) ? px0 : pxb;
                const float* W  = W_gcn + (long long)(c*NLAY + l)*DD*DD;
                const float* bg = b_gcn + (c*NLAY + l)*DD;
                k_sgemm<<<gx, 256>>>(in, W, ph, BB*NN1, DD, DD, DD, DD, DD);
                k_spmm <<<gs, 256>>>(ph, pxb, pdeg, bg,
                                     (l == NLAY-1) ? pres : nullptr, c);
            }
        }
    }

    // collapsed head/tail + logits
    k_ho<<<blocks(2*DD*3 + 6), 256>>>(W_head, W_tail, W_out, b_head, b_tail,
                                      pWho, pWto, pbho, pbto);
    k_hw<<<blocks(2*BB*NN1*3), 256>>>(pres, pWho, pWto, pbho, pbto, phW, phT);
    k_logits<<<blocks(BB*NN1*(NN1-1)*3), 256>>>(cands, phW, phT, b_out, out);
}

// round 6
// speedup vs baseline: 1.8166x; 1.0010x over previous
#include <cuda_runtime.h>
#include <cuda_bf16.h>
#include <cstdint>

// ---------------------------------------------------------------------------
// Problem constants
// ---------------------------------------------------------------------------
#define BB    16
#define SS    2048
#define NN1   257
#define EE    4096
#define HH    512
#define LDD   16
#define ETRD  768
#define DD    528
#define NCLS  3
#define NLAY  2

#define XSZ   (BB*NN1*DD)
#define DEGSZ (NCLS*BB*NN1)
#define CBSZ  (NCLS*BB)

// ---------------------------------------------------------------------------
// Device scratch
// ---------------------------------------------------------------------------
__device__ float g_x0 [XSZ];
__device__ float g_h  [XSZ];
__device__ float g_xb [XSZ];
__device__ float g_res[XSZ];
__device__ float g_deg[DEGSZ];
__device__ int   g_off[CBSZ*(NN1+1)];
__device__ int   g_cur[CBSZ*NN1];
__device__ int   g_esrc[CBSZ*EE];
__device__ float g_ecoef[CBSZ*EE];
__device__ float g_Wr [ETRD*HH];     // W_red tf32-rounded
__device__ float g_Who[DD*3];
__device__ float g_Wto[DD*3];
__device__ float g_bho[3];
__device__ float g_bto[3];
__device__ float g_hW [BB*NN1*3];
__device__ float g_hT [BB*NN1*3];

__device__ __forceinline__ uint32_t f2tf32(float f) {
    uint32_t r;
    asm("cvt.rna.tf32.f32 %0, %1;" : "=r"(r) : "f"(f));
    return r;
}

__device__ __forceinline__ void mma_tf32(float* c, const uint32_t* a, const uint32_t* b) {
    asm volatile(
        "mma.sync.aligned.m16n8k8.row.col.f32.tf32.tf32.f32 "
        "{%0,%1,%2,%3}, {%4,%5,%6,%7}, {%8,%9}, {%0,%1,%2,%3};"
        : "+f"(c[0]), "+f"(c[1]), "+f"(c[2]), "+f"(c[3])
        : "r"(a[0]), "r"(a[1]), "r"(a[2]), "r"(a[3]), "r"(b[0]), "r"(b[1]));
}

// ---------------------------------------------------------------------------
// Small helper kernels
// ---------------------------------------------------------------------------
__global__ void k_fill(float* __restrict__ p, int n, float v) {
    int i = blockIdx.x * blockDim.x + threadIdx.x;
    if (i < n) p[i] = v;
}

__global__ void k_labels(float* __restrict__ x0,
                         const int* __restrict__ entLab,
                         const float* __restrict__ tbl) {
    int t = blockIdx.x * blockDim.x + threadIdx.x;
    if (t >= BB*NN1*LDD) return;
    int d = t & 15;
    int i = (t >> 4) % NN1;
    int b = t / (NN1*LDD);
    float v;
    if (i == 0) v = tbl[d];
    else {
        int lbl = entLab[b*(NN1-1) + i - 1];
        v = lbl ? tbl[lbl*LDD + d] : 0.f;
    }
    x0[((long long)(b*NN1 + i))*DD + d] = v;
}

__global__ void k_deg(float* __restrict__ deg,
                      const int* __restrict__ ei,
                      const int* __restrict__ ea) {
    int t = blockIdx.x * blockDim.x + threadIdx.x;
    if (t >= BB*EE) return;
    int b = t >> 12, e = t & (EE-1);
    int dst = ei[b*2*EE + EE + e];
    int a   = ea[b*EE + e];
    atomicAdd(&deg[(a*BB + b)*NN1 + dst], 1.f);
}

__global__ void k_off(const float* __restrict__ deg) {
    int t = blockIdx.x * blockDim.x + threadIdx.x;
    if (t >= CBSZ) return;
    const float* dg = deg + t*NN1;
    int* off = g_off + t*(NN1+1);
    int* cur = g_cur + t*NN1;
    int acc = 0;
    off[0] = 0;
    for (int i = 0; i < NN1; i++) {
        cur[i] = acc;
        acc += (int)dg[i] - 1;
        off[i+1] = acc;
    }
}

__global__ void k_scatter(const float* __restrict__ deg,
                          const int* __restrict__ ei,
                          const int* __restrict__ ea) {
    int t = blockIdx.x * blockDim.x + threadIdx.x;
    if (t >= BB*EE) return;
    int b = t >> 12, e = t & (EE-1);
    int src = ei[b*2*EE + e];
    int dst = ei[b*2*EE + EE + e];
    int a   = ea[b*EE + e];
    int cb  = a*BB + b;
    const float* dg = deg + cb*NN1;
    float coef = rsqrtf(dg[src]) * rsqrtf(dg[dst]);
    int pos = atomicAdd(&g_cur[cb*NN1 + dst], 1);
    g_esrc [cb*EE + pos] = src;
    g_ecoef[cb*EE + pos] = coef;
}

__global__ void k_wr(const float* __restrict__ W, float* __restrict__ Wr, int n) {
    int i = blockIdx.x * blockDim.x + threadIdx.x;
    if (i < n) Wr[i] = __uint_as_float(f2tf32(W[i]));
}

// ---------------------------------------------------------------------------
// Big tf32 GEMM, 512 threads (16 warps of 32x32), CTA 128x128, K chunks 32.
// red = emb @ W_red (+bias, relu, segment-max atomic scatter)
// ---------------------------------------------------------------------------
#define SA_LD 36
#define SB_LD 136
#define SA_SZ (128*SA_LD)
#define SB_SZ (32*SB_LD)
#define SMEM_BYTES ((2*SA_SZ + 2*SB_SZ)*4)

__global__ void __launch_bounds__(512, 1) k_mma_red(
    const float* __restrict__ A,      // emb (32768 x 768)
    const float* __restrict__ Bw,     // W_red tf32-rounded (768 x 512)
    const float* __restrict__ bias,
    const int*   __restrict__ entIdx,
    float*       __restrict__ x0)
{
    extern __shared__ float sm[];
    float* sAb[2] = { sm,            sm + SA_SZ };
    float* sBb[2] = { sm + 2*SA_SZ,  sm + 2*SA_SZ + SB_SZ };

    const int tid  = threadIdx.x;
    const int lane = tid & 31;
    const int wid  = tid >> 5;
    const int gr   = lane >> 2;
    const int kq   = lane & 3;
    const int wm   = wid & 3;       // 4 row groups of 32
    const int wn   = wid >> 2;      // 4 col groups of 32
    const int row0 = blockIdx.y * 128;
    const int col0 = blockIdx.x * 128;

    // staging: A 128x32 = 1024 float4 (2/thread), B 32x128 = 1024 float4 (2/thread)
    const int am  = tid >> 2;       // 0..127
    const int akv = tid & 3;        // +4 per pass
    const int bk  = tid >> 4;       // 0..31
    const int bnv = tid & 15;       // +16 per pass

    float acc[2][4][4];
    #pragma unroll
    for (int i = 0; i < 2; i++)
        #pragma unroll
        for (int j = 0; j < 4; j++)
            #pragma unroll
            for (int u = 0; u < 4; u++) acc[i][j][u] = 0.f;

    float4 ra[2], rb[2];

    auto ldchunk = [&](int k0) {
        #pragma unroll
        for (int p = 0; p < 2; p++)
            ra[p] = *(const float4*)(A + (size_t)(row0 + am)*ETRD + k0 + (akv + 4*p)*4);
        #pragma unroll
        for (int p = 0; p < 2; p++)
            rb[p] = *(const float4*)(Bw + (size_t)(k0 + bk)*HH + col0 + (bnv + 16*p)*4);
    };
    auto stchunk = [&](int buf) {
        #pragma unroll
        for (int p = 0; p < 2; p++) {
            float4 v = ra[p];
            v.x = __uint_as_float(f2tf32(v.x));
            v.y = __uint_as_float(f2tf32(v.y));
            v.z = __uint_as_float(f2tf32(v.z));
            v.w = __uint_as_float(f2tf32(v.w));
            *(float4*)(sAb[buf] + am*SA_LD + (akv + 4*p)*4) = v;
        }
        #pragma unroll
        for (int p = 0; p < 2; p++)
            *(float4*)(sBb[buf] + bk*SB_LD + (bnv + 16*p)*4) = rb[p];
    };
    auto compute = [&](int buf) {
        const uint32_t* uA = (const uint32_t*)sAb[buf];
        const uint32_t* uB = (const uint32_t*)sBb[buf];
        #pragma unroll
        for (int ks = 0; ks < 4; ks++) {
            uint32_t af[2][4], bf[4][2];
            #pragma unroll
            for (int mi = 0; mi < 2; mi++) {
                int r = wm*32 + mi*16 + gr;
                af[mi][0] = uA[(size_t)r*SA_LD     + ks*8 + kq];
                af[mi][1] = uA[(size_t)(r+8)*SA_LD + ks*8 + kq];
                af[mi][2] = uA[(size_t)r*SA_LD     + ks*8 + kq + 4];
                af[mi][3] = uA[(size_t)(r+8)*SA_LD + ks*8 + kq + 4];
            }
            #pragma unroll
            for (int ni = 0; ni < 4; ni++) {
                int c = wn*32 + ni*8 + gr;
                bf[ni][0] = uB[(size_t)(ks*8 + kq)*SB_LD     + c];
                bf[ni][1] = uB[(size_t)(ks*8 + kq + 4)*SB_LD + c];
            }
            #pragma unroll
            for (int mi = 0; mi < 2; mi++)
                #pragma unroll
                for (int ni = 0; ni < 4; ni++)
                    mma_tf32(acc[mi][ni], af[mi], bf[ni]);
        }
    };

    ldchunk(0);
    stchunk(0);
    __syncthreads();
    #pragma unroll 1
    for (int ch = 0; ch < ETRD/32; ch++) {
        if (ch + 1 < ETRD/32) ldchunk((ch + 1)*32);
        compute(ch & 1);
        if (ch + 1 < ETRD/32) {
            stchunk((ch + 1) & 1);
            __syncthreads();
        }
    }

    // Epilogue: fused bias + relu + segment-max scatter
    int    nodev[2][2];
    float* basep[2][2];
    #pragma unroll
    for (int mi = 0; mi < 2; mi++)
        #pragma unroll
        for (int h = 0; h < 2; h++) {
            int r  = row0 + wm*32 + mi*16 + gr + h*8;
            int nd = entIdx[r];
            nodev[mi][h] = nd;
            int b = r >> 11;
            basep[mi][h] = x0 + ((size_t)(b*NN1 + nd))*DD + LDD;
        }
    #pragma unroll
    for (int ni = 0; ni < 4; ni++) {
        int c = col0 + wn*32 + ni*8 + kq*2;
        float b0 = __ldg(bias + c), b1 = __ldg(bias + c + 1);
        #pragma unroll
        for (int mi = 0; mi < 2; mi++) {
            #pragma unroll
            for (int h = 0; h < 2; h++) {
                if (nodev[mi][h] == 0) continue;
                float v0 = fmaxf(acc[mi][ni][2*h    ] + b0, 0.f);
                float v1 = fmaxf(acc[mi][ni][2*h + 1] + b1, 0.f);
                atomicMax((int*)(basep[mi][h] + c),     __float_as_int(v0));
                atomicMax((int*)(basep[mi][h] + c + 1), __float_as_int(v1));
            }
        }
    }
}

// ---------------------------------------------------------------------------
// tf32 GEMM for xW: h = x @ W  (M=4112, N=K=528), guarded, K chunks of 16.
// 512 threads, CTA 128x128, warp tile 32x32.
// ---------------------------------------------------------------------------
#define XA_LD 20
#define XB_LD 136
#define XA_SZ (128*XA_LD)   // 2560
#define XB_SZ (16*XB_LD)    // 2176
#define XW_SMEM ((2*XA_SZ + 2*XB_SZ)*4)

__global__ void __launch_bounds__(512, 1) k_mma_xw(
    const float* __restrict__ A,      // x (M x 528)
    const float* __restrict__ Bw,     // W (528 x 528) raw fp32
    float*       __restrict__ C,      // h (M x 528)
    int M)
{
    extern __shared__ float sm[];
    float* sAb[2] = { sm,            sm + XA_SZ };
    float* sBb[2] = { sm + 2*XA_SZ,  sm + 2*XA_SZ + XB_SZ };

    const int tid  = threadIdx.x;
    const int lane = tid & 31;
    const int wid  = tid >> 5;
    const int gr   = lane >> 2;
    const int kq   = lane & 3;
    const int wm   = wid & 3;
    const int wn   = wid >> 2;
    const int row0 = blockIdx.y * 128;
    const int col0 = blockIdx.x * 128;

    // staging: A 128x16 = 512 float4 (1/thread), B 16x128 = 512 float4 (1/thread)
    const int am  = tid >> 2;       // 0..127
    const int akv = tid & 3;        // float4 col
    const int bk  = tid >> 5;       // 0..15
    const int bnv = tid & 31;       // float4 col

    float acc[2][4][4];
    #pragma unroll
    for (int i = 0; i < 2; i++)
        #pragma unroll
        for (int j = 0; j < 4; j++)
            #pragma unroll
            for (int u = 0; u < 4; u++) acc[i][j][u] = 0.f;

    float4 ra, rb;

    auto ldchunk = [&](int k0) {
        int gm = row0 + am;
        ra = (gm < M) ? *(const float4*)(A + (size_t)gm*DD + k0 + akv*4)
                      : make_float4(0.f, 0.f, 0.f, 0.f);
        int gn = col0 + bnv*4;
        rb = (gn + 3 < DD) ? *(const float4*)(Bw + (size_t)(k0 + bk)*DD + gn)
                           : make_float4(0.f, 0.f, 0.f, 0.f);
    };
    auto stchunk = [&](int buf) {
        float4 v = ra;
        v.x = __uint_as_float(f2tf32(v.x));
        v.y = __uint_as_float(f2tf32(v.y));
        v.z = __uint_as_float(f2tf32(v.z));
        v.w = __uint_as_float(f2tf32(v.w));
        *(float4*)(sAb[buf] + am*XA_LD + akv*4) = v;
        float4 w = rb;
        w.x = __uint_as_float(f2tf32(w.x));
        w.y = __uint_as_float(f2tf32(w.y));
        w.z = __uint_as_float(f2tf32(w.z));
        w.w = __uint_as_float(f2tf32(w.w));
        *(float4*)(sBb[buf] + bk*XB_LD + bnv*4) = w;
    };
    auto compute = [&](int buf) {
        const uint32_t* uA = (const uint32_t*)sAb[buf];
        const uint32_t* uB = (const uint32_t*)sBb[buf];
        #pragma unroll
        for (int ks = 0; ks < 2; ks++) {
            uint32_t af[2][4], bf[4][2];
            #pragma unroll
            for (int mi = 0; mi < 2; mi++) {
                int r = wm*32 + mi*16 + gr;
                af[mi][0] = uA[(size_t)r*XA_LD     + ks*8 + kq];
                af[mi][1] = uA[(size_t)(r+8)*XA_LD + ks*8 + kq];
                af[mi][2] = uA[(size_t)r*XA_LD     + ks*8 + kq + 4];
                af[mi][3] = uA[(size_t)(r+8)*XA_LD + ks*8 + kq + 4];
            }
            #pragma unroll
            for (int ni = 0; ni < 4; ni++) {
                int c = wn*32 + ni*8 + gr;
                bf[ni][0] = uB[(size_t)(ks*8 + kq)*XB_LD     + c];
                bf[ni][1] = uB[(size_t)(ks*8 + kq + 4)*XB_LD + c];
            }
            #pragma unroll
            for (int mi = 0; mi < 2; mi++)
                #pragma unroll
                for (int ni = 0; ni < 4; ni++)
                    mma_tf32(acc[mi][ni], af[mi], bf[ni]);
        }
    };

    ldchunk(0);
    stchunk(0);
    __syncthreads();
    #pragma unroll 1
    for (int ch = 0; ch < DD/16; ch++) {       // 33 exact chunks
        if (ch + 1 < DD/16) ldchunk((ch + 1)*16);
        compute(ch & 1);
        if (ch + 1 < DD/16) {
            stchunk((ch + 1) & 1);
            __syncthreads();
        }
    }

    // Epilogue: plain guarded store
    #pragma unroll
    for (int mi = 0; mi < 2; mi++) {
        #pragma unroll
        for (int h = 0; h < 2; h++) {
            int gm = row0 + wm*32 + mi*16 + gr + h*8;
            if (gm >= M) continue;
            #pragma unroll
            for (int ni = 0; ni < 4; ni++) {
                int gn = col0 + wn*32 + ni*8 + kq*2;
                if (gn + 1 < DD) {
                    C[(size_t)gm*DD + gn    ] = acc[mi][ni][2*h];
                    C[(size_t)gm*DD + gn + 1] = acc[mi][ni][2*h + 1];
                }
            }
        }
    }
}

// ---------------------------------------------------------------------------
// Sparse GCN aggregation
// ---------------------------------------------------------------------------
__global__ void __launch_bounds__(256) k_spmm(
    const float* __restrict__ h,
    float* __restrict__ xb,
    const float* __restrict__ deg,
    const float* __restrict__ bias,
    float* __restrict__ res,
    int cls)
{
    int dst = blockIdx.x;
    int b   = blockIdx.y;
    int cb  = cls*BB + b;
    int tid = threadIdx.x;

    const int* off = g_off + cb*(NN1+1);
    int e0 = off[dst], e1 = off[dst+1];
    const int*   es = g_esrc  + cb*EE;
    const float* ec = g_ecoef + cb*EE;
    const float* hb = h + (size_t)b*NN1*DD;

    int c0 = tid, c1 = tid + 256, c2 = tid + 512;
    float a0 = 0.f, a1 = 0.f, a2 = 0.f;

    for (int e = e0; e < e1; e++) {
        int   src = es[e];
        float w   = ec[e];
        const float* hr = hb + (size_t)src*DD;
        a0 += w * hr[c0];
        if (c1 < DD) a1 += w * hr[c1];
        if (c2 < DD) a2 += w * hr[c2];
    }

    float dinv = 1.f / deg[cb*NN1 + dst];
    const float* hd = hb + (size_t)dst*DD;
    float* xo = xb + ((size_t)b*NN1 + dst)*DD;
    float* ro = res ? res + ((size_t)b*NN1 + dst)*DD : nullptr;

    float v0 = a0 + hd[c0]*dinv + bias[c0];
    xo[c0] = v0;
    if (ro) ro[c0] += v0;
    if (c1 < DD) {
        float v1 = a1 + hd[c1]*dinv + bias[c1];
        xo[c1] = v1;
        if (ro) ro[c1] += v1;
    }
    if (c2 < DD) {
        float v2 = a2 + hd[c2]*dinv + bias[c2];
        xo[c2] = v2;
        if (ro) ro[c2] += v2;
    }
}

// ---------------------------------------------------------------------------
// Collapsed head/tail + logits
// ---------------------------------------------------------------------------
__global__ void k_ho(const float* __restrict__ W_head, const float* __restrict__ W_tail,
                     const float* __restrict__ W_out,
                     const float* __restrict__ b_head, const float* __restrict__ b_tail,
                     float* __restrict__ Who, float* __restrict__ Wto,
                     float* __restrict__ bho, float* __restrict__ bto) {
    int t = blockIdx.x * blockDim.x + threadIdx.x;
    if (t < 2*DD*3) {
        int which = t / (DD*3), rc = t % (DD*3), r = rc / 3, c = rc % 3;
        const float* W = which ? W_tail : W_head;
        float acc = 0.f;
        for (int j = 0; j < DD; j++) acc += W[r*DD + j] * W_out[j*3 + c];
        (which ? Wto : Who)[r*3 + c] = acc;
    } else if (t < 2*DD*3 + 6) {
        int u = t - 2*DD*3, which = u / 3, c = u % 3;
        const float* bb = which ? b_tail : b_head;
        float acc = 0.f;
        for (int j = 0; j < DD; j++) acc += bb[j] * W_out[j*3 + c];
        (which ? bto : bho)[c] = acc;
    }
}

__global__ void k_hw(const float* __restrict__ res,
                     const float* __restrict__ Who, const float* __restrict__ Wto,
                     const float* __restrict__ bho, const float* __restrict__ bto,
                     float* __restrict__ hW, float* __restrict__ hT) {
    int t = blockIdx.x * blockDim.x + threadIdx.x;
    if (t >= 2*BB*NN1*3) return;
    int which = t / (BB*NN1*3);
    int rem = t % (BB*NN1*3);
    int bi = rem / 3, c = rem % 3;
    const float* row = res + (long long)bi*DD;
    const float* W   = which ? Wto : Who;
    float acc = 0.f;
    for (int k = 0; k < DD; k++) acc += row[k] * W[k*3 + c];
    acc = acc * (1.f/3.f) + (which ? bto[c] : bho[c]);
    (which ? hT : hW)[bi*3 + c] = acc;
}

__global__ void k_logits(const int* __restrict__ cands,
                         const float* __restrict__ hW, const float* __restrict__ hT,
                         const float* __restrict__ b_out,
                         float* __restrict__ out) {
    int t = blockIdx.x * blockDim.x + threadIdx.x;
    const int TOT = BB*NN1*(NN1-1)*3;
    if (t >= TOT) return;
    int c = t % 3;
    int j = (t / 3) & 255;
    int i = (t / (3*256)) % NN1;
    int b = t / (3*256*NN1);
    int m = cands[((long long)(b*NN1 + i))*NN1 + j + 1];
    float v = b_out[c];
    if (m) v += hW[(b*NN1 + i)*3 + c] + hT[(b*NN1 + j + 1)*3 + c];
    out[t] = v;
}

// ---------------------------------------------------------------------------
// Launch
// ---------------------------------------------------------------------------
extern "C" void kernel_launch(void* const* d_in, const int* in_sizes, int n_in,
                              void* d_out, int out_size) {
    const float* emb     = (const float*)d_in[0];
    const int*   entIdx  = (const int*)  d_in[1];
    const int*   entLab  = (const int*)  d_in[2];
    const int*   edgeIdx = (const int*)  d_in[3];
    const int*   edgeAttr= (const int*)  d_in[4];
    const int*   cands   = (const int*)  d_in[5];
    const float* W_red   = (const float*)d_in[6];
    const float* b_red   = (const float*)d_in[7];
    const float* tbl     = (const float*)d_in[8];
    const float* W_gcn   = (const float*)d_in[9];
    const float* b_gcn   = (const float*)d_in[10];
    const float* W_head  = (const float*)d_in[11];
    const float* b_head  = (const float*)d_in[12];
    const float* W_tail  = (const float*)d_in[13];
    const float* b_tail  = (const float*)d_in[14];
    const float* W_out   = (const float*)d_in[15];
    const float* b_out   = (const float*)d_in[16];
    float* out = (float*)d_out;

    static float *px0=nullptr, *ph, *pxb, *pres, *pdeg, *pWr,
                 *pWho, *pWto, *pbho, *pbto, *phW, *phT;
    static bool attr_set = false;
    if (!px0) {
        cudaGetSymbolAddress((void**)&px0,  g_x0);
        cudaGetSymbolAddress((void**)&ph,   g_h);
        cudaGetSymbolAddress((void**)&pxb,  g_xb);
        cudaGetSymbolAddress((void**)&pres, g_res);
        cudaGetSymbolAddress((void**)&pdeg, g_deg);
        cudaGetSymbolAddress((void**)&pWr,  g_Wr);
        cudaGetSymbolAddress((void**)&pWho, g_Who);
        cudaGetSymbolAddress((void**)&pWto, g_Wto);
        cudaGetSymbolAddress((void**)&pbho, g_bho);
        cudaGetSymbolAddress((void**)&pbto, g_bto);
        cudaGetSymbolAddress((void**)&phW,  g_hW);
        cudaGetSymbolAddress((void**)&phT,  g_hT);
    }
    if (!attr_set) {
        cudaFuncSetAttribute(k_mma_red, cudaFuncAttributeMaxDynamicSharedMemorySize, SMEM_BYTES);
        cudaFuncSetAttribute(k_mma_xw,  cudaFuncAttributeMaxDynamicSharedMemorySize, XW_SMEM);
        attr_set = true;
    }

    auto blocks = [](int n) { return (n + 255) / 256; };

    // init scratch
    k_fill<<<blocks(XSZ), 256>>>(px0,  XSZ, 0.f);
    k_fill<<<blocks(XSZ), 256>>>(pres, XSZ, 0.f);
    k_fill<<<blocks(DEGSZ), 256>>>(pdeg, DEGSZ, 1.f);

    // labels + graph structure (CSR) + weight rounding
    k_labels<<<blocks(BB*NN1*LDD), 256>>>(px0, entLab, tbl);
    k_deg    <<<blocks(BB*EE), 256>>>(pdeg, edgeIdx, edgeAttr);
    k_off    <<<1, 64>>>(pdeg);
    k_scatter<<<blocks(BB*EE), 256>>>(pdeg, edgeIdx, edgeAttr);
    k_wr     <<<blocks(ETRD*HH), 256>>>(W_red, pWr, ETRD*HH);

    // big GEMM on tensor cores (tf32, 16 warps) + fused relu/segmax scatter
    {
        dim3 g(HH/128, (BB*SS)/128);   // (4, 256)
        k_mma_red<<<g, 512, SMEM_BYTES>>>(emb, pWr, b_red, entIdx, px0);
    }

    // GCN: per class, 2 layers; tf32 xW + sparse aggregation
    {
        dim3 gx((DD + 127)/128, (BB*NN1 + 127)/128);   // (5, 33)
        dim3 gs(NN1, BB);
        for (int c = 0; c < NCLS; c++) {
            for (int l = 0; l < NLAY; l++) {
                const float* in = (l == 0) ? px0 : pxb;
                const float* W  = W_gcn + (long long)(c*NLAY + l)*DD*DD;
                const float* bg = b_gcn + (c*NLAY + l)*DD;
                k_mma_xw<<<gx, 512, XW_SMEM>>>(in, W, ph, BB*NN1);
                k_spmm  <<<gs, 256>>>(ph, pxb, pdeg, bg,
                                      (l == NLAY-1) ? pres : nullptr, c);
            }
        }
    }

    // collapsed head/tail + logits
    k_ho<<<blocks(2*DD*3 + 6), 256>>>(W_head, W_tail, W_out, b_head, b_tail,
                                      pWho, pWto, pbho, pbto);
    k_hw<<<blocks(2*BB*NN1*3), 256>>>(pres, pWho, pWto, pbho, pbto, phW, phT);
    k_logits<<<blocks(BB*NN1*(NN1-1)*3), 256>>>(cands, phW, phT, b_out, out);
}

// round 7
// speedup vs baseline: 2.4586x; 1.3534x over previous
#include <cuda_runtime.h>
#include <cuda_fp16.h>
#include <cstdint>

// ---------------------------------------------------------------------------
// Problem constants
// ---------------------------------------------------------------------------
#define BB    16
#define SS    2048
#define NN1   257
#define EE    4096
#define HH    512
#define LDD   16
#define ETRD  768
#define DD    528
#define NCLS  3
#define NLAY  2

#define XSZ   (BB*NN1*DD)
#define DEGSZ (NCLS*BB*NN1)
#define CBSZ  (NCLS*BB)

// ---------------------------------------------------------------------------
// Device scratch
// ---------------------------------------------------------------------------
__device__ float  g_x0 [XSZ];
__device__ float  g_hc [NCLS*XSZ];
__device__ float  g_xbc[NCLS*XSZ];
__device__ float  g_deg[DEGSZ];
__device__ int    g_off[CBSZ*(NN1+1)];
__device__ int    g_cur[CBSZ*NN1];
__device__ int    g_esrc[CBSZ*EE];
__device__ float  g_ecoef[CBSZ*EE];
__device__ __half g_Wt [HH*ETRD];          // W_red^T  (n-major) fp16
__device__ __half g_Wg [NCLS*NLAY*DD*DD];  // W_gcn^T per (c,l), n-major fp16
__device__ float  g_Who[DD*3];
__device__ float  g_Wto[DD*3];
__device__ float  g_bho[3];
__device__ float  g_bto[3];
__device__ float  g_hW [BB*NN1*3];
__device__ float  g_hT [BB*NN1*3];

// ---------------------------------------------------------------------------
// fp16 mma (m16n8k16, f32 accum)
// ---------------------------------------------------------------------------
__device__ __forceinline__ void mma_f16(float* c, const uint32_t* a, const uint32_t* b) {
    asm volatile(
        "mma.sync.aligned.m16n8k16.row.col.f32.f16.f16.f32 "
        "{%0,%1,%2,%3}, {%4,%5,%6,%7}, {%8,%9}, {%0,%1,%2,%3};"
        : "+f"(c[0]), "+f"(c[1]), "+f"(c[2]), "+f"(c[3])
        : "r"(a[0]), "r"(a[1]), "r"(a[2]), "r"(a[3]), "r"(b[0]), "r"(b[1]));
}

__device__ __forceinline__ uint32_t pack_h2(float x, float y) {
    __half2 h = __floats2half2_rn(x, y);   // low = x
    return *(uint32_t*)&h;
}

// ---------------------------------------------------------------------------
// Small helper kernels
// ---------------------------------------------------------------------------
__global__ void k_fill(float* __restrict__ p, int n, float v) {
    int i = blockIdx.x * blockDim.x + threadIdx.x;
    if (i < n) p[i] = v;
}

__global__ void k_labels(float* __restrict__ x0,
                         const int* __restrict__ entLab,
                         const float* __restrict__ tbl) {
    int t = blockIdx.x * blockDim.x + threadIdx.x;
    if (t >= BB*NN1*LDD) return;
    int d = t & 15;
    int i = (t >> 4) % NN1;
    int b = t / (NN1*LDD);
    float v;
    if (i == 0) v = tbl[d];
    else {
        int lbl = entLab[b*(NN1-1) + i - 1];
        v = lbl ? tbl[lbl*LDD + d] : 0.f;
    }
    x0[((long long)(b*NN1 + i))*DD + d] = v;
}

__global__ void k_deg(float* __restrict__ deg,
                      const int* __restrict__ ei,
                      const int* __restrict__ ea) {
    int t = blockIdx.x * blockDim.x + threadIdx.x;
    if (t >= BB*EE) return;
    int b = t >> 12, e = t & (EE-1);
    int dst = ei[b*2*EE + EE + e];
    int a   = ea[b*EE + e];
    atomicAdd(&deg[(a*BB + b)*NN1 + dst], 1.f);
}

__global__ void k_off(const float* __restrict__ deg) {
    int t = blockIdx.x * blockDim.x + threadIdx.x;
    if (t >= CBSZ) return;
    const float* dg = deg + t*NN1;
    int* off = g_off + t*(NN1+1);
    int* cur = g_cur + t*NN1;
    int acc = 0;
    off[0] = 0;
    for (int i = 0; i < NN1; i++) {
        cur[i] = acc;
        acc += (int)dg[i] - 1;
        off[i+1] = acc;
    }
}

__global__ void k_scatter(const float* __restrict__ deg,
                          const int* __restrict__ ei,
                          const int* __restrict__ ea) {
    int t = blockIdx.x * blockDim.x + threadIdx.x;
    if (t >= BB*EE) return;
    int b = t >> 12, e = t & (EE-1);
    int src = ei[b*2*EE + e];
    int dst = ei[b*2*EE + EE + e];
    int a   = ea[b*EE + e];
    int cb  = a*BB + b;
    const float* dg = deg + cb*NN1;
    float coef = rsqrtf(dg[src]) * rsqrtf(dg[dst]);
    int pos = atomicAdd(&g_cur[cb*NN1 + dst], 1);
    g_esrc [cb*EE + pos] = src;
    g_ecoef[cb*EE + pos] = coef;
}

// transpose + fp16 convert: W [K][N] f32 -> Wt [N][K] fp16 (z-batched)
__global__ void k_th(const float* __restrict__ W, __half* __restrict__ Wt,
                     int K, int N) {
    const float* Wz  = W  + (size_t)blockIdx.z*K*N;
    __half*      Wtz = Wt + (size_t)blockIdx.z*K*N;
    __shared__ float t[32][33];
    int k = blockIdx.x*32 + threadIdx.y;
    int n = blockIdx.y*32 + threadIdx.x;
    if (k < K && n < N) t[threadIdx.y][threadIdx.x] = Wz[(size_t)k*N + n];
    __syncthreads();
    int no = blockIdx.y*32 + threadIdx.y;
    int ko = blockIdx.x*32 + threadIdx.x;
    if (no < N && ko < K) Wtz[(size_t)no*K + ko] = __float2half_rn(t[threadIdx.x][threadIdx.y]);
}

// ---------------------------------------------------------------------------
// Big fp16 GEMM: red = emb @ W_red (+bias, relu, segment-max atomic scatter).
// M=32768, N=512, K=768. 512 thr, 16 warps of 32x32, K chunks 32, dbl-buffer.
// SMEM: As[m=128][k pad 40] halfs, Bst[n=128][k pad 40] halfs.
// ---------------------------------------------------------------------------
#define RA_LD 40
#define R_SZH (128*RA_LD)                   // halfs per buffer
#define RED_SMEM (4*R_SZH*2)                // 2 bufs x (A+B), bytes

__global__ void __launch_bounds__(512, 1) k_mma_red(
    const float*  __restrict__ A,      // emb (32768 x 768) f32
    const __half* __restrict__ Bt,     // W_red^T (512 x 768) fp16 n-major
    const float*  __restrict__ bias,
    const int*    __restrict__ entIdx,
    float*        __restrict__ x0)
{
    extern __shared__ __half smh[];
    __half* sAb[2] = { smh,            smh + R_SZH };
    __half* sBb[2] = { smh + 2*R_SZH,  smh + 3*R_SZH };

    const int tid  = threadIdx.x;
    const int lane = tid & 31;
    const int wid  = tid >> 5;
    const int gr   = lane >> 2;
    const int kq   = lane & 3;
    const int wm   = wid & 3;
    const int wn   = wid >> 2;
    const int row0 = blockIdx.y * 128;
    const int col0 = blockIdx.x * 128;

    const int sr = tid >> 2;      // 0..127 staging row
    const int sg = tid & 3;       // 0..3

    float acc[2][4][4];
    #pragma unroll
    for (int i = 0; i < 2; i++)
        #pragma unroll
        for (int j = 0; j < 4; j++)
            #pragma unroll
            for (int u = 0; u < 4; u++) acc[i][j][u] = 0.f;

    float4 ra[2];
    uint4  rb;

    auto ldchunk = [&](int k0) {
        #pragma unroll
        for (int p = 0; p < 2; p++)
            ra[p] = *(const float4*)(A + (size_t)(row0 + sr)*ETRD + k0 + (sg + 4*p)*4);
        rb = *(const uint4*)(Bt + (size_t)(col0 + sr)*ETRD + k0 + sg*8);
    };
    auto stchunk = [&](int buf) {
        #pragma unroll
        for (int p = 0; p < 2; p++) {
            uint2 u;
            u.x = pack_h2(ra[p].x, ra[p].y);
            u.y = pack_h2(ra[p].z, ra[p].w);
            *(uint2*)(sAb[buf] + sr*RA_LD + (sg + 4*p)*4) = u;
        }
        *(uint4*)(sBb[buf] + sr*RA_LD + sg*8) = rb;
    };
    auto compute = [&](int buf) {
        const __half* hA = sAb[buf];
        const __half* hB = sBb[buf];
        #pragma unroll
        for (int ks = 0; ks < 2; ks++) {
            uint32_t af[2][4], bf[4][2];
            #pragma unroll
            for (int mi = 0; mi < 2; mi++) {
                int r = wm*32 + mi*16 + gr;
                af[mi][0] = *(const uint32_t*)(hA + (size_t)r*RA_LD     + ks*16 + 2*kq);
                af[mi][1] = *(const uint32_t*)(hA + (size_t)(r+8)*RA_LD + ks*16 + 2*kq);
                af[mi][2] = *(const uint32_t*)(hA + (size_t)r*RA_LD     + ks*16 + 2*kq + 8);
                af[mi][3] = *(const uint32_t*)(hA + (size_t)(r+8)*RA_LD + ks*16 + 2*kq + 8);
            }
            #pragma unroll
            for (int ni = 0; ni < 4; ni++) {
                int c = wn*32 + ni*8 + gr;
                bf[ni][0] = *(const uint32_t*)(hB + (size_t)c*RA_LD + ks*16 + 2*kq);
                bf[ni][1] = *(const uint32_t*)(hB + (size_t)c*RA_LD + ks*16 + 2*kq + 8);
            }
            #pragma unroll
            for (int mi = 0; mi < 2; mi++)
                #pragma unroll
                for (int ni = 0; ni < 4; ni++)
                    mma_f16(acc[mi][ni], af[mi], bf[ni]);
        }
    };

    ldchunk(0);
    stchunk(0);
    __syncthreads();
    #pragma unroll 1
    for (int ch = 0; ch < ETRD/32; ch++) {
        if (ch + 1 < ETRD/32) ldchunk((ch + 1)*32);
        compute(ch & 1);
        if (ch + 1 < ETRD/32) {
            stchunk((ch + 1) & 1);
            __syncthreads();
        }
    }

    // Epilogue: fused bias + relu + segment-max scatter
    int    nodev[2][2];
    float* basep[2][2];
    #pragma unroll
    for (int mi = 0; mi < 2; mi++)
        #pragma unroll
        for (int h = 0; h < 2; h++) {
            int r  = row0 + wm*32 + mi*16 + gr + h*8;
            int nd = entIdx[r];
            nodev[mi][h] = nd;
            int b = r >> 11;
            basep[mi][h] = x0 + ((size_t)(b*NN1 + nd))*DD + LDD;
        }
    #pragma unroll
    for (int ni = 0; ni < 4; ni++) {
        int c = col0 + wn*32 + ni*8 + kq*2;
        float b0 = __ldg(bias + c), b1 = __ldg(bias + c + 1);
        #pragma unroll
        for (int mi = 0; mi < 2; mi++) {
            #pragma unroll
            for (int h = 0; h < 2; h++) {
                if (nodev[mi][h] == 0) continue;
                float v0 = fmaxf(acc[mi][ni][2*h    ] + b0, 0.f);
                float v1 = fmaxf(acc[mi][ni][2*h + 1] + b1, 0.f);
                atomicMax((int*)(basep[mi][h] + c),     __float_as_int(v0));
                atomicMax((int*)(basep[mi][h] + c + 1), __float_as_int(v1));
            }
        }
    }
}

// ---------------------------------------------------------------------------
// fp16 GEMM for xW, 3 classes via grid.z: h_z = x_z @ W_z.
// M=4112, N=K=528. K chunks of 16. 512 thr, warp tile 32x32.
// ---------------------------------------------------------------------------
#define XA_LD 24
#define X_SZH (128*XA_LD)
#define XW_SMEM (4*X_SZH*2)

__global__ void __launch_bounds__(512, 1) k_mma_xw(
    const float*  __restrict__ Abase,  // x (M x 528) f32; + z*strideA
    const __half* __restrict__ Wg,     // W^T fp16 n-major; + (z*NLAY+l)*DD*DD
    float*        __restrict__ Cbase,  // h ; + z*XSZ
    int M, long long strideA, int layer)
{
    const int z = blockIdx.z;
    const float*  A  = Abase + (size_t)z*strideA;
    const __half* Bt = Wg + ((size_t)z*NLAY + layer)*DD*DD;
    float* C = Cbase + (size_t)z*XSZ;

    extern __shared__ __half smh[];
    __half* sAb[2] = { smh,            smh + X_SZH };
    __half* sBb[2] = { smh + 2*X_SZH,  smh + 3*X_SZH };

    const int tid  = threadIdx.x;
    const int lane = tid & 31;
    const int wid  = tid >> 5;
    const int gr   = lane >> 2;
    const int kq   = lane & 3;
    const int wm   = wid & 3;
    const int wn   = wid >> 2;
    const int row0 = blockIdx.y * 128;
    const int col0 = blockIdx.x * 128;

    const int sr = tid >> 2;
    const int sg = tid & 3;

    float acc[2][4][4];
    #pragma unroll
    for (int i = 0; i < 2; i++)
        #pragma unroll
        for (int j = 0; j < 4; j++)
            #pragma unroll
            for (int u = 0; u < 4; u++) acc[i][j][u] = 0.f;

    float4 ra;
    uint2  rb;

    auto ldchunk = [&](int k0) {
        int gm = row0 + sr;
        ra = (gm < M) ? *(const float4*)(A + (size_t)gm*DD + k0 + sg*4)
                      : make_float4(0.f, 0.f, 0.f, 0.f);
        int gn = col0 + sr;
        rb = (gn < DD) ? *(const uint2*)(Bt + (size_t)gn*DD + k0 + sg*4)
                       : make_uint2(0u, 0u);
    };
    auto stchunk = [&](int buf) {
        uint2 u;
        u.x = pack_h2(ra.x, ra.y);
        u.y = pack_h2(ra.z, ra.w);
        *(uint2*)(sAb[buf] + sr*XA_LD + sg*4) = u;
        *(uint2*)(sBb[buf] + sr*XA_LD + sg*4) = rb;
    };
    auto compute = [&](int buf) {
        const __half* hA = sAb[buf];
        const __half* hB = sBb[buf];
        uint32_t af[2][4], bf[4][2];
        #pragma unroll
        for (int mi = 0; mi < 2; mi++) {
            int r = wm*32 + mi*16 + gr;
            af[mi][0] = *(const uint32_t*)(hA + (size_t)r*XA_LD     + 2*kq);
            af[mi][1] = *(const uint32_t*)(hA + (size_t)(r+8)*XA_LD + 2*kq);
            af[mi][2] = *(const uint32_t*)(hA + (size_t)r*XA_LD     + 2*kq + 8);
            af[mi][3] = *(const uint32_t*)(hA + (size_t)(r+8)*XA_LD + 2*kq + 8);
        }
        #pragma unroll
        for (int ni = 0; ni < 4; ni++) {
            int c = wn*32 + ni*8 + gr;
            bf[ni][0] = *(const uint32_t*)(hB + (size_t)c*XA_LD + 2*kq);
            bf[ni][1] = *(const uint32_t*)(hB + (size_t)c*XA_LD + 2*kq + 8);
        }
        #pragma unroll
        for (int mi = 0; mi < 2; mi++)
            #pragma unroll
            for (int ni = 0; ni < 4; ni++)
                mma_f16(acc[mi][ni], af[mi], bf[ni]);
    };

    ldchunk(0);
    stchunk(0);
    __syncthreads();
    #pragma unroll 1
    for (int ch = 0; ch < DD/16; ch++) {      // 33 exact chunks
        if (ch + 1 < DD/16) ldchunk((ch + 1)*16);
        compute(ch & 1);
        if (ch + 1 < DD/16) {
            stchunk((ch + 1) & 1);
            __syncthreads();
        }
    }

    #pragma unroll
    for (int mi = 0; mi < 2; mi++) {
        #pragma unroll
        for (int h = 0; h < 2; h++) {
            int gm = row0 + wm*32 + mi*16 + gr + h*8;
            if (gm >= M) continue;
            #pragma unroll
            for (int ni = 0; ni < 4; ni++) {
                int gn = col0 + wn*32 + ni*8 + kq*2;
                if (gn + 1 < DD) {
                    C[(size_t)gm*DD + gn    ] = acc[mi][ni][2*h];
                    C[(size_t)gm*DD + gn + 1] = acc[mi][ni][2*h + 1];
                }
            }
        }
    }
}

// ---------------------------------------------------------------------------
// Sparse GCN aggregation, 3 classes via grid.z
// ---------------------------------------------------------------------------
__global__ void __launch_bounds__(256) k_spmm(
    const float* __restrict__ hbase,
    float* __restrict__ xbbase,
    const float* __restrict__ deg,
    const float* __restrict__ bgcn,    // b_gcn base; + (cls*NLAY+layer)*DD
    int layer)
{
    int dst = blockIdx.x;
    int b   = blockIdx.y;
    int cls = blockIdx.z;
    int cb  = cls*BB + b;
    int tid = threadIdx.x;

    const float* bias = bgcn + (size_t)(cls*NLAY + layer)*DD;
    const float* h    = hbase + (size_t)cls*XSZ;
    float*       xb   = xbbase + (size_t)cls*XSZ;

    const int* off = g_off + cb*(NN1+1);
    int e0 = off[dst], e1 = off[dst+1];
    const int*   es = g_esrc  + cb*EE;
    const float* ec = g_ecoef + cb*EE;
    const float* hb = h + (size_t)b*NN1*DD;

    int c0 = tid, c1 = tid + 256, c2 = tid + 512;
    float a0 = 0.f, a1 = 0.f, a2 = 0.f;

    for (int e = e0; e < e1; e++) {
        int   src = es[e];
        float w   = ec[e];
        const float* hr = hb + (size_t)src*DD;
        a0 += w * hr[c0];
        if (c1 < DD) a1 += w * hr[c1];
        if (c2 < DD) a2 += w * hr[c2];
    }

    float dinv = 1.f / deg[cb*NN1 + dst];
    const float* hd = hb + (size_t)dst*DD;
    float* xo = xb + ((size_t)b*NN1 + dst)*DD;

    xo[c0] = a0 + hd[c0]*dinv + bias[c0];
    if (c1 < DD) xo[c1] = a1 + hd[c1]*dinv + bias[c1];
    if (c2 < DD) xo[c2] = a2 + hd[c2]*dinv + bias[c2];
}

// ---------------------------------------------------------------------------
// Collapsed head/tail + logits
// ---------------------------------------------------------------------------
__global__ void k_ho(const float* __restrict__ W_head, const float* __restrict__ W_tail,
                     const float* __restrict__ W_out,
                     const float* __restrict__ b_head, const float* __restrict__ b_tail,
                     float* __restrict__ Who, float* __restrict__ Wto,
                     float* __restrict__ bho, float* __restrict__ bto) {
    int t = blockIdx.x * blockDim.x + threadIdx.x;
    if (t < 2*DD*3) {
        int which = t / (DD*3), rc = t % (DD*3), r = rc / 3, c = rc % 3;
        const float* W = which ? W_tail : W_head;
        float acc = 0.f;
        for (int j = 0; j < DD; j++) acc += W[r*DD + j] * W_out[j*3 + c];
        (which ? Wto : Who)[r*3 + c] = acc;
    } else if (t < 2*DD*3 + 6) {
        int u = t - 2*DD*3, which = u / 3, c = u % 3;
        const float* bb = which ? b_tail : b_head;
        float acc = 0.f;
        for (int j = 0; j < DD; j++) acc += bb[j] * W_out[j*3 + c];
        (which ? bto : bho)[c] = acc;
    }
}

// hW[b,i,c] = ((xb0+xb1+xb2)[b,i,:]/3) @ Who[:,c] + bho[c]; same for tail
__global__ void k_hw(const float* __restrict__ xbc,
                     const float* __restrict__ Who, const float* __restrict__ Wto,
                     const float* __restrict__ bho, const float* __restrict__ bto,
                     float* __restrict__ hW, float* __restrict__ hT) {
    int t = blockIdx.x * blockDim.x + threadIdx.x;
    if (t >= 2*BB*NN1*3) return;
    int which = t / (BB*NN1*3);
    int rem = t % (BB*NN1*3);
    int bi = rem / 3, c = rem % 3;
    const float* r0 = xbc + (size_t)bi*DD;
    const float* r1 = r0 + XSZ;
    const float* r2 = r1 + XSZ;
    const float* W  = which ? Wto : Who;
    float acc = 0.f;
    for (int k = 0; k < DD; k++) acc += (r0[k] + r1[k] + r2[k]) * W[k*3 + c];
    acc = acc * (1.f/3.f) + (which ? bto[c] : bho[c]);
    (which ? hT : hW)[bi*3 + c] = acc;
}

__global__ void k_logits(const int* __restrict__ cands,
                         const float* __restrict__ hW, const float* __restrict__ hT,
                         const float* __restrict__ b_out,
                         float* __restrict__ out) {
    int t = blockIdx.x * blockDim.x + threadIdx.x;
    const int TOT = BB*NN1*(NN1-1)*3;
    if (t >= TOT) return;
    int c = t % 3;
    int j = (t / 3) & 255;
    int i = (t / (3*256)) % NN1;
    int b = t / (3*256*NN1);
    int m = cands[((long long)(b*NN1 + i))*NN1 + j + 1];
    float v = b_out[c];
    if (m) v += hW[(b*NN1 + i)*3 + c] + hT[(b*NN1 + j + 1)*3 + c];
    out[t] = v;
}

// ---------------------------------------------------------------------------
// Launch
// ---------------------------------------------------------------------------
extern "C" void kernel_launch(void* const* d_in, const int* in_sizes, int n_in,
                              void* d_out, int out_size) {
    const float* emb     = (const float*)d_in[0];
    const int*   entIdx  = (const int*)  d_in[1];
    const int*   entLab  = (const int*)  d_in[2];
    const int*   edgeIdx = (const int*)  d_in[3];
    const int*   edgeAttr= (const int*)  d_in[4];
    const int*   cands   = (const int*)  d_in[5];
    const float* W_red   = (const float*)d_in[6];
    const float* b_red   = (const float*)d_in[7];
    const float* tbl     = (const float*)d_in[8];
    const float* W_gcn   = (const float*)d_in[9];
    const float* b_gcn   = (const float*)d_in[10];
    const float* W_head  = (const float*)d_in[11];
    const float* b_head  = (const float*)d_in[12];
    const float* W_tail  = (const float*)d_in[13];
    const float* b_tail  = (const float*)d_in[14];
    const float* W_out   = (const float*)d_in[15];
    const float* b_out   = (const float*)d_in[16];
    float* out = (float*)d_out;

    static float *px0=nullptr, *phc, *pxbc, *pdeg,
                 *pWho, *pWto, *pbho, *pbto, *phW, *phT;
    static __half *pWt, *pWg;
    static bool attr_set = false;
    if (!px0) {
        cudaGetSymbolAddress((void**)&px0,  g_x0);
        cudaGetSymbolAddress((void**)&phc,  g_hc);
        cudaGetSymbolAddress((void**)&pxbc, g_xbc);
        cudaGetSymbolAddress((void**)&pdeg, g_deg);
        cudaGetSymbolAddress((void**)&pWt,  g_Wt);
        cudaGetSymbolAddress((void**)&pWg,  g_Wg);
        cudaGetSymbolAddress((void**)&pWho, g_Who);
        cudaGetSymbolAddress((void**)&pWto, g_Wto);
        cudaGetSymbolAddress((void**)&pbho, g_bho);
        cudaGetSymbolAddress((void**)&pbto, g_bto);
        cudaGetSymbolAddress((void**)&phW,  g_hW);
        cudaGetSymbolAddress((void**)&phT,  g_hT);
    }
    if (!attr_set) {
        cudaFuncSetAttribute(k_mma_red, cudaFuncAttributeMaxDynamicSharedMemorySize, RED_SMEM);
        cudaFuncSetAttribute(k_mma_xw,  cudaFuncAttributeMaxDynamicSharedMemorySize, XW_SMEM);
        attr_set = true;
    }

    auto blocks = [](int n) { return (n + 255) / 256; };

    // init scratch
    k_fill<<<blocks(XSZ), 256>>>(px0, XSZ, 0.f);
    k_fill<<<blocks(DEGSZ), 256>>>(pdeg, DEGSZ, 1.f);

    // labels + graph structure (CSR) + weight transposes (fp16)
    k_labels<<<blocks(BB*NN1*LDD), 256>>>(px0, entLab, tbl);
    k_deg    <<<blocks(BB*EE), 256>>>(pdeg, edgeIdx, edgeAttr);
    k_off    <<<1, 64>>>(pdeg);
    k_scatter<<<blocks(BB*EE), 256>>>(pdeg, edgeIdx, edgeAttr);
    {
        dim3 bl(32, 32);
        k_th<<<dim3(ETRD/32, HH/32, 1), bl>>>(W_red, pWt, ETRD, HH);
        k_th<<<dim3((DD+31)/32, (DD+31)/32, NCLS*NLAY), bl>>>(W_gcn, pWg, DD, DD);
    }

    // big GEMM on tensor cores (fp16 mma) + fused relu/segmax scatter
    {
        dim3 g(HH/128, (BB*SS)/128);   // (4, 256)
        k_mma_red<<<g, 512, RED_SMEM>>>(emb, pWt, b_red, entIdx, px0);
    }

    // GCN: 2 layers, all 3 classes per launch
    {
        dim3 gx((DD + 127)/128, (BB*NN1 + 127)/128, NCLS);   // (5, 33, 3)
        dim3 gs(NN1, BB, NCLS);
        // layer 0: input x0 (shared across classes)
        k_mma_xw<<<gx, 512, XW_SMEM>>>(px0, pWg, phc, BB*NN1, 0LL, 0);
        k_spmm  <<<gs, 256>>>(phc, pxbc, pdeg, b_gcn, 0);
        // layer 1: input xb_c per class
        k_mma_xw<<<gx, 512, XW_SMEM>>>(pxbc, pWg, phc, BB*NN1, (long long)XSZ, 1);
        k_spmm  <<<gs, 256>>>(phc, pxbc, pdeg, b_gcn, 1);
    }

    // collapsed head/tail + logits (k_hw sums the 3 class outputs)
    k_ho<<<blocks(2*DD*3 + 6), 256>>>(W_head, W_tail, W_out, b_head, b_tail,
                                      pWho, pWto, pbho, pbto);
    k_hw<<<blocks(2*BB*NN1*3), 256>>>(pxbc, pWho, pWto, pbho, pbto, phW, phT);
    k_logits<<<blocks(BB*NN1*(NN1-1)*3), 256>>>(cands, phW, phT, b_out, out);
}

// round 8
// speedup vs baseline: 3.0139x; 1.2258x over previous
#include <cuda_runtime.h>
#include <cuda_fp16.h>
#include <cstdint>

// ---------------------------------------------------------------------------
// Problem constants
// ---------------------------------------------------------------------------
#define BB    16
#define SS    2048
#define NN1   257
#define EE    4096
#define HH    512
#define LDD   16
#define ETRD  768
#define DD    528
#define NCLS  3
#define NLAY  2

#define XSZ   (BB*NN1*DD)
#define DEGSZ (NCLS*BB*NN1)
#define CBSZ  (NCLS*BB)

// ---------------------------------------------------------------------------
// Device scratch
// ---------------------------------------------------------------------------
__device__ float  g_x0 [XSZ];
__device__ float  g_hc [NCLS*XSZ];
__device__ float  g_xbc[NCLS*XSZ];
__device__ float  g_deg[DEGSZ];
__device__ int    g_off[CBSZ*(NN1+1)];
__device__ int    g_cur[CBSZ*NN1];
__device__ int    g_esrc[CBSZ*EE];
__device__ float  g_ecoef[CBSZ*EE];
__device__ __half g_Wt [HH*ETRD];          // W_red^T  (n-major) fp16
__device__ __half g_Wg [NCLS*NLAY*DD*DD];  // W_gcn^T per (c,l), n-major fp16
__device__ float  g_Who[DD*3];
__device__ float  g_Wto[DD*3];
__device__ float  g_bho[3];
__device__ float  g_bto[3];
__device__ float  g_hW [BB*NN1*3];
__device__ float  g_hT [BB*NN1*3];

// ---------------------------------------------------------------------------
// mma + ldmatrix helpers (generic PTX, sm_75+/80+, OK for compute_103)
// ---------------------------------------------------------------------------
__device__ __forceinline__ void mma_f16(float* c, const uint32_t* a, const uint32_t* b) {
    asm volatile(
        "mma.sync.aligned.m16n8k16.row.col.f32.f16.f16.f32 "
        "{%0,%1,%2,%3}, {%4,%5,%6,%7}, {%8,%9}, {%0,%1,%2,%3};"
        : "+f"(c[0]), "+f"(c[1]), "+f"(c[2]), "+f"(c[3])
        : "r"(a[0]), "r"(a[1]), "r"(a[2]), "r"(a[3]), "r"(b[0]), "r"(b[1]));
}

__device__ __forceinline__ void ldsm4(uint32_t* r, uint32_t saddr) {
    asm volatile("ldmatrix.sync.aligned.m8n8.x4.shared.b16 {%0,%1,%2,%3}, [%4];"
                 : "=r"(r[0]), "=r"(r[1]), "=r"(r[2]), "=r"(r[3]) : "r"(saddr));
}

__device__ __forceinline__ uint32_t s2u(const void* p) {
    return (uint32_t)__cvta_generic_to_shared(p);
}

__device__ __forceinline__ uint32_t pack_h2(float x, float y) {
    __half2 h = __floats2half2_rn(x, y);
    return *(uint32_t*)&h;
}

// ---------------------------------------------------------------------------
// Small helper kernels
// ---------------------------------------------------------------------------
__global__ void k_fill(float* __restrict__ p, int n, float v) {
    int i = blockIdx.x * blockDim.x + threadIdx.x;
    if (i < n) p[i] = v;
}

__global__ void k_labels(float* __restrict__ x0,
                         const int* __restrict__ entLab,
                         const float* __restrict__ tbl) {
    int t = blockIdx.x * blockDim.x + threadIdx.x;
    if (t >= BB*NN1*LDD) return;
    int d = t & 15;
    int i = (t >> 4) % NN1;
    int b = t / (NN1*LDD);
    float v;
    if (i == 0) v = tbl[d];
    else {
        int lbl = entLab[b*(NN1-1) + i - 1];
        v = lbl ? tbl[lbl*LDD + d] : 0.f;
    }
    x0[((long long)(b*NN1 + i))*DD + d] = v;
}

__global__ void k_deg(float* __restrict__ deg,
                      const int* __restrict__ ei,
                      const int* __restrict__ ea) {
    int t = blockIdx.x * blockDim.x + threadIdx.x;
    if (t >= BB*EE) return;
    int b = t >> 12, e = t & (EE-1);
    int dst = ei[b*2*EE + EE + e];
    int a   = ea[b*EE + e];
    atomicAdd(&deg[(a*BB + b)*NN1 + dst], 1.f);
}

__global__ void k_off(const float* __restrict__ deg) {
    int t = blockIdx.x * blockDim.x + threadIdx.x;
    if (t >= CBSZ) return;
    const float* dg = deg + t*NN1;
    int* off = g_off + t*(NN1+1);
    int* cur = g_cur + t*NN1;
    int acc = 0;
    off[0] = 0;
    for (int i = 0; i < NN1; i++) {
        cur[i] = acc;
        acc += (int)dg[i] - 1;
        off[i+1] = acc;
    }
}

__global__ void k_scatter(const float* __restrict__ deg,
                          const int* __restrict__ ei,
                          const int* __restrict__ ea) {
    int t = blockIdx.x * blockDim.x + threadIdx.x;
    if (t >= BB*EE) return;
    int b = t >> 12, e = t & (EE-1);
    int src = ei[b*2*EE + e];
    int dst = ei[b*2*EE + EE + e];
    int a   = ea[b*EE + e];
    int cb  = a*BB + b;
    const float* dg = deg + cb*NN1;
    float coef = rsqrtf(dg[src]) * rsqrtf(dg[dst]);
    int pos = atomicAdd(&g_cur[cb*NN1 + dst], 1);
    g_esrc [cb*EE + pos] = src;
    g_ecoef[cb*EE + pos] = coef;
}

// transpose + fp16 convert: W [K][N] f32 -> Wt [N][K] fp16 (z-batched)
__global__ void k_th(const float* __restrict__ W, __half* __restrict__ Wt,
                     int K, int N) {
    const float* Wz  = W  + (size_t)blockIdx.z*K*N;
    __half*      Wtz = Wt + (size_t)blockIdx.z*K*N;
    __shared__ float t[32][33];
    int k = blockIdx.x*32 + threadIdx.y;
    int n = blockIdx.y*32 + threadIdx.x;
    if (k < K && n < N) t[threadIdx.y][threadIdx.x] = Wz[(size_t)k*N + n];
    __syncthreads();
    int no = blockIdx.y*32 + threadIdx.y;
    int ko = blockIdx.x*32 + threadIdx.x;
    if (no < N && ko < K) Wtz[(size_t)no*K + ko] = __float2half_rn(t[threadIdx.x][threadIdx.y]);
}

// ---------------------------------------------------------------------------
// Big fp16 GEMM with LDSM frag loads: red = emb @ W_red (+bias/relu/segmax).
// M=32768, N=512, K=768. 512 thr, 16 warps 32x32, K chunks of 64, dbl-buffer.
// Layout: As[m=128][72] halfs, Bs[n=128][72] halfs (stride 144B, LDSM
// conflict-free: i*36 words %32 all distinct).
// ---------------------------------------------------------------------------
#define KC    64
#define RA_LD 72
#define R_SZH (128*RA_LD)                  // halfs per buffer
#define RED_SMEM (4*R_SZH*2)               // 2 bufs x (A+B), bytes = 73728

__global__ void __launch_bounds__(512, 1) k_mma_red(
    const float*  __restrict__ A,      // emb (32768 x 768) f32
    const __half* __restrict__ Bt,     // W_red^T (512 x 768) fp16 n-major
    const float*  __restrict__ bias,
    const int*    __restrict__ entIdx,
    float*        __restrict__ x0)
{
    extern __shared__ __align__(16) __half smh[];
    __half* sAb[2] = { smh,            smh + R_SZH };
    __half* sBb[2] = { smh + 2*R_SZH,  smh + 3*R_SZH };

    const int tid  = threadIdx.x;
    const int lane = tid & 31;
    const int wid  = tid >> 5;
    const int gr   = lane >> 2;
    const int kq   = lane & 3;
    const int wm   = wid & 3;
    const int wn   = wid >> 2;
    const int row0 = blockIdx.y * 128;
    const int col0 = blockIdx.x * 128;

    const int sr = tid >> 2;      // staging row 0..127
    const int sg = tid & 3;

    // LDSM lane addressing (byte offsets into a buffer)
    const int arow_l = ((lane >> 3) & 1)*8 + (lane & 7);
    const int acol_l = (lane >> 4)*8;
    const int brow_l = (lane >> 4)*8 + (lane & 7);
    const int bcol_l = ((lane >> 3) & 1)*8;
    uint32_t aoff[2], boff[2];
    #pragma unroll
    for (int mi = 0; mi < 2; mi++)
        aoff[mi] = ((wm*32 + mi*16 + arow_l)*RA_LD + acol_l)*2;
    #pragma unroll
    for (int pr = 0; pr < 2; pr++)
        boff[pr] = ((wn*32 + pr*16 + brow_l)*RA_LD + bcol_l)*2;
    uint32_t sAu[2] = { s2u(sAb[0]), s2u(sAb[1]) };
    uint32_t sBu[2] = { s2u(sBb[0]), s2u(sBb[1]) };

    float acc[2][4][4];
    #pragma unroll
    for (int i = 0; i < 2; i++)
        #pragma unroll
        for (int j = 0; j < 4; j++)
            #pragma unroll
            for (int u = 0; u < 4; u++) acc[i][j][u] = 0.f;

    float4 ra[4];
    uint4  rb[2];

    auto ldchunk = [&](int k0) {
        #pragma unroll
        for (int p = 0; p < 4; p++)
            ra[p] = *(const float4*)(A + (size_t)(row0 + sr)*ETRD + k0 + (sg*4 + p)*4);
        #pragma unroll
        for (int p = 0; p < 2; p++)
            rb[p] = *(const uint4*)(Bt + (size_t)(col0 + sr)*ETRD + k0 + sg*16 + p*8);
    };
    auto stchunk = [&](int buf) {
        #pragma unroll
        for (int p = 0; p < 4; p++) {
            uint2 u;
            u.x = pack_h2(ra[p].x, ra[p].y);
            u.y = pack_h2(ra[p].z, ra[p].w);
            *(uint2*)(sAb[buf] + sr*RA_LD + (sg*4 + p)*4) = u;
        }
        #pragma unroll
        for (int p = 0; p < 2; p++)
            *(uint4*)(sBb[buf] + sr*RA_LD + sg*16 + p*8) = rb[p];
    };
    auto compute = [&](int buf) {
        #pragma unroll
        for (int ks = 0; ks < KC/16; ks++) {
            uint32_t af[2][4], bf[2][4];
            ldsm4(af[0], sAu[buf] + aoff[0] + ks*32);
            ldsm4(af[1], sAu[buf] + aoff[1] + ks*32);
            ldsm4(bf[0], sBu[buf] + boff[0] + ks*32);
            ldsm4(bf[1], sBu[buf] + boff[1] + ks*32);
            #pragma unroll
            for (int mi = 0; mi < 2; mi++) {
                mma_f16(acc[mi][0], af[mi], &bf[0][0]);
                mma_f16(acc[mi][1], af[mi], &bf[0][2]);
                mma_f16(acc[mi][2], af[mi], &bf[1][0]);
                mma_f16(acc[mi][3], af[mi], &bf[1][2]);
            }
        }
    };

    ldchunk(0);
    stchunk(0);
    __syncthreads();
    #pragma unroll 1
    for (int ch = 0; ch < ETRD/KC; ch++) {     // 12 chunks
        if (ch + 1 < ETRD/KC) ldchunk((ch + 1)*KC);
        compute(ch & 1);
        if (ch + 1 < ETRD/KC) {
            stchunk((ch + 1) & 1);
            __syncthreads();
        }
    }

    // Epilogue: fused bias + relu + segment-max scatter
    int    nodev[2][2];
    float* basep[2][2];
    #pragma unroll
    for (int mi = 0; mi < 2; mi++)
        #pragma unroll
        for (int h = 0; h < 2; h++) {
            int r  = row0 + wm*32 + mi*16 + gr + h*8;
            int nd = entIdx[r];
            nodev[mi][h] = nd;
            int b = r >> 11;
            basep[mi][h] = x0 + ((size_t)(b*NN1 + nd))*DD + LDD;
        }
    #pragma unroll
    for (int ni = 0; ni < 4; ni++) {
        int c = col0 + wn*32 + ni*8 + kq*2;
        float b0 = __ldg(bias + c), b1 = __ldg(bias + c + 1);
        #pragma unroll
        for (int mi = 0; mi < 2; mi++) {
            #pragma unroll
            for (int h = 0; h < 2; h++) {
                if (nodev[mi][h] == 0) continue;
                float v0 = fmaxf(acc[mi][ni][2*h    ] + b0, 0.f);
                float v1 = fmaxf(acc[mi][ni][2*h + 1] + b1, 0.f);
                atomicMax((int*)(basep[mi][h] + c),     __float_as_int(v0));
                atomicMax((int*)(basep[mi][h] + c + 1), __float_as_int(v1));
            }
        }
    }
}

// ---------------------------------------------------------------------------
// fp16 GEMM for xW with LDSM, 3 classes via grid.z: h_z = x_z @ W_z.
// M=4112, N=K=528. K chunks of 48 (11 exact). Stride 56 halfs (112B),
// LDSM conflict-free (i*28 words %32 distinct).
// ---------------------------------------------------------------------------
#define XKC   48
#define XA_LD 56
#define X_SZH (128*XA_LD)
#define XW_SMEM (4*X_SZH*2)

__global__ void __launch_bounds__(512, 1) k_mma_xw(
    const float*  __restrict__ Abase,  // x (M x 528) f32; + z*strideA
    const __half* __restrict__ Wg,     // W^T fp16 n-major; + (z*NLAY+l)*DD*DD
    float*        __restrict__ Cbase,  // h ; + z*XSZ
    int M, long long strideA, int layer)
{
    const int z = blockIdx.z;
    const float*  A  = Abase + (size_t)z*strideA;
    const __half* Bt = Wg + ((size_t)z*NLAY + layer)*DD*DD;
    float* C = Cbase + (size_t)z*XSZ;

    extern __shared__ __align__(16) __half smh[];
    __half* sAb[2] = { smh,            smh + X_SZH };
    __half* sBb[2] = { smh + 2*X_SZH,  smh + 3*X_SZH };

    const int tid  = threadIdx.x;
    const int lane = tid & 31;
    const int wid  = tid >> 5;
    const int gr   = lane >> 2;
    const int kq   = lane & 3;
    const int wm   = wid & 3;
    const int wn   = wid >> 2;
    const int row0 = blockIdx.y * 128;
    const int col0 = blockIdx.x * 128;

    const int sr = tid >> 2;
    const int sg = tid & 3;

    const int arow_l = ((lane >> 3) & 1)*8 + (lane & 7);
    const int acol_l = (lane >> 4)*8;
    const int brow_l = (lane >> 4)*8 + (lane & 7);
    const int bcol_l = ((lane >> 3) & 1)*8;
    uint32_t aoff[2], boff[2];
    #pragma unroll
    for (int mi = 0; mi < 2; mi++)
        aoff[mi] = ((wm*32 + mi*16 + arow_l)*XA_LD + acol_l)*2;
    #pragma unroll
    for (int pr = 0; pr < 2; pr++)
        boff[pr] = ((wn*32 + pr*16 + brow_l)*XA_LD + bcol_l)*2;
    uint32_t sAu[2] = { s2u(sAb[0]), s2u(sAb[1]) };
    uint32_t sBu[2] = { s2u(sBb[0]), s2u(sBb[1]) };

    float acc[2][4][4];
    #pragma unroll
    for (int i = 0; i < 2; i++)
        #pragma unroll
        for (int j = 0; j < 4; j++)
            #pragma unroll
            for (int u = 0; u < 4; u++) acc[i][j][u] = 0.f;

    // staging: A 128 rows x 12 float4 -> 3/thread; B 128 rows x 6 uint4 ->
    // 768 total: tid and tid+512 (tid<256)
    float4 ra[3];
    uint4  rb0, rb1;
    const int b_i0r = tid / 6,        b_i0q = tid % 6;
    const int b_i1r = (tid + 512)/6,  b_i1q = (tid + 512) % 6;
    const bool hasb1 = (tid < 256);

    auto ldchunk = [&](int k0) {
        int gm = row0 + sr;
        #pragma unroll
        for (int p = 0; p < 3; p++)
            ra[p] = (gm < M) ? *(const float4*)(A + (size_t)gm*DD + k0 + (sg*3 + p)*4)
                             : make_float4(0.f, 0.f, 0.f, 0.f);
        int gn0 = col0 + b_i0r;
        rb0 = (gn0 < DD) ? *(const uint4*)(Bt + (size_t)gn0*DD + k0 + b_i0q*8)
                         : make_uint4(0u, 0u, 0u, 0u);
        if (hasb1) {
            int gn1 = col0 + b_i1r;
            rb1 = (gn1 < DD) ? *(const uint4*)(Bt + (size_t)gn1*DD + k0 + b_i1q*8)
                             : make_uint4(0u, 0u, 0u, 0u);
        }
    };
    auto stchunk = [&](int buf) {
        #pragma unroll
        for (int p = 0; p < 3; p++) {
            uint2 u;
            u.x = pack_h2(ra[p].x, ra[p].y);
            u.y = pack_h2(ra[p].z, ra[p].w);
            *(uint2*)(sAb[buf] + sr*XA_LD + (sg*3 + p)*4) = u;
        }
        *(uint4*)(sBb[buf] + b_i0r*XA_LD + b_i0q*8) = rb0;
        if (hasb1) *(uint4*)(sBb[buf] + b_i1r*XA_LD + b_i1q*8) = rb1;
    };
    auto compute = [&](int buf) {
        #pragma unroll
        for (int ks = 0; ks < XKC/16; ks++) {
            uint32_t af[2][4], bf[2][4];
            ldsm4(af[0], sAu[buf] + aoff[0] + ks*32);
            ldsm4(af[1], sAu[buf] + aoff[1] + ks*32);
            ldsm4(bf[0], sBu[buf] + boff[0] + ks*32);
            ldsm4(bf[1], sBu[buf] + boff[1] + ks*32);
            #pragma unroll
            for (int mi = 0; mi < 2; mi++) {
                mma_f16(acc[mi][0], af[mi], &bf[0][0]);
                mma_f16(acc[mi][1], af[mi], &bf[0][2]);
                mma_f16(acc[mi][2], af[mi], &bf[1][0]);
                mma_f16(acc[mi][3], af[mi], &bf[1][2]);
            }
        }
    };

    ldchunk(0);
    stchunk(0);
    __syncthreads();
    #pragma unroll 1
    for (int ch = 0; ch < DD/XKC; ch++) {      // 11 exact chunks
        if (ch + 1 < DD/XKC) ldchunk((ch + 1)*XKC);
        compute(ch & 1);
        if (ch + 1 < DD/XKC) {
            stchunk((ch + 1) & 1);
            __syncthreads();
        }
    }

    #pragma unroll
    for (int mi = 0; mi < 2; mi++) {
        #pragma unroll
        for (int h = 0; h < 2; h++) {
            int gm = row0 + wm*32 + mi*16 + gr + h*8;
            if (gm >= M) continue;
            #pragma unroll
            for (int ni = 0; ni < 4; ni++) {
                int gn = col0 + wn*32 + ni*8 + kq*2;
                if (gn + 1 < DD) {
                    C[(size_t)gm*DD + gn    ] = acc[mi][ni][2*h];
                    C[(size_t)gm*DD + gn + 1] = acc[mi][ni][2*h + 1];
                }
            }
        }
    }
}

// ---------------------------------------------------------------------------
// Sparse GCN aggregation, 3 classes via grid.z
// ---------------------------------------------------------------------------
__global__ void __launch_bounds__(256) k_spmm(
    const float* __restrict__ hbase,
    float* __restrict__ xbbase,
    const float* __restrict__ deg,
    const float* __restrict__ bgcn,
    int layer)
{
    int dst = blockIdx.x;
    int b   = blockIdx.y;
    int cls = blockIdx.z;
    int cb  = cls*BB + b;
    int tid = threadIdx.x;

    const float* bias = bgcn + (size_t)(cls*NLAY + layer)*DD;
    const float* h    = hbase + (size_t)cls*XSZ;
    float*       xb   = xbbase + (size_t)cls*XSZ;

    const int* off = g_off + cb*(NN1+1);
    int e0 = off[dst], e1 = off[dst+1];
    const int*   es = g_esrc  + cb*EE;
    const float* ec = g_ecoef + cb*EE;
    const float* hb = h + (size_t)b*NN1*DD;

    int c0 = tid, c1 = tid + 256, c2 = tid + 512;
    float a0 = 0.f, a1 = 0.f, a2 = 0.f;

    for (int e = e0; e < e1; e++) {
        int   src = es[e];
        float w   = ec[e];
        const float* hr = hb + (size_t)src*DD;
        a0 += w * hr[c0];
        if (c1 < DD) a1 += w * hr[c1];
        if (c2 < DD) a2 += w * hr[c2];
    }

    float dinv = 1.f / deg[cb*NN1 + dst];
    const float* hd = hb + (size_t)dst*DD;
    float* xo = xb + ((size_t)b*NN1 + dst)*DD;

    xo[c0] = a0 + hd[c0]*dinv + bias[c0];
    if (c1 < DD) xo[c1] = a1 + hd[c1]*dinv + bias[c1];
    if (c2 < DD) xo[c2] = a2 + hd[c2]*dinv + bias[c2];
}

// ---------------------------------------------------------------------------
// Collapsed head/tail + logits
// ---------------------------------------------------------------------------
__global__ void k_ho(const float* __restrict__ W_head, const float* __restrict__ W_tail,
                     const float* __restrict__ W_out,
                     const float* __restrict__ b_head, const float* __restrict__ b_tail,
                     float* __restrict__ Who, float* __restrict__ Wto,
                     float* __restrict__ bho, float* __restrict__ bto) {
    int t = blockIdx.x * blockDim.x + threadIdx.x;
    if (t < 2*DD*3) {
        int which = t / (DD*3), rc = t % (DD*3), r = rc / 3, c = rc % 3;
        const float* W = which ? W_tail : W_head;
        float acc = 0.f;
        for (int j = 0; j < DD; j++) acc += W[r*DD + j] * W_out[j*3 + c];
        (which ? Wto : Who)[r*3 + c] = acc;
    } else if (t < 2*DD*3 + 6) {
        int u = t - 2*DD*3, which = u / 3, c = u % 3;
        const float* bb = which ? b_tail : b_head;
        float acc = 0.f;
        for (int j = 0; j < DD; j++) acc += bb[j] * W_out[j*3 + c];
        (which ? bto : bho)[c] = acc;
    }
}

__global__ void k_hw(const float* __restrict__ xbc,
                     const float* __restrict__ Who, const float* __restrict__ Wto,
                     const float* __restrict__ bho, const float* __restrict__ bto,
                     float* __restrict__ hW, float* __restrict__ hT) {
    int t = blockIdx.x * blockDim.x + threadIdx.x;
    if (t >= 2*BB*NN1*3) return;
    int which = t / (BB*NN1*3);
    int rem = t % (BB*NN1*3);
    int bi = rem / 3, c = rem % 3;
    const float* r0 = xbc + (size_t)bi*DD;
    const float* r1 = r0 + XSZ;
    const float* r2 = r1 + XSZ;
    const float* W  = which ? Wto : Who;
    float acc = 0.f;
    for (int k = 0; k < DD; k++) acc += (r0[k] + r1[k] + r2[k]) * W[k*3 + c];
    acc = acc * (1.f/3.f) + (which ? bto[c] : bho[c]);
    (which ? hT : hW)[bi*3 + c] = acc;
}

__global__ void k_logits(const int* __restrict__ cands,
                         const float* __restrict__ hW, const float* __restrict__ hT,
                         const float* __restrict__ b_out,
                         float* __restrict__ out) {
    int t = blockIdx.x * blockDim.x + threadIdx.x;
    const int TOT = BB*NN1*(NN1-1)*3;
    if (t >= TOT) return;
    int c = t % 3;
    int j = (t / 3) & 255;
    int i = (t / (3*256)) % NN1;
    int b = t / (3*256*NN1);
    int m = cands[((long long)(b*NN1 + i))*NN1 + j + 1];
    float v = b_out[c];
    if (m) v += hW[(b*NN1 + i)*3 + c] + hT[(b*NN1 + j + 1)*3 + c];
    out[t] = v;
}

// ---------------------------------------------------------------------------
// Launch
// ---------------------------------------------------------------------------
extern "C" void kernel_launch(void* const* d_in, const int* in_sizes, int n_in,
                              void* d_out, int out_size) {
    const float* emb     = (const float*)d_in[0];
    const int*   entIdx  = (const int*)  d_in[1];
    const int*   entLab  = (const int*)  d_in[2];
    const int*   edgeIdx = (const int*)  d_in[3];
    const int*   edgeAttr= (const int*)  d_in[4];
    const int*   cands   = (const int*)  d_in[5];
    const float* W_red   = (const float*)d_in[6];
    const float* b_red   = (const float*)d_in[7];
    const float* tbl     = (const float*)d_in[8];
    const float* W_gcn   = (const float*)d_in[9];
    const float* b_gcn   = (const float*)d_in[10];
    const float* W_head  = (const float*)d_in[11];
    const float* b_head  = (const float*)d_in[12];
    const float* W_tail  = (const float*)d_in[13];
    const float* b_tail  = (const float*)d_in[14];
    const float* W_out   = (const float*)d_in[15];
    const float* b_out   = (const float*)d_in[16];
    float* out = (float*)d_out;

    static float *px0=nullptr, *phc, *pxbc, *pdeg,
                 *pWho, *pWto, *pbho, *pbto, *phW, *phT;
    static __half *pWt, *pWg;
    static bool attr_set = false;
    if (!px0) {
        cudaGetSymbolAddress((void**)&px0,  g_x0);
        cudaGetSymbolAddress((void**)&phc,  g_hc);
        cudaGetSymbolAddress((void**)&pxbc, g_xbc);
        cudaGetSymbolAddress((void**)&pdeg, g_deg);
        cudaGetSymbolAddress((void**)&pWt,  g_Wt);
        cudaGetSymbolAddress((void**)&pWg,  g_Wg);
        cudaGetSymbolAddress((void**)&pWho, g_Who);
        cudaGetSymbolAddress((void**)&pWto, g_Wto);
        cudaGetSymbolAddress((void**)&pbho, g_bho);
        cudaGetSymbolAddress((void**)&pbto, g_bto);
        cudaGetSymbolAddress((void**)&phW,  g_hW);
        cudaGetSymbolAddress((void**)&phT,  g_hT);
    }
    if (!attr_set) {
        cudaFuncSetAttribute(k_mma_red, cudaFuncAttributeMaxDynamicSharedMemorySize, RED_SMEM);
        cudaFuncSetAttribute(k_mma_xw,  cudaFuncAttributeMaxDynamicSharedMemorySize, XW_SMEM);
        attr_set = true;
    }

    auto blocks = [](int n) { return (n + 255) / 256; };

    // init scratch
    k_fill<<<blocks(XSZ), 256>>>(px0, XSZ, 0.f);
    k_fill<<<blocks(DEGSZ), 256>>>(pdeg, DEGSZ, 1.f);

    // labels + graph structure (CSR) + weight transposes (fp16)
    k_labels<<<blocks(BB*NN1*LDD), 256>>>(px0, entLab, tbl);
    k_deg    <<<blocks(BB*EE), 256>>>(pdeg, edgeIdx, edgeAttr);
    k_off    <<<1, 64>>>(pdeg);
    k_scatter<<<blocks(BB*EE), 256>>>(pdeg, edgeIdx, edgeAttr);
    {
        dim3 bl(32, 32);
        k_th<<<dim3(ETRD/32, HH/32, 1), bl>>>(W_red, pWt, ETRD, HH);
        k_th<<<dim3((DD+31)/32, (DD+31)/32, NCLS*NLAY), bl>>>(W_gcn, pWg, DD, DD);
    }

    // big GEMM on tensor cores (fp16 mma + LDSM) + fused relu/segmax scatter
    {
        dim3 g(HH/128, (BB*SS)/128);   // (4, 256)
        k_mma_red<<<g, 512, RED_SMEM>>>(emb, pWt, b_red, entIdx, px0);
    }

    // GCN: 2 layers, all 3 classes per launch
    {
        dim3 gx((DD + 127)/128, (BB*NN1 + 127)/128, NCLS);   // (5, 33, 3)
        dim3 gs(NN1, BB, NCLS);
        k_mma_xw<<<gx, 512, XW_SMEM>>>(px0, pWg, phc, BB*NN1, 0LL, 0);
        k_spmm  <<<gs, 256>>>(phc, pxbc, pdeg, b_gcn, 0);
        k_mma_xw<<<gx, 512, XW_SMEM>>>(pxbc, pWg, phc, BB*NN1, (long long)XSZ, 1);
        k_spmm  <<<gs, 256>>>(phc, pxbc, pdeg, b_gcn, 1);
    }

    // collapsed head/tail + logits (k_hw sums the 3 class outputs)
    k_ho<<<blocks(2*DD*3 + 6), 256>>>(W_head, W_tail, W_out, b_head, b_tail,
                                      pWho, pWto, pbho, pbto);
    k_hw<<<blocks(2*BB*NN1*3), 256>>>(pxbc, pWho, pWto, pbho, pbto, phW, phT);
    k_logits<<<blocks(BB*NN1*(NN1-1)*3), 256>>>(cands, phW, phT, b_out, out);
}

// round 9
// speedup vs baseline: 3.1895x; 1.0583x over previous
#include <cuda_runtime.h>
#include <cuda_fp16.h>
#include <cstdint>

// ---------------------------------------------------------------------------
// Problem constants
// ---------------------------------------------------------------------------
#define BB    16
#define SS    2048
#define NN1   257
#define EE    4096
#define HH    512
#define LDD   16
#define ETRD  768
#define DD    528
#define NCLS  3
#define NLAY  2

#define XSZ   (BB*NN1*DD)
#define DEGSZ (NCLS*BB*NN1)
#define CBSZ  (NCLS*BB)

// ---------------------------------------------------------------------------
// Device scratch
// ---------------------------------------------------------------------------
__device__ float  g_x0 [XSZ];
__device__ float  g_hc [NCLS*XSZ];
__device__ float  g_xbc[NCLS*XSZ];
__device__ float  g_deg[DEGSZ];
__device__ int    g_off[CBSZ*(NN1+1)];
__device__ int    g_cur[CBSZ*NN1];
__device__ int    g_esrc[CBSZ*EE];
__device__ float  g_ecoef[CBSZ*EE];
__device__ __half g_embh[BB*SS*ETRD];      // emb pre-converted to fp16
__device__ __half g_Wt [HH*ETRD];          // W_red^T  (n-major) fp16
__device__ __half g_Wg [NCLS*NLAY*DD*DD];  // W_gcn^T per (c,l), n-major fp16
__device__ float  g_Who[DD*3];
__device__ float  g_Wto[DD*3];
__device__ float  g_bho[3];
__device__ float  g_bto[3];
__device__ float  g_hW [BB*NN1*3];
__device__ float  g_hT [BB*NN1*3];

// ---------------------------------------------------------------------------
// mma / ldmatrix / cp.async helpers (generic PTX, OK for compute_103)
// ---------------------------------------------------------------------------
__device__ __forceinline__ void mma_f16(float* c, const uint32_t* a, const uint32_t* b) {
    asm volatile(
        "mma.sync.aligned.m16n8k16.row.col.f32.f16.f16.f32 "
        "{%0,%1,%2,%3}, {%4,%5,%6,%7}, {%8,%9}, {%0,%1,%2,%3};"
        : "+f"(c[0]), "+f"(c[1]), "+f"(c[2]), "+f"(c[3])
        : "r"(a[0]), "r"(a[1]), "r"(a[2]), "r"(a[3]), "r"(b[0]), "r"(b[1]));
}

__device__ __forceinline__ void ldsm4(uint32_t* r, uint32_t saddr) {
    asm volatile("ldmatrix.sync.aligned.m8n8.x4.shared.b16 {%0,%1,%2,%3}, [%4];"
                 : "=r"(r[0]), "=r"(r[1]), "=r"(r[2]), "=r"(r[3]) : "r"(saddr));
}

__device__ __forceinline__ uint32_t s2u(const void* p) {
    return (uint32_t)__cvta_generic_to_shared(p);
}

__device__ __forceinline__ void cp16(uint32_t s, const void* g) {
    asm volatile("cp.async.cg.shared.global [%0], [%1], 16;" :: "r"(s), "l"(g));
}
#define CP_COMMIT() asm volatile("cp.async.commit_group;" ::: "memory")
#define CP_WAIT0()  asm volatile("cp.async.wait_group 0;"  ::: "memory")

__device__ __forceinline__ uint32_t pack_h2(float x, float y) {
    __half2 h = __floats2half2_rn(x, y);
    return *(uint32_t*)&h;
}

// ---------------------------------------------------------------------------
// Small helper kernels
// ---------------------------------------------------------------------------
__global__ void k_fill(float* __restrict__ p, int n, float v) {
    int i = blockIdx.x * blockDim.x + threadIdx.x;
    if (i < n) p[i] = v;
}

// fp32 -> fp16 bulk convert (vectorized: one float4 -> one uint2)
__global__ void k_eh(const float4* __restrict__ in, uint2* __restrict__ outp, int n4) {
    int i = blockIdx.x * blockDim.x + threadIdx.x;
    if (i < n4) {
        float4 v = in[i];
        uint2 u;
        u.x = pack_h2(v.x, v.y);
        u.y = pack_h2(v.z, v.w);
        outp[i] = u;
    }
}

__global__ void k_labels(float* __restrict__ x0,
                         const int* __restrict__ entLab,
                         const float* __restrict__ tbl) {
    int t = blockIdx.x * blockDim.x + threadIdx.x;
    if (t >= BB*NN1*LDD) return;
    int d = t & 15;
    int i = (t >> 4) % NN1;
    int b = t / (NN1*LDD);
    float v;
    if (i == 0) v = tbl[d];
    else {
        int lbl = entLab[b*(NN1-1) + i - 1];
        v = lbl ? tbl[lbl*LDD + d] : 0.f;
    }
    x0[((long long)(b*NN1 + i))*DD + d] = v;
}

__global__ void k_deg(float* __restrict__ deg,
                      const int* __restrict__ ei,
                      const int* __restrict__ ea) {
    int t = blockIdx.x * blockDim.x + threadIdx.x;
    if (t >= BB*EE) return;
    int b = t >> 12, e = t & (EE-1);
    int dst = ei[b*2*EE + EE + e];
    int a   = ea[b*EE + e];
    atomicAdd(&deg[(a*BB + b)*NN1 + dst], 1.f);
}

__global__ void k_off(const float* __restrict__ deg) {
    int t = blockIdx.x * blockDim.x + threadIdx.x;
    if (t >= CBSZ) return;
    const float* dg = deg + t*NN1;
    int* off = g_off + t*(NN1+1);
    int* cur = g_cur + t*NN1;
    int acc = 0;
    off[0] = 0;
    for (int i = 0; i < NN1; i++) {
        cur[i] = acc;
        acc += (int)dg[i] - 1;
        off[i+1] = acc;
    }
}

__global__ void k_scatter(const float* __restrict__ deg,
                          const int* __restrict__ ei,
                          const int* __restrict__ ea) {
    int t = blockIdx.x * blockDim.x + threadIdx.x;
    if (t >= BB*EE) return;
    int b = t >> 12, e = t & (EE-1);
    int src = ei[b*2*EE + e];
    int dst = ei[b*2*EE + EE + e];
    int a   = ea[b*EE + e];
    int cb  = a*BB + b;
    const float* dg = deg + cb*NN1;
    float coef = rsqrtf(dg[src]) * rsqrtf(dg[dst]);
    int pos = atomicAdd(&g_cur[cb*NN1 + dst], 1);
    g_esrc [cb*EE + pos] = src;
    g_ecoef[cb*EE + pos] = coef;
}

// transpose + fp16 convert: W [K][N] f32 -> Wt [N][K] fp16 (z-batched)
__global__ void k_th(const float* __restrict__ W, __half* __restrict__ Wt,
                     int K, int N) {
    const float* Wz  = W  + (size_t)blockIdx.z*K*N;
    __half*      Wtz = Wt + (size_t)blockIdx.z*K*N;
    __shared__ float t[32][33];
    int k = blockIdx.x*32 + threadIdx.y;
    int n = blockIdx.y*32 + threadIdx.x;
    if (k < K && n < N) t[threadIdx.y][threadIdx.x] = Wz[(size_t)k*N + n];
    __syncthreads();
    int no = blockIdx.y*32 + threadIdx.y;
    int ko = blockIdx.x*32 + threadIdx.x;
    if (no < N && ko < K) Wtz[(size_t)no*K + ko] = __float2half_rn(t[threadIdx.x][threadIdx.y]);
}

// ---------------------------------------------------------------------------
// Big fp16 GEMM, cp.async feeds + LDSM frags: red = emb@W_red (+bias/relu/
// segmax scatter). M=32768, N=512, K=768. 512 thr, 16 warps 32x32, KC=64.
// ---------------------------------------------------------------------------
#define KC    64
#define RA_LD 72
#define R_SZH (128*RA_LD)
#define RED_SMEM (4*R_SZH*2)               // 73728 B

__global__ void __launch_bounds__(512, 1) k_mma_red(
    const __half* __restrict__ A,      // emb fp16 (32768 x 768)
    const __half* __restrict__ Bt,     // W_red^T fp16 (512 x 768) n-major
    const float*  __restrict__ bias,
    const int*    __restrict__ entIdx,
    float*        __restrict__ x0)
{
    extern __shared__ __align__(16) __half smh[];
    __half* sAb[2] = { smh,            smh + R_SZH };
    __half* sBb[2] = { smh + 2*R_SZH,  smh + 3*R_SZH };

    const int tid  = threadIdx.x;
    const int lane = tid & 31;
    const int wid  = tid >> 5;
    const int gr   = lane >> 2;
    const int kq   = lane & 3;
    const int wm   = wid & 3;
    const int wn   = wid >> 2;
    const int row0 = blockIdx.y * 128;
    const int col0 = blockIdx.x * 128;

    const int sr = tid >> 2;      // staging row 0..127
    const int sg = tid & 3;       // 16 halfs each

    const int arow_l = ((lane >> 3) & 1)*8 + (lane & 7);
    const int acol_l = (lane >> 4)*8;
    const int brow_l = (lane >> 4)*8 + (lane & 7);
    const int bcol_l = ((lane >> 3) & 1)*8;
    uint32_t aoff[2], boff[2];
    #pragma unroll
    for (int mi = 0; mi < 2; mi++)
        aoff[mi] = ((wm*32 + mi*16 + arow_l)*RA_LD + acol_l)*2;
    #pragma unroll
    for (int pr = 0; pr < 2; pr++)
        boff[pr] = ((wn*32 + pr*16 + brow_l)*RA_LD + bcol_l)*2;
    uint32_t sAu[2] = { s2u(sAb[0]), s2u(sAb[1]) };
    uint32_t sBu[2] = { s2u(sBb[0]), s2u(sBb[1]) };

    float acc[2][4][4];
    #pragma unroll
    for (int i = 0; i < 2; i++)
        #pragma unroll
        for (int j = 0; j < 4; j++)
            #pragma unroll
            for (int u = 0; u < 4; u++) acc[i][j][u] = 0.f;

    const __half* agp = A  + (size_t)(row0 + sr)*ETRD + sg*16;
    const __half* bgp = Bt + (size_t)(col0 + sr)*ETRD + sg*16;
    const uint32_t sAoff = (sr*RA_LD + sg*16)*2;
    const uint32_t sBoff = sAoff;

    auto ldchunk = [&](int k0, int buf) {
        cp16(sAu[buf] + sAoff,      agp + k0);
        cp16(sAu[buf] + sAoff + 16, agp + k0 + 8);
        cp16(sBu[buf] + sBoff,      bgp + k0);
        cp16(sBu[buf] + sBoff + 16, bgp + k0 + 8);
        CP_COMMIT();
    };
    auto compute = [&](int buf) {
        #pragma unroll
        for (int ks = 0; ks < KC/16; ks++) {
            uint32_t af[2][4], bf[2][4];
            ldsm4(af[0], sAu[buf] + aoff[0] + ks*32);
            ldsm4(af[1], sAu[buf] + aoff[1] + ks*32);
            ldsm4(bf[0], sBu[buf] + boff[0] + ks*32);
            ldsm4(bf[1], sBu[buf] + boff[1] + ks*32);
            #pragma unroll
            for (int mi = 0; mi < 2; mi++) {
                mma_f16(acc[mi][0], af[mi], &bf[0][0]);
                mma_f16(acc[mi][1], af[mi], &bf[0][2]);
                mma_f16(acc[mi][2], af[mi], &bf[1][0]);
                mma_f16(acc[mi][3], af[mi], &bf[1][2]);
            }
        }
    };

    ldchunk(0, 0);
    CP_WAIT0();
    __syncthreads();
    #pragma unroll 1
    for (int ch = 0; ch < ETRD/KC; ch++) {     // 12 chunks
        if (ch + 1 < ETRD/KC) ldchunk((ch + 1)*KC, (ch + 1) & 1);
        compute(ch & 1);
        if (ch + 1 < ETRD/KC) {
            CP_WAIT0();
            __syncthreads();
        }
    }

    // Epilogue: fused bias + relu + segment-max scatter (predicated: values
    // <= 0 can never change the 0-initialized max target).
    int    nodev[2][2];
    float* basep[2][2];
    #pragma unroll
    for (int mi = 0; mi < 2; mi++)
        #pragma unroll
        for (int h = 0; h < 2; h++) {
            int r  = row0 + wm*32 + mi*16 + gr + h*8;
            int nd = entIdx[r];
            nodev[mi][h] = nd;
            int b = r >> 11;
            basep[mi][h] = x0 + ((size_t)(b*NN1 + nd))*DD + LDD;
        }
    #pragma unroll
    for (int ni = 0; ni < 4; ni++) {
        int c = col0 + wn*32 + ni*8 + kq*2;
        float b0 = __ldg(bias + c), b1 = __ldg(bias + c + 1);
        #pragma unroll
        for (int mi = 0; mi < 2; mi++) {
            #pragma unroll
            for (int h = 0; h < 2; h++) {
                if (nodev[mi][h] == 0) continue;
                float v0 = acc[mi][ni][2*h    ] + b0;
                float v1 = acc[mi][ni][2*h + 1] + b1;
                if (v0 > 0.f) atomicMax((int*)(basep[mi][h] + c),     __float_as_int(v0));
                if (v1 > 0.f) atomicMax((int*)(basep[mi][h] + c + 1), __float_as_int(v1));
            }
        }
    }
}

// ---------------------------------------------------------------------------
// fp16 GEMM for xW with LDSM, 3 classes via grid.z: h_z = x_z @ W_z.
// M=4112, N=K=528. K chunks of 48 (11 exact). Stride 56 halfs.
// ---------------------------------------------------------------------------
#define XKC   48
#define XA_LD 56
#define X_SZH (128*XA_LD)
#define XW_SMEM (4*X_SZH*2)

__global__ void __launch_bounds__(512, 1) k_mma_xw(
    const float*  __restrict__ Abase,
    const __half* __restrict__ Wg,
    float*        __restrict__ Cbase,
    int M, long long strideA, int layer)
{
    const int z = blockIdx.z;
    const float*  A  = Abase + (size_t)z*strideA;
    const __half* Bt = Wg + ((size_t)z*NLAY + layer)*DD*DD;
    float* C = Cbase + (size_t)z*XSZ;

    extern __shared__ __align__(16) __half smh[];
    __half* sAb[2] = { smh,            smh + X_SZH };
    __half* sBb[2] = { smh + 2*X_SZH,  smh + 3*X_SZH };

    const int tid  = threadIdx.x;
    const int lane = tid & 31;
    const int wid  = tid >> 5;
    const int gr   = lane >> 2;
    const int kq   = lane & 3;
    const int wm   = wid & 3;
    const int wn   = wid >> 2;
    const int row0 = blockIdx.y * 128;
    const int col0 = blockIdx.x * 128;

    const int sr = tid >> 2;
    const int sg = tid & 3;

    const int arow_l = ((lane >> 3) & 1)*8 + (lane & 7);
    const int acol_l = (lane >> 4)*8;
    const int brow_l = (lane >> 4)*8 + (lane & 7);
    const int bcol_l = ((lane >> 3) & 1)*8;
    uint32_t aoff[2], boff[2];
    #pragma unroll
    for (int mi = 0; mi < 2; mi++)
        aoff[mi] = ((wm*32 + mi*16 + arow_l)*XA_LD + acol_l)*2;
    #pragma unroll
    for (int pr = 0; pr < 2; pr++)
        boff[pr] = ((wn*32 + pr*16 + brow_l)*XA_LD + bcol_l)*2;
    uint32_t sAu[2] = { s2u(sAb[0]), s2u(sAb[1]) };
    uint32_t sBu[2] = { s2u(sBb[0]), s2u(sBb[1]) };

    float acc[2][4][4];
    #pragma unroll
    for (int i = 0; i < 2; i++)
        #pragma unroll
        for (int j = 0; j < 4; j++)
            #pragma unroll
            for (int u = 0; u < 4; u++) acc[i][j][u] = 0.f;

    float4 ra[3];
    uint4  rb0, rb1;
    const int b_i0r = tid / 6,        b_i0q = tid % 6;
    const int b_i1r = (tid + 512)/6,  b_i1q = (tid + 512) % 6;
    const bool hasb1 = (tid < 256);

    auto ldchunk = [&](int k0) {
        int gm = row0 + sr;
        #pragma unroll
        for (int p = 0; p < 3; p++)
            ra[p] = (gm < M) ? *(const float4*)(A + (size_t)gm*DD + k0 + (sg*3 + p)*4)
                             : make_float4(0.f, 0.f, 0.f, 0.f);
        int gn0 = col0 + b_i0r;
        rb0 = (gn0 < DD) ? *(const uint4*)(Bt + (size_t)gn0*DD + k0 + b_i0q*8)
                         : make_uint4(0u, 0u, 0u, 0u);
        if (hasb1) {
            int gn1 = col0 + b_i1r;
            rb1 = (gn1 < DD) ? *(const uint4*)(Bt + (size_t)gn1*DD + k0 + b_i1q*8)
                             : make_uint4(0u, 0u, 0u, 0u);
        }
    };
    auto stchunk = [&](int buf) {
        #pragma unroll
        for (int p = 0; p < 3; p++) {
            uint2 u;
            u.x = pack_h2(ra[p].x, ra[p].y);
            u.y = pack_h2(ra[p].z, ra[p].w);
            *(uint2*)(sAb[buf] + sr*XA_LD + (sg*3 + p)*4) = u;
        }
        *(uint4*)(sBb[buf] + b_i0r*XA_LD + b_i0q*8) = rb0;
        if (hasb1) *(uint4*)(sBb[buf] + b_i1r*XA_LD + b_i1q*8) = rb1;
    };
    auto compute = [&](int buf) {
        #pragma unroll
        for (int ks = 0; ks < XKC/16; ks++) {
            uint32_t af[2][4], bf[2][4];
            ldsm4(af[0], sAu[buf] + aoff[0] + ks*32);
            ldsm4(af[1], sAu[buf] + aoff[1] + ks*32);
            ldsm4(bf[0], sBu[buf] + boff[0] + ks*32);
            ldsm4(bf[1], sBu[buf] + boff[1] + ks*32);
            #pragma unroll
            for (int mi = 0; mi < 2; mi++) {
                mma_f16(acc[mi][0], af[mi], &bf[0][0]);
                mma_f16(acc[mi][1], af[mi], &bf[0][2]);
                mma_f16(acc[mi][2], af[mi], &bf[1][0]);
                mma_f16(acc[mi][3], af[mi], &bf[1][2]);
            }
        }
    };

    ldchunk(0);
    stchunk(0);
    __syncthreads();
    #pragma unroll 1
    for (int ch = 0; ch < DD/XKC; ch++) {
        if (ch + 1 < DD/XKC) ldchunk((ch + 1)*XKC);
        compute(ch & 1);
        if (ch + 1 < DD/XKC) {
            stchunk((ch + 1) & 1);
            __syncthreads();
        }
    }

    #pragma unroll
    for (int mi = 0; mi < 2; mi++) {
        #pragma unroll
        for (int h = 0; h < 2; h++) {
            int gm = row0 + wm*32 + mi*16 + gr + h*8;
            if (gm >= M) continue;
            #pragma unroll
            for (int ni = 0; ni < 4; ni++) {
                int gn = col0 + wn*32 + ni*8 + kq*2;
                if (gn + 1 < DD) {
                    C[(size_t)gm*DD + gn    ] = acc[mi][ni][2*h];
                    C[(size_t)gm*DD + gn + 1] = acc[mi][ni][2*h + 1];
                }
            }
        }
    }
}

// ---------------------------------------------------------------------------
// Sparse GCN aggregation, 3 classes via grid.z
// ---------------------------------------------------------------------------
__global__ void __launch_bounds__(256) k_spmm(
    const float* __restrict__ hbase,
    float* __restrict__ xbbase,
    const float* __restrict__ deg,
    const float* __restrict__ bgcn,
    int layer)
{
    int dst = blockIdx.x;
    int b   = blockIdx.y;
    int cls = blockIdx.z;
    int cb  = cls*BB + b;
    int tid = threadIdx.x;

    const float* bias = bgcn + (size_t)(cls*NLAY + layer)*DD;
    const float* h    = hbase + (size_t)cls*XSZ;
    float*       xb   = xbbase + (size_t)cls*XSZ;

    const int* off = g_off + cb*(NN1+1);
    int e0 = off[dst], e1 = off[dst+1];
    const int*   es = g_esrc  + cb*EE;
    const float* ec = g_ecoef + cb*EE;
    const float* hb = h + (size_t)b*NN1*DD;

    int c0 = tid, c1 = tid + 256, c2 = tid + 512;
    float a0 = 0.f, a1 = 0.f, a2 = 0.f;

    for (int e = e0; e < e1; e++) {
        int   src = es[e];
        float w   = ec[e];
        const float* hr = hb + (size_t)src*DD;
        a0 += w * hr[c0];
        if (c1 < DD) a1 += w * hr[c1];
        if (c2 < DD) a2 += w * hr[c2];
    }

    float dinv = 1.f / deg[cb*NN1 + dst];
    const float* hd = hb + (size_t)dst*DD;
    float* xo = xb + ((size_t)b*NN1 + dst)*DD;

    xo[c0] = a0 + hd[c0]*dinv + bias[c0];
    if (c1 < DD) xo[c1] = a1 + hd[c1]*dinv + bias[c1];
    if (c2 < DD) xo[c2] = a2 + hd[c2]*dinv + bias[c2];
}

// ---------------------------------------------------------------------------
// Collapsed head/tail + logits
// ---------------------------------------------------------------------------
__global__ void k_ho(const float* __restrict__ W_head, const float* __restrict__ W_tail,
                     const float* __restrict__ W_out,
                     const float* __restrict__ b_head, const float* __restrict__ b_tail,
                     float* __restrict__ Who, float* __restrict__ Wto,
                     float* __restrict__ bho, float* __restrict__ bto) {
    int t = blockIdx.x * blockDim.x + threadIdx.x;
    if (t < 2*DD*3) {
        int which = t / (DD*3), rc = t % (DD*3), r = rc / 3, c = rc % 3;
        const float* W = which ? W_tail : W_head;
        float acc = 0.f;
        for (int j = 0; j < DD; j++) acc += W[r*DD + j] * W_out[j*3 + c];
        (which ? Wto : Who)[r*3 + c] = acc;
    } else if (t < 2*DD*3 + 6) {
        int u = t - 2*DD*3, which = u / 3, c = u % 3;
        const float* bb = which ? b_tail : b_head;
        float acc = 0.f;
        for (int j = 0; j < DD; j++) acc += bb[j] * W_out[j*3 + c];
        (which ? bto : bho)[c] = acc;
    }
}

__global__ void k_hw(const float* __restrict__ xbc,
                     const float* __restrict__ Who, const float* __restrict__ Wto,
                     const float* __restrict__ bho, const float* __restrict__ bto,
                     float* __restrict__ hW, float* __restrict__ hT) {
    int t = blockIdx.x * blockDim.x + threadIdx.x;
    if (t >= 2*BB*NN1*3) return;
    int which = t / (BB*NN1*3);
    int rem = t % (BB*NN1*3);
    int bi = rem / 3, c = rem % 3;
    const float* r0 = xbc + (size_t)bi*DD;
    const float* r1 = r0 + XSZ;
    const float* r2 = r1 + XSZ;
    const float* W  = which ? Wto : Who;
    float acc = 0.f;
    for (int k = 0; k < DD; k++) acc += (r0[k] + r1[k] + r2[k]) * W[k*3 + c];
    acc = acc * (1.f/3.f) + (which ? bto[c] : bho[c]);
    (which ? hT : hW)[bi*3 + c] = acc;
}

__global__ void k_logits(const int* __restrict__ cands,
                         const float* __restrict__ hW, const float* __restrict__ hT,
                         const float* __restrict__ b_out,
                         float* __restrict__ out) {
    int t = blockIdx.x * blockDim.x + threadIdx.x;
    const int TOT = BB*NN1*(NN1-1)*3;
    if (t >= TOT) return;
    int c = t % 3;
    int j = (t / 3) & 255;
    int i = (t / (3*256)) % NN1;
    int b = t / (3*256*NN1);
    int m = cands[((long long)(b*NN1 + i))*NN1 + j + 1];
    float v = b_out[c];
    if (m) v += hW[(b*NN1 + i)*3 + c] + hT[(b*NN1 + j + 1)*3 + c];
    out[t] = v;
}

// ---------------------------------------------------------------------------
// Launch
// ---------------------------------------------------------------------------
extern "C" void kernel_launch(void* const* d_in, const int* in_sizes, int n_in,
                              void* d_out, int out_size) {
    const float* emb     = (const float*)d_in[0];
    const int*   entIdx  = (const int*)  d_in[1];
    const int*   entLab  = (const int*)  d_in[2];
    const int*   edgeIdx = (const int*)  d_in[3];
    const int*   edgeAttr= (const int*)  d_in[4];
    const int*   cands   = (const int*)  d_in[5];
    const float* W_red   = (const float*)d_in[6];
    const float* b_red   = (const float*)d_in[7];
    const float* tbl     = (const float*)d_in[8];
    const float* W_gcn   = (const float*)d_in[9];
    const float* b_gcn   = (const float*)d_in[10];
    const float* W_head  = (const float*)d_in[11];
    const float* b_head  = (const float*)d_in[12];
    const float* W_tail  = (const float*)d_in[13];
    const float* b_tail  = (const float*)d_in[14];
    const float* W_out   = (const float*)d_in[15];
    const float* b_out   = (const float*)d_in[16];
    float* out = (float*)d_out;

    static float *px0=nullptr, *phc, *pxbc, *pdeg,
                 *pWho, *pWto, *pbho, *pbto, *phW, *phT;
    static __half *pWt, *pWg, *pEh;
    static bool attr_set = false;
    if (!px0) {
        cudaGetSymbolAddress((void**)&px0,  g_x0);
        cudaGetSymbolAddress((void**)&phc,  g_hc);
        cudaGetSymbolAddress((void**)&pxbc, g_xbc);
        cudaGetSymbolAddress((void**)&pdeg, g_deg);
        cudaGetSymbolAddress((void**)&pWt,  g_Wt);
        cudaGetSymbolAddress((void**)&pWg,  g_Wg);
        cudaGetSymbolAddress((void**)&pEh,  g_embh);
        cudaGetSymbolAddress((void**)&pWho, g_Who);
        cudaGetSymbolAddress((void**)&pWto, g_Wto);
        cudaGetSymbolAddress((void**)&pbho, g_bho);
        cudaGetSymbolAddress((void**)&pbto, g_bto);
        cudaGetSymbolAddress((void**)&phW,  g_hW);
        cudaGetSymbolAddress((void**)&phT,  g_hT);
    }
    if (!attr_set) {
        cudaFuncSetAttribute(k_mma_red, cudaFuncAttributeMaxDynamicSharedMemorySize, RED_SMEM);
        cudaFuncSetAttribute(k_mma_xw,  cudaFuncAttributeMaxDynamicSharedMemorySize, XW_SMEM);
        attr_set = true;
    }

    auto blocks = [](int n) { return (n + 255) / 256; };

    // init scratch
    k_fill<<<blocks(XSZ), 256>>>(px0, XSZ, 0.f);
    k_fill<<<blocks(DEGSZ), 256>>>(pdeg, DEGSZ, 1.f);

    // labels + graph structure (CSR) + fp16 conversions
    k_labels<<<blocks(BB*NN1*LDD), 256>>>(px0, entLab, tbl);
    k_deg    <<<blocks(BB*EE), 256>>>(pdeg, edgeIdx, edgeAttr);
    k_off    <<<1, 64>>>(pdeg);
    k_scatter<<<blocks(BB*EE), 256>>>(pdeg, edgeIdx, edgeAttr);
    k_eh     <<<blocks(BB*SS*ETRD/4), 256>>>((const float4*)emb, (uint2*)pEh, BB*SS*ETRD/4);
    {
        dim3 bl(32, 32);
        k_th<<<dim3(ETRD/32, HH/32, 1), bl>>>(W_red, pWt, ETRD, HH);
        k_th<<<dim3((DD+31)/32, (DD+31)/32, NCLS*NLAY), bl>>>(W_gcn, pWg, DD, DD);
    }

    // big GEMM (fp16 mma + LDSM + cp.async) + fused relu/segmax scatter
    {
        dim3 g(HH/128, (BB*SS)/128);   // (4, 256)
        k_mma_red<<<g, 512, RED_SMEM>>>(pEh, pWt, b_red, entIdx, px0);
    }

    // GCN: 2 layers, all 3 classes per launch
    {
        dim3 gx((DD + 127)/128, (BB*NN1 + 127)/128, NCLS);   // (5, 33, 3)
        dim3 gs(NN1, BB, NCLS);
        k_mma_xw<<<gx, 512, XW_SMEM>>>(px0, pWg, phc, BB*NN1, 0LL, 0);
        k_spmm  <<<gs, 256>>>(phc, pxbc, pdeg, b_gcn, 0);
        k_mma_xw<<<gx, 512, XW_SMEM>>>(pxbc, pWg, phc, BB*NN1, (long long)XSZ, 1);
        k_spmm  <<<gs, 256>>>(phc, pxbc, pdeg, b_gcn, 1);
    }

    // collapsed head/tail + logits
    k_ho<<<blocks(2*DD*3 + 6), 256>>>(W_head, W_tail, W_out, b_head, b_tail,
                                      pWho, pWto, pbho, pbto);
    k_hw<<<blocks(2*BB*NN1*3), 256>>>(pxbc, pWho, pWto, pbho, pbto, phW, phT);
    k_logits<<<blocks(BB*NN1*(NN1-1)*3), 256>>>(cands, phW, phT, b_out, out);
}

// round 10
// speedup vs baseline: 3.2671x; 1.0243x over previous
#include <cuda_runtime.h>
#include <cuda_fp16.h>
#include <cstdint>

// ---------------------------------------------------------------------------
// Problem constants
// ---------------------------------------------------------------------------
#define BB    16
#define SS    2048
#define NN1   257
#define EE    4096
#define HH    512
#define LDD   16
#define ETRD  768
#define DD    528
#define DDP   576          // k-padded stride for fp16 activations/weights
#define NCLS  3
#define NLAY  2

#define MM    (BB*NN1)     // 4112 rows
#define XSZ   (BB*NN1*DD)
#define DEGSZ (NCLS*BB*NN1)
#define CBSZ  (NCLS*BB)

// ---------------------------------------------------------------------------
// Device scratch
// ---------------------------------------------------------------------------
__device__ float  g_x0 [XSZ];
__device__ __half g_x0h[MM*DDP];           // x0 fp16, k-padded
__device__ float  g_hc [NCLS*XSZ];         // h per class (fp32)
__device__ __half g_xb16[NCLS*MM*DDP];     // layer-0 output, fp16 k-padded
__device__ float  g_xbc[NCLS*XSZ];         // layer-1 output (fp32, for k_hw)
__device__ float  g_deg[DEGSZ];
__device__ int    g_off[CBSZ*(NN1+1)];
__device__ int    g_cur[CBSZ*NN1];
__device__ int    g_esrc[CBSZ*EE];
__device__ float  g_ecoef[CBSZ*EE];
__device__ __half g_embh[BB*SS*ETRD];      // emb fp16
__device__ __half g_Wt [HH*ETRD];          // W_red^T (n-major) fp16
__device__ __half g_Wg [NCLS*NLAY*DD*DDP]; // W_gcn^T per (c,l), n-major, k-padded fp16
__device__ float  g_Who[DD*3];
__device__ float  g_Wto[DD*3];
__device__ float  g_bho[3];
__device__ float  g_bto[3];
__device__ float  g_hW [BB*NN1*3];
__device__ float  g_hT [BB*NN1*3];

// ---------------------------------------------------------------------------
// mma / ldmatrix / cp.async helpers (generic PTX, OK for compute_103)
// ---------------------------------------------------------------------------
__device__ __forceinline__ void mma_f16(float* c, const uint32_t* a, const uint32_t* b) {
    asm volatile(
        "mma.sync.aligned.m16n8k16.row.col.f32.f16.f16.f32 "
        "{%0,%1,%2,%3}, {%4,%5,%6,%7}, {%8,%9}, {%0,%1,%2,%3};"
        : "+f"(c[0]), "+f"(c[1]), "+f"(c[2]), "+f"(c[3])
        : "r"(a[0]), "r"(a[1]), "r"(a[2]), "r"(a[3]), "r"(b[0]), "r"(b[1]));
}

__device__ __forceinline__ void ldsm4(uint32_t* r, uint32_t saddr) {
    asm volatile("ldmatrix.sync.aligned.m8n8.x4.shared.b16 {%0,%1,%2,%3}, [%4];"
                 : "=r"(r[0]), "=r"(r[1]), "=r"(r[2]), "=r"(r[3]) : "r"(saddr));
}

__device__ __forceinline__ uint32_t s2u(const void* p) {
    return (uint32_t)__cvta_generic_to_shared(p);
}

__device__ __forceinline__ void cp16(uint32_t s, const void* g) {
    asm volatile("cp.async.cg.shared.global [%0], [%1], 16;" :: "r"(s), "l"(g));
}
#define CP_COMMIT() asm volatile("cp.async.commit_group;" ::: "memory")
#define CP_WAIT0()  asm volatile("cp.async.wait_group 0;"  ::: "memory")

__device__ __forceinline__ uint32_t pack_h2(float x, float y) {
    __half2 h = __floats2half2_rn(x, y);
    return *(uint32_t*)&h;
}

// ---------------------------------------------------------------------------
// Small helper kernels
// ---------------------------------------------------------------------------
__global__ void k_fill(float* __restrict__ p, int n, float v) {
    int i = blockIdx.x * blockDim.x + threadIdx.x;
    if (i < n) p[i] = v;
}

// fp32 -> fp16 bulk convert (float4 -> uint2)
__global__ void k_eh(const float4* __restrict__ in, uint2* __restrict__ outp, int n4) {
    int i = blockIdx.x * blockDim.x + threadIdx.x;
    if (i < n4) {
        float4 v = in[i];
        uint2 u;
        u.x = pack_h2(v.x, v.y);
        u.y = pack_h2(v.z, v.w);
        outp[i] = u;
    }
}

// x0 fp32 [MM][DD] -> x0h fp16 [MM][DDP] with zero pad
__global__ void k_x0h(const float* __restrict__ x0, __half* __restrict__ x0h) {
    int t = blockIdx.x * blockDim.x + threadIdx.x;
    if (t >= MM*DDP) return;
    int r = t / DDP, c = t % DDP;
    x0h[t] = (c < DD) ? __float2half_rn(x0[(size_t)r*DD + c]) : __half(0);
}

__global__ void k_labels(float* __restrict__ x0,
                         const int* __restrict__ entLab,
                         const float* __restrict__ tbl) {
    int t = blockIdx.x * blockDim.x + threadIdx.x;
    if (t >= BB*NN1*LDD) return;
    int d = t & 15;
    int i = (t >> 4) % NN1;
    int b = t / (NN1*LDD);
    float v;
    if (i == 0) v = tbl[d];
    else {
        int lbl = entLab[b*(NN1-1) + i - 1];
        v = lbl ? tbl[lbl*LDD + d] : 0.f;
    }
    x0[((long long)(b*NN1 + i))*DD + d] = v;
}

__global__ void k_deg(float* __restrict__ deg,
                      const int* __restrict__ ei,
                      const int* __restrict__ ea) {
    int t = blockIdx.x * blockDim.x + threadIdx.x;
    if (t >= BB*EE) return;
    int b = t >> 12, e = t & (EE-1);
    int dst = ei[b*2*EE + EE + e];
    int a   = ea[b*EE + e];
    atomicAdd(&deg[(a*BB + b)*NN1 + dst], 1.f);
}

__global__ void k_off(const float* __restrict__ deg) {
    int t = blockIdx.x * blockDim.x + threadIdx.x;
    if (t >= CBSZ) return;
    const float* dg = deg + t*NN1;
    int* off = g_off + t*(NN1+1);
    int* cur = g_cur + t*NN1;
    int acc = 0;
    off[0] = 0;
    for (int i = 0; i < NN1; i++) {
        cur[i] = acc;
        acc += (int)dg[i] - 1;
        off[i+1] = acc;
    }
}

__global__ void k_scatter(const float* __restrict__ deg,
                          const int* __restrict__ ei,
                          const int* __restrict__ ea) {
    int t = blockIdx.x * blockDim.x + threadIdx.x;
    if (t >= BB*EE) return;
    int b = t >> 12, e = t & (EE-1);
    int src = ei[b*2*EE + e];
    int dst = ei[b*2*EE + EE + e];
    int a   = ea[b*EE + e];
    int cb  = a*BB + b;
    const float* dg = deg + cb*NN1;
    float coef = rsqrtf(dg[src]) * rsqrtf(dg[dst]);
    int pos = atomicAdd(&g_cur[cb*NN1 + dst], 1);
    g_esrc [cb*EE + pos] = src;
    g_ecoef[cb*EE + pos] = coef;
}

// transpose + fp16 convert with k padding: W [K][N] f32 -> Wt [N][KP] fp16
// (zero for ko in [K,KP)), z-batched.
__global__ void k_th(const float* __restrict__ W, __half* __restrict__ Wt,
                     int K, int N, int KP) {
    const float* Wz  = W  + (size_t)blockIdx.z*K*N;
    __half*      Wtz = Wt + (size_t)blockIdx.z*N*KP;
    __shared__ float t[32][33];
    int k = blockIdx.x*32 + threadIdx.y;
    int n = blockIdx.y*32 + threadIdx.x;
    if (k < K && n < N) t[threadIdx.y][threadIdx.x] = Wz[(size_t)k*N + n];
    __syncthreads();
    int no = blockIdx.y*32 + threadIdx.y;
    int ko = blockIdx.x*32 + threadIdx.x;
    if (no < N && ko < KP)
        Wtz[(size_t)no*KP + ko] = (ko < K) ? __float2half_rn(t[threadIdx.x][threadIdx.y])
                                           : __half(0);
}

// ---------------------------------------------------------------------------
// Big fp16 GEMM, cp.async + LDSM: red = emb@W_red (+bias/relu/segmax).
// M=32768, N=512, K=768. 512 thr, 16 warps 32x32, KC=64.
// ---------------------------------------------------------------------------
#define KC    64
#define RA_LD 72
#define R_SZH (128*RA_LD)
#define RED_SMEM (4*R_SZH*2)

__global__ void __launch_bounds__(512, 1) k_mma_red(
    const __half* __restrict__ A,
    const __half* __restrict__ Bt,
    const float*  __restrict__ bias,
    const int*    __restrict__ entIdx,
    float*        __restrict__ x0)
{
    extern __shared__ __align__(16) __half smh[];
    __half* sAb[2] = { smh,            smh + R_SZH };
    __half* sBb[2] = { smh + 2*R_SZH,  smh + 3*R_SZH };

    const int tid  = threadIdx.x;
    const int lane = tid & 31;
    const int wid  = tid >> 5;
    const int gr   = lane >> 2;
    const int kq   = lane & 3;
    const int wm   = wid & 3;
    const int wn   = wid >> 2;
    const int row0 = blockIdx.y * 128;
    const int col0 = blockIdx.x * 128;

    const int sr = tid >> 2;
    const int sg = tid & 3;

    const int arow_l = ((lane >> 3) & 1)*8 + (lane & 7);
    const int acol_l = (lane >> 4)*8;
    const int brow_l = (lane >> 4)*8 + (lane & 7);
    const int bcol_l = ((lane >> 3) & 1)*8;
    uint32_t aoff[2], boff[2];
    #pragma unroll
    for (int mi = 0; mi < 2; mi++)
        aoff[mi] = ((wm*32 + mi*16 + arow_l)*RA_LD + acol_l)*2;
    #pragma unroll
    for (int pr = 0; pr < 2; pr++)
        boff[pr] = ((wn*32 + pr*16 + brow_l)*RA_LD + bcol_l)*2;
    uint32_t sAu[2] = { s2u(sAb[0]), s2u(sAb[1]) };
    uint32_t sBu[2] = { s2u(sBb[0]), s2u(sBb[1]) };

    float acc[2][4][4];
    #pragma unroll
    for (int i = 0; i < 2; i++)
        #pragma unroll
        for (int j = 0; j < 4; j++)
            #pragma unroll
            for (int u = 0; u < 4; u++) acc[i][j][u] = 0.f;

    const __half* agp = A  + (size_t)(row0 + sr)*ETRD + sg*16;
    const __half* bgp = Bt + (size_t)(col0 + sr)*ETRD + sg*16;
    const uint32_t sAoff = (sr*RA_LD + sg*16)*2;

    auto ldchunk = [&](int k0, int buf) {
        cp16(sAu[buf] + sAoff,      agp + k0);
        cp16(sAu[buf] + sAoff + 16, agp + k0 + 8);
        cp16(sBu[buf] + sAoff,      bgp + k0);
        cp16(sBu[buf] + sAoff + 16, bgp + k0 + 8);
        CP_COMMIT();
    };
    auto compute = [&](int buf) {
        #pragma unroll
        for (int ks = 0; ks < KC/16; ks++) {
            uint32_t af[2][4], bf[2][4];
            ldsm4(af[0], sAu[buf] + aoff[0] + ks*32);
            ldsm4(af[1], sAu[buf] + aoff[1] + ks*32);
            ldsm4(bf[0], sBu[buf] + boff[0] + ks*32);
            ldsm4(bf[1], sBu[buf] + boff[1] + ks*32);
            #pragma unroll
            for (int mi = 0; mi < 2; mi++) {
                mma_f16(acc[mi][0], af[mi], &bf[0][0]);
                mma_f16(acc[mi][1], af[mi], &bf[0][2]);
                mma_f16(acc[mi][2], af[mi], &bf[1][0]);
                mma_f16(acc[mi][3], af[mi], &bf[1][2]);
            }
        }
    };

    ldchunk(0, 0);
    CP_WAIT0();
    __syncthreads();
    #pragma unroll 1
    for (int ch = 0; ch < ETRD/KC; ch++) {
        if (ch + 1 < ETRD/KC) ldchunk((ch + 1)*KC, (ch + 1) & 1);
        compute(ch & 1);
        if (ch + 1 < ETRD/KC) {
            CP_WAIT0();
            __syncthreads();
        }
    }

    // Epilogue: fused bias + relu + segment-max scatter (predicated)
    int    nodev[2][2];
    float* basep[2][2];
    #pragma unroll
    for (int mi = 0; mi < 2; mi++)
        #pragma unroll
        for (int h = 0; h < 2; h++) {
            int r  = row0 + wm*32 + mi*16 + gr + h*8;
            int nd = entIdx[r];
            nodev[mi][h] = nd;
            int b = r >> 11;
            basep[mi][h] = x0 + ((size_t)(b*NN1 + nd))*DD + LDD;
        }
    #pragma unroll
    for (int ni = 0; ni < 4; ni++) {
        int c = col0 + wn*32 + ni*8 + kq*2;
        float b0 = __ldg(bias + c), b1 = __ldg(bias + c + 1);
        #pragma unroll
        for (int mi = 0; mi < 2; mi++) {
            #pragma unroll
            for (int h = 0; h < 2; h++) {
                if (nodev[mi][h] == 0) continue;
                float v0 = acc[mi][ni][2*h    ] + b0;
                float v1 = acc[mi][ni][2*h + 1] + b1;
                if (v0 > 0.f) atomicMax((int*)(basep[mi][h] + c),     __float_as_int(v0));
                if (v1 > 0.f) atomicMax((int*)(basep[mi][h] + c + 1), __float_as_int(v1));
            }
        }
    }
}

// ---------------------------------------------------------------------------
// xW GEMM, full cp.async + LDSM, 3 classes via grid.z: h_z = x_z @ W_z.
// A fp16 k-padded [M][DDP], B fp16 n-major k-padded [DD][DDP].
// M=4112, N=528(DD), K=576(DDP, zero-padded). KC=64 -> 9 exact chunks.
// Row/col cp.async clamps; garbage maps only to unstored outputs.
// ---------------------------------------------------------------------------
__global__ void __launch_bounds__(512, 1) k_mma_xw(
    const __half* __restrict__ Abase,  // + z*strideA
    const __half* __restrict__ Wg,     // + (z*NLAY+l)*DD*DDP
    float*        __restrict__ Cbase,  // + z*XSZ, stride DD
    int M, long long strideA, int layer)
{
    const int z = blockIdx.z;
    const __half* A  = Abase + (size_t)z*strideA;
    const __half* Bt = Wg + ((size_t)z*NLAY + layer)*DD*DDP;
    float* C = Cbase + (size_t)z*XSZ;

    extern __shared__ __align__(16) __half smh[];
    __half* sAb[2] = { smh,            smh + R_SZH };
    __half* sBb[2] = { smh + 2*R_SZH,  smh + 3*R_SZH };

    const int tid  = threadIdx.x;
    const int lane = tid & 31;
    const int wid  = tid >> 5;
    const int gr   = lane >> 2;
    const int kq   = lane & 3;
    const int wm   = wid & 3;
    const int wn   = wid >> 2;
    const int row0 = blockIdx.y * 128;
    const int col0 = blockIdx.x * 128;

    const int sr = tid >> 2;
    const int sg = tid & 3;

    const int arow_l = ((lane >> 3) & 1)*8 + (lane & 7);
    const int acol_l = (lane >> 4)*8;
    const int brow_l = (lane >> 4)*8 + (lane & 7);
    const int bcol_l = ((lane >> 3) & 1)*8;
    uint32_t aoff[2], boff[2];
    #pragma unroll
    for (int mi = 0; mi < 2; mi++)
        aoff[mi] = ((wm*32 + mi*16 + arow_l)*RA_LD + acol_l)*2;
    #pragma unroll
    for (int pr = 0; pr < 2; pr++)
        boff[pr] = ((wn*32 + pr*16 + brow_l)*RA_LD + bcol_l)*2;
    uint32_t sAu[2] = { s2u(sAb[0]), s2u(sAb[1]) };
    uint32_t sBu[2] = { s2u(sBb[0]), s2u(sBb[1]) };

    float acc[2][4][4];
    #pragma unroll
    for (int i = 0; i < 2; i++)
        #pragma unroll
        for (int j = 0; j < 4; j++)
            #pragma unroll
            for (int u = 0; u < 4; u++) acc[i][j][u] = 0.f;

    // clamped feed pointers (clamped rows produce garbage only in unstored outputs)
    int arow = row0 + sr; if (arow >= M)  arow = M - 1;
    int brow = col0 + sr; if (brow >= DD) brow = DD - 1;
    const __half* agp = A  + (size_t)arow*DDP + sg*16;
    const __half* bgp = Bt + (size_t)brow*DDP + sg*16;
    const uint32_t sAoff = (sr*RA_LD + sg*16)*2;

    auto ldchunk = [&](int k0, int buf) {
        cp16(sAu[buf] + sAoff,      agp + k0);
        cp16(sAu[buf] + sAoff + 16, agp + k0 + 8);
        cp16(sBu[buf] + sAoff,      bgp + k0);
        cp16(sBu[buf] + sAoff + 16, bgp + k0 + 8);
        CP_COMMIT();
    };
    auto compute = [&](int buf) {
        #pragma unroll
        for (int ks = 0; ks < KC/16; ks++) {
            uint32_t af[2][4], bf[2][4];
            ldsm4(af[0], sAu[buf] + aoff[0] + ks*32);
            ldsm4(af[1], sAu[buf] + aoff[1] + ks*32);
            ldsm4(bf[0], sBu[buf] + boff[0] + ks*32);
            ldsm4(bf[1], sBu[buf] + boff[1] + ks*32);
            #pragma unroll
            for (int mi = 0; mi < 2; mi++) {
                mma_f16(acc[mi][0], af[mi], &bf[0][0]);
                mma_f16(acc[mi][1], af[mi], &bf[0][2]);
                mma_f16(acc[mi][2], af[mi], &bf[1][0]);
                mma_f16(acc[mi][3], af[mi], &bf[1][2]);
            }
        }
    };

    ldchunk(0, 0);
    CP_WAIT0();
    __syncthreads();
    #pragma unroll 1
    for (int ch = 0; ch < DDP/KC; ch++) {      // 9 chunks, pad contributes 0
        if (ch + 1 < DDP/KC) ldchunk((ch + 1)*KC, (ch + 1) & 1);
        compute(ch & 1);
        if (ch + 1 < DDP/KC) {
            CP_WAIT0();
            __syncthreads();
        }
    }

    #pragma unroll
    for (int mi = 0; mi < 2; mi++) {
        #pragma unroll
        for (int h = 0; h < 2; h++) {
            int gm = row0 + wm*32 + mi*16 + gr + h*8;
            if (gm >= M) continue;
            #pragma unroll
            for (int ni = 0; ni < 4; ni++) {
                int gn = col0 + wn*32 + ni*8 + kq*2;
                if (gn < DD) {
                    C[(size_t)gm*DD + gn    ] = acc[mi][ni][2*h];
                    C[(size_t)gm*DD + gn + 1] = acc[mi][ni][2*h + 1];
                }
            }
        }
    }
}

// ---------------------------------------------------------------------------
// Sparse GCN aggregation, 3 classes via grid.z.
// layer 0: writes fp16 k-padded xb16 (zero pad filled here).
// layer 1: writes fp32 xb (for k_hw).
// ---------------------------------------------------------------------------
__global__ void __launch_bounds__(256) k_spmm(
    const float* __restrict__ hbase,
    float*  __restrict__ xbF,          // layer1 out (fp32, stride DD)
    __half* __restrict__ xbH,          // layer0 out (fp16, stride DDP)
    const float* __restrict__ deg,
    const float* __restrict__ bgcn,
    int layer)
{
    int dst = blockIdx.x;
    int b   = blockIdx.y;
    int cls = blockIdx.z;
    int cb  = cls*BB + b;
    int tid = threadIdx.x;

    const float* bias = bgcn + (size_t)(cls*NLAY + layer)*DD;
    const float* h    = hbase + (size_t)cls*XSZ;

    const int* off = g_off + cb*(NN1+1);
    int e0 = off[dst], e1 = off[dst+1];
    const int*   es = g_esrc  + cb*EE;
    const float* ec = g_ecoef + cb*EE;
    const float* hb = h + (size_t)b*NN1*DD;

    int c0 = tid, c1 = tid + 256, c2 = tid + 512;
    float a0 = 0.f, a1 = 0.f, a2 = 0.f;

    for (int e = e0; e < e1; e++) {
        int   src = es[e];
        float w   = ec[e];
        const float* hr = hb + (size_t)src*DD;
        a0 += w * hr[c0];
        if (c1 < DD) a1 += w * hr[c1];
        if (c2 < DD) a2 += w * hr[c2];
    }

    float dinv = 1.f / deg[cb*NN1 + dst];
    const float* hd = hb + (size_t)dst*DD;

    float v0 = a0 + hd[c0]*dinv + bias[c0];
    float v1 = (c1 < DD) ? a1 + hd[c1]*dinv + bias[c1] : 0.f;
    float v2 = (c2 < DD) ? a2 + hd[c2]*dinv + bias[c2] : 0.f;

    if (layer == 0) {
        __half* xo = xbH + ((size_t)cls*MM + (size_t)b*NN1 + dst)*DDP;
        xo[c0] = __float2half_rn(v0);
        if (c1 < DD) xo[c1] = __float2half_rn(v1);
        if (c2 < DD) xo[c2] = __float2half_rn(v2);
        else if (c2 < DDP) xo[c2] = __half(0);   // zero pad cols [528,576)
    } else {
        float* xo = xbF + ((size_t)cls*MM + (size_t)b*NN1 + dst)*DD;
        xo[c0] = v0;
        if (c1 < DD) xo[c1] = v1;
        if (c2 < DD) xo[c2] = v2;
    }
}

// ---------------------------------------------------------------------------
// Collapsed head/tail + logits
// ---------------------------------------------------------------------------
__global__ void k_ho(const float* __restrict__ W_head, const float* __restrict__ W_tail,
                     const float* __restrict__ W_out,
                     const float* __restrict__ b_head, const float* __restrict__ b_tail,
                     float* __restrict__ Who, float* __restrict__ Wto,
                     float* __restrict__ bho, float* __restrict__ bto) {
    int t = blockIdx.x * blockDim.x + threadIdx.x;
    if (t < 2*DD*3) {
        int which = t / (DD*3), rc = t % (DD*3), r = rc / 3, c = rc % 3;
        const float* W = which ? W_tail : W_head;
        float acc = 0.f;
        for (int j = 0; j < DD; j++) acc += W[r*DD + j] * W_out[j*3 + c];
        (which ? Wto : Who)[r*3 + c] = acc;
    } else if (t < 2*DD*3 + 6) {
        int u = t - 2*DD*3, which = u / 3, c = u % 3;
        const float* bb = which ? b_tail : b_head;
        float acc = 0.f;
        for (int j = 0; j < DD; j++) acc += bb[j] * W_out[j*3 + c];
        (which ? bto : bho)[c] = acc;
    }
}

__global__ void k_hw(const float* __restrict__ xbc,
                     const float* __restrict__ Who, const float* __restrict__ Wto,
                     const float* __restrict__ bho, const float* __restrict__ bto,
                     float* __restrict__ hW, float* __restrict__ hT) {
    int t = blockIdx.x * blockDim.x + threadIdx.x;
    if (t >= 2*BB*NN1*3) return;
    int which = t / (BB*NN1*3);
    int rem = t % (BB*NN1*3);
    int bi = rem / 3, c = rem % 3;
    const float* r0 = xbc + (size_t)bi*DD;
    const float* r1 = r0 + XSZ;
    const float* r2 = r1 + XSZ;
    const float* W  = which ? Wto : Who;
    float acc = 0.f;
    for (int k = 0; k < DD; k++) acc += (r0[k] + r1[k] + r2[k]) * W[k*3 + c];
    acc = acc * (1.f/3.f) + (which ? bto[c] : bho[c]);
    (which ? hT : hW)[bi*3 + c] = acc;
}

__global__ void k_logits(const int* __restrict__ cands,
                         const float* __restrict__ hW, const float* __restrict__ hT,
                         const float* __restrict__ b_out,
                         float* __restrict__ out) {
    int t = blockIdx.x * blockDim.x + threadIdx.x;
    const int TOT = BB*NN1*(NN1-1)*3;
    if (t >= TOT) return;
    int c = t % 3;
    int j = (t / 3) & 255;
    int i = (t / (3*256)) % NN1;
    int b = t / (3*256*NN1);
    int m = cands[((long long)(b*NN1 + i))*NN1 + j + 1];
    float v = b_out[c];
    if (m) v += hW[(b*NN1 + i)*3 + c] + hT[(b*NN1 + j + 1)*3 + c];
    out[t] = v;
}

// ---------------------------------------------------------------------------
// Launch
// ---------------------------------------------------------------------------
extern "C" void kernel_launch(void* const* d_in, const int* in_sizes, int n_in,
                              void* d_out, int out_size) {
    const float* emb     = (const float*)d_in[0];
    const int*   entIdx  = (const int*)  d_in[1];
    const int*   entLab  = (const int*)  d_in[2];
    const int*   edgeIdx = (const int*)  d_in[3];
    const int*   edgeAttr= (const int*)  d_in[4];
    const int*   cands   = (const int*)  d_in[5];
    const float* W_red   = (const float*)d_in[6];
    const float* b_red   = (const float*)d_in[7];
    const float* tbl     = (const float*)d_in[8];
    const float* W_gcn   = (const float*)d_in[9];
    const float* b_gcn   = (const float*)d_in[10];
    const float* W_head  = (const float*)d_in[11];
    const float* b_head  = (const float*)d_in[12];
    const float* W_tail  = (const float*)d_in[13];
    const float* b_tail  = (const float*)d_in[14];
    const float* W_out   = (const float*)d_in[15];
    const float* b_out   = (const float*)d_in[16];
    float* out = (float*)d_out;

    static float *px0=nullptr, *phc, *pxbc, *pdeg,
                 *pWho, *pWto, *pbho, *pbto, *phW, *phT;
    static __half *pWt, *pWg, *pEh, *px0h, *pxb16;
    static bool attr_set = false;
    if (!px0) {
        cudaGetSymbolAddress((void**)&px0,   g_x0);
        cudaGetSymbolAddress((void**)&px0h,  g_x0h);
        cudaGetSymbolAddress((void**)&phc,   g_hc);
        cudaGetSymbolAddress((void**)&pxb16, g_xb16);
        cudaGetSymbolAddress((void**)&pxbc,  g_xbc);
        cudaGetSymbolAddress((void**)&pdeg,  g_deg);
        cudaGetSymbolAddress((void**)&pWt,   g_Wt);
        cudaGetSymbolAddress((void**)&pWg,   g_Wg);
        cudaGetSymbolAddress((void**)&pEh,   g_embh);
        cudaGetSymbolAddress((void**)&pWho,  g_Who);
        cudaGetSymbolAddress((void**)&pWto,  g_Wto);
        cudaGetSymbolAddress((void**)&pbho,  g_bho);
        cudaGetSymbolAddress((void**)&pbto,  g_bto);
        cudaGetSymbolAddress((void**)&phW,   g_hW);
        cudaGetSymbolAddress((void**)&phT,   g_hT);
    }
    if (!attr_set) {
        cudaFuncSetAttribute(k_mma_red, cudaFuncAttributeMaxDynamicSharedMemorySize, RED_SMEM);
        cudaFuncSetAttribute(k_mma_xw,  cudaFuncAttributeMaxDynamicSharedMemorySize, RED_SMEM);
        attr_set = true;
    }

    auto blocks = [](int n) { return (n + 255) / 256; };

    // init scratch
    k_fill<<<blocks(XSZ), 256>>>(px0, XSZ, 0.f);
    k_fill<<<blocks(DEGSZ), 256>>>(pdeg, DEGSZ, 1.f);

    // labels + graph structure (CSR) + fp16 conversions
    k_labels<<<blocks(BB*NN1*LDD), 256>>>(px0, entLab, tbl);
    k_deg    <<<blocks(BB*EE), 256>>>(pdeg, edgeIdx, edgeAttr);
    k_off    <<<1, 64>>>(pdeg);
    k_scatter<<<blocks(BB*EE), 256>>>(pdeg, edgeIdx, edgeAttr);
    k_eh     <<<blocks(BB*SS*ETRD/4), 256>>>((const float4*)emb, (uint2*)pEh, BB*SS*ETRD/4);
    {
        dim3 bl(32, 32);
        k_th<<<dim3(ETRD/32, HH/32, 1), bl>>>(W_red, pWt, ETRD, HH, ETRD);
        k_th<<<dim3(DDP/32, (DD+31)/32, NCLS*NLAY), bl>>>(W_gcn, pWg, DD, DD, DDP);
    }

    // big GEMM (fp16 mma + LDSM + cp.async) + fused relu/segmax scatter
    {
        dim3 g(HH/128, (BB*SS)/128);   // (4, 256)
        k_mma_red<<<g, 512, RED_SMEM>>>(pEh, pWt, b_red, entIdx, px0);
    }
    // x0 -> fp16 k-padded mirror
    k_x0h<<<blocks(MM*DDP), 256>>>(px0, px0h);

    // GCN: 2 layers, all 3 classes per launch, full cp.async GEMMs
    {
        dim3 gx((DD + 127)/128, (MM + 127)/128, NCLS);   // (5, 33, 3)
        dim3 gs(NN1, BB, NCLS);
        k_mma_xw<<<gx, 512, RED_SMEM>>>(px0h, pWg, phc, MM, 0LL, 0);
        k_spmm  <<<gs, 256>>>(phc, nullptr, pxb16, pdeg, b_gcn, 0);
        k_mma_xw<<<gx, 512, RED_SMEM>>>(pxb16, pWg, phc, MM, (long long)MM*DDP, 1);
        k_spmm  <<<gs, 256>>>(phc, pxbc, nullptr, pdeg, b_gcn, 1);
    }

    // collapsed head/tail + logits
    k_ho<<<blocks(2*DD*3 + 6), 256>>>(W_head, W_tail, W_out, b_head, b_tail,
                                      pWho, pWto, pbho, pbto);
    k_hw<<<blocks(2*BB*NN1*3), 256>>>(pxbc, pWho, pWto, pbho, pbto, phW, phT);
    k_logits<<<blocks(BB*NN1*(NN1-1)*3), 256>>>(cands, phW, phT, b_out, out);
}

// round 11
// speedup vs baseline: 3.3307x; 1.0195x over previous
#include <cuda_runtime.h>
#include <cuda_fp16.h>
#include <cstdint>

// ---------------------------------------------------------------------------
// Problem constants
// ---------------------------------------------------------------------------
#define BB    16
#define SS    2048
#define NN1   257
#define EE    4096
#define HH    512
#define LDD   16
#define ETRD  768
#define DD    528
#define DDP   576          // k-padded stride for fp16 activations/weights
#define NCLS  3
#define NLAY  2

#define MM    (BB*NN1)     // 4112 rows
#define XSZ   (BB*NN1*DD)
#define DEGSZ (NCLS*BB*NN1)
#define CBSZ  (NCLS*BB)

// ---------------------------------------------------------------------------
// Device scratch
// ---------------------------------------------------------------------------
__device__ float  g_x0 [XSZ];
__device__ __half g_x0h[MM*DDP];           // x0 fp16, k-padded
__device__ __half g_hc [NCLS*MM*DDP];      // h per class, fp16 k-strided (pad unread)
__device__ __half g_xb16[NCLS*MM*DDP];     // layer-0 output, fp16 k-padded
__device__ float  g_xbc[NCLS*XSZ];         // layer-1 output (fp32, for k_hw)
__device__ float  g_deg[DEGSZ];
__device__ int    g_off[CBSZ*(NN1+1)];
__device__ int    g_cur[CBSZ*NN1];
__device__ int    g_esrc[CBSZ*EE];
__device__ float  g_ecoef[CBSZ*EE];
__device__ __half g_embh[BB*SS*ETRD];      // emb fp16
__device__ __half g_Wt [HH*ETRD];          // W_red^T (n-major) fp16
__device__ __half g_Wg [NCLS*NLAY*DD*DDP]; // W_gcn^T per (c,l), n-major, k-padded fp16
__device__ float  g_Who[DD*3];
__device__ float  g_Wto[DD*3];
__device__ float  g_bho[3];
__device__ float  g_bto[3];
__device__ float  g_hW [BB*NN1*3];
__device__ float  g_hT [BB*NN1*3];

// ---------------------------------------------------------------------------
// mma / ldmatrix / cp.async helpers (generic PTX, OK for compute_103)
// ---------------------------------------------------------------------------
__device__ __forceinline__ void mma_f16(float* c, const uint32_t* a, const uint32_t* b) {
    asm volatile(
        "mma.sync.aligned.m16n8k16.row.col.f32.f16.f16.f32 "
        "{%0,%1,%2,%3}, {%4,%5,%6,%7}, {%8,%9}, {%0,%1,%2,%3};"
        : "+f"(c[0]), "+f"(c[1]), "+f"(c[2]), "+f"(c[3])
        : "r"(a[0]), "r"(a[1]), "r"(a[2]), "r"(a[3]), "r"(b[0]), "r"(b[1]));
}

__device__ __forceinline__ void ldsm4(uint32_t* r, uint32_t saddr) {
    asm volatile("ldmatrix.sync.aligned.m8n8.x4.shared.b16 {%0,%1,%2,%3}, [%4];"
                 : "=r"(r[0]), "=r"(r[1]), "=r"(r[2]), "=r"(r[3]) : "r"(saddr));
}

__device__ __forceinline__ uint32_t s2u(const void* p) {
    return (uint32_t)__cvta_generic_to_shared(p);
}

__device__ __forceinline__ void cp16(uint32_t s, const void* g) {
    asm volatile("cp.async.cg.shared.global [%0], [%1], 16;" :: "r"(s), "l"(g));
}
#define CP_COMMIT() asm volatile("cp.async.commit_group;" ::: "memory")
#define CP_WAIT0()  asm volatile("cp.async.wait_group 0;"  ::: "memory")

__device__ __forceinline__ uint32_t pack_h2(float x, float y) {
    __half2 h = __floats2half2_rn(x, y);
    return *(uint32_t*)&h;
}

// ---------------------------------------------------------------------------
// Small helper kernels
// ---------------------------------------------------------------------------
__global__ void k_fill(float* __restrict__ p, int n, float v) {
    int i = blockIdx.x * blockDim.x + threadIdx.x;
    if (i < n) p[i] = v;
}

// x0 init: zeros + label part in one pass
__global__ void k_initx0(float* __restrict__ x0,
                         const int* __restrict__ entLab,
                         const float* __restrict__ tbl) {
    int t = blockIdx.x * blockDim.x + threadIdx.x;
    if (t >= XSZ) return;
    int r = t / DD, c = t % DD;
    float v = 0.f;
    if (c < LDD) {
        int i = r % NN1, b = r / NN1;
        if (i == 0) v = tbl[c];
        else {
            int lbl = entLab[b*(NN1-1) + i - 1];
            v = lbl ? tbl[lbl*LDD + c] : 0.f;
        }
    }
    x0[t] = v;
}

// fp32 -> fp16 bulk convert (float4 -> uint2)
__global__ void k_eh(const float4* __restrict__ in, uint2* __restrict__ outp, int n4) {
    int i = blockIdx.x * blockDim.x + threadIdx.x;
    if (i < n4) {
        float4 v = in[i];
        uint2 u;
        u.x = pack_h2(v.x, v.y);
        u.y = pack_h2(v.z, v.w);
        outp[i] = u;
    }
}

// x0 fp32 [MM][DD] -> x0h fp16 [MM][DDP] with zero pad
__global__ void k_x0h(const float* __restrict__ x0, __half* __restrict__ x0h) {
    int t = blockIdx.x * blockDim.x + threadIdx.x;
    if (t >= MM*DDP) return;
    int r = t / DDP, c = t % DDP;
    x0h[t] = (c < DD) ? __float2half_rn(x0[(size_t)r*DD + c]) : __half(0);
}

__global__ void k_deg(float* __restrict__ deg,
                      const int* __restrict__ ei,
                      const int* __restrict__ ea) {
    int t = blockIdx.x * blockDim.x + threadIdx.x;
    if (t >= BB*EE) return;
    int b = t >> 12, e = t & (EE-1);
    int dst = ei[b*2*EE + EE + e];
    int a   = ea[b*EE + e];
    atomicAdd(&deg[(a*BB + b)*NN1 + dst], 1.f);
}

__global__ void k_off(const float* __restrict__ deg) {
    int t = blockIdx.x * blockDim.x + threadIdx.x;
    if (t >= CBSZ) return;
    const float* dg = deg + t*NN1;
    int* off = g_off + t*(NN1+1);
    int* cur = g_cur + t*NN1;
    int acc = 0;
    off[0] = 0;
    for (int i = 0; i < NN1; i++) {
        cur[i] = acc;
        acc += (int)dg[i] - 1;
        off[i+1] = acc;
    }
}

__global__ void k_scatter(const float* __restrict__ deg,
                          const int* __restrict__ ei,
                          const int* __restrict__ ea) {
    int t = blockIdx.x * blockDim.x + threadIdx.x;
    if (t >= BB*EE) return;
    int b = t >> 12, e = t & (EE-1);
    int src = ei[b*2*EE + e];
    int dst = ei[b*2*EE + EE + e];
    int a   = ea[b*EE + e];
    int cb  = a*BB + b;
    const float* dg = deg + cb*NN1;
    float coef = rsqrtf(dg[src]) * rsqrtf(dg[dst]);
    int pos = atomicAdd(&g_cur[cb*NN1 + dst], 1);
    g_esrc [cb*EE + pos] = src;
    g_ecoef[cb*EE + pos] = coef;
}

// transpose + fp16 convert with k padding: W [K][N] f32 -> Wt [N][KP] fp16
__global__ void k_th(const float* __restrict__ W, __half* __restrict__ Wt,
                     int K, int N, int KP) {
    const float* Wz  = W  + (size_t)blockIdx.z*K*N;
    __half*      Wtz = Wt + (size_t)blockIdx.z*N*KP;
    __shared__ float t[32][33];
    int k = blockIdx.x*32 + threadIdx.y;
    int n = blockIdx.y*32 + threadIdx.x;
    if (k < K && n < N) t[threadIdx.y][threadIdx.x] = Wz[(size_t)k*N + n];
    __syncthreads();
    int no = blockIdx.y*32 + threadIdx.y;
    int ko = blockIdx.x*32 + threadIdx.x;
    if (no < N && ko < KP)
        Wtz[(size_t)no*KP + ko] = (ko < K) ? __float2half_rn(t[threadIdx.x][threadIdx.y])
                                           : __half(0);
}

// ---------------------------------------------------------------------------
// Big fp16 GEMM, cp.async + LDSM: red = emb@W_red (+bias/relu/segmax).
// ---------------------------------------------------------------------------
#define KC    64
#define RA_LD 72
#define R_SZH (128*RA_LD)
#define RED_SMEM (4*R_SZH*2)

__global__ void __launch_bounds__(512, 1) k_mma_red(
    const __half* __restrict__ A,
    const __half* __restrict__ Bt,
    const float*  __restrict__ bias,
    const int*    __restrict__ entIdx,
    float*        __restrict__ x0)
{
    extern __shared__ __align__(16) __half smh[];
    __half* sAb[2] = { smh,            smh + R_SZH };
    __half* sBb[2] = { smh + 2*R_SZH,  smh + 3*R_SZH };

    const int tid  = threadIdx.x;
    const int lane = tid & 31;
    const int wid  = tid >> 5;
    const int gr   = lane >> 2;
    const int kq   = lane & 3;
    const int wm   = wid & 3;
    const int wn   = wid >> 2;
    const int row0 = blockIdx.y * 128;
    const int col0 = blockIdx.x * 128;

    const int sr = tid >> 2;
    const int sg = tid & 3;

    const int arow_l = ((lane >> 3) & 1)*8 + (lane & 7);
    const int acol_l = (lane >> 4)*8;
    const int brow_l = (lane >> 4)*8 + (lane & 7);
    const int bcol_l = ((lane >> 3) & 1)*8;
    uint32_t aoff[2], boff[2];
    #pragma unroll
    for (int mi = 0; mi < 2; mi++)
        aoff[mi] = ((wm*32 + mi*16 + arow_l)*RA_LD + acol_l)*2;
    #pragma unroll
    for (int pr = 0; pr < 2; pr++)
        boff[pr] = ((wn*32 + pr*16 + brow_l)*RA_LD + bcol_l)*2;
    uint32_t sAu[2] = { s2u(sAb[0]), s2u(sAb[1]) };
    uint32_t sBu[2] = { s2u(sBb[0]), s2u(sBb[1]) };

    float acc[2][4][4];
    #pragma unroll
    for (int i = 0; i < 2; i++)
        #pragma unroll
        for (int j = 0; j < 4; j++)
            #pragma unroll
            for (int u = 0; u < 4; u++) acc[i][j][u] = 0.f;

    const __half* agp = A  + (size_t)(row0 + sr)*ETRD + sg*16;
    const __half* bgp = Bt + (size_t)(col0 + sr)*ETRD + sg*16;
    const uint32_t sAoff = (sr*RA_LD + sg*16)*2;

    auto ldchunk = [&](int k0, int buf) {
        cp16(sAu[buf] + sAoff,      agp + k0);
        cp16(sAu[buf] + sAoff + 16, agp + k0 + 8);
        cp16(sBu[buf] + sAoff,      bgp + k0);
        cp16(sBu[buf] + sAoff + 16, bgp + k0 + 8);
        CP_COMMIT();
    };
    auto compute = [&](int buf) {
        #pragma unroll
        for (int ks = 0; ks < KC/16; ks++) {
            uint32_t af[2][4], bf[2][4];
            ldsm4(af[0], sAu[buf] + aoff[0] + ks*32);
            ldsm4(af[1], sAu[buf] + aoff[1] + ks*32);
            ldsm4(bf[0], sBu[buf] + boff[0] + ks*32);
            ldsm4(bf[1], sBu[buf] + boff[1] + ks*32);
            #pragma unroll
            for (int mi = 0; mi < 2; mi++) {
                mma_f16(acc[mi][0], af[mi], &bf[0][0]);
                mma_f16(acc[mi][1], af[mi], &bf[0][2]);
                mma_f16(acc[mi][2], af[mi], &bf[1][0]);
                mma_f16(acc[mi][3], af[mi], &bf[1][2]);
            }
        }
    };

    ldchunk(0, 0);
    CP_WAIT0();
    __syncthreads();
    #pragma unroll 1
    for (int ch = 0; ch < ETRD/KC; ch++) {
        if (ch + 1 < ETRD/KC) ldchunk((ch + 1)*KC, (ch + 1) & 1);
        compute(ch & 1);
        if (ch + 1 < ETRD/KC) {
            CP_WAIT0();
            __syncthreads();
        }
    }

    // Epilogue: fused bias + relu + segment-max scatter (predicated)
    int    nodev[2][2];
    float* basep[2][2];
    #pragma unroll
    for (int mi = 0; mi < 2; mi++)
        #pragma unroll
        for (int h = 0; h < 2; h++) {
            int r  = row0 + wm*32 + mi*16 + gr + h*8;
            int nd = entIdx[r];
            nodev[mi][h] = nd;
            int b = r >> 11;
            basep[mi][h] = x0 + ((size_t)(b*NN1 + nd))*DD + LDD;
        }
    #pragma unroll
    for (int ni = 0; ni < 4; ni++) {
        int c = col0 + wn*32 + ni*8 + kq*2;
        float b0 = __ldg(bias + c), b1 = __ldg(bias + c + 1);
        #pragma unroll
        for (int mi = 0; mi < 2; mi++) {
            #pragma unroll
            for (int h = 0; h < 2; h++) {
                if (nodev[mi][h] == 0) continue;
                float v0 = acc[mi][ni][2*h    ] + b0;
                float v1 = acc[mi][ni][2*h + 1] + b1;
                if (v0 > 0.f) atomicMax((int*)(basep[mi][h] + c),     __float_as_int(v0));
                if (v1 > 0.f) atomicMax((int*)(basep[mi][h] + c + 1), __float_as_int(v1));
            }
        }
    }
}

// ---------------------------------------------------------------------------
// xW GEMM, full cp.async + LDSM, 3 classes via grid.z: h_z = x_z @ W_z.
// Output now fp16 (stride DDP, pad unwritten/unread).
// ---------------------------------------------------------------------------
__global__ void __launch_bounds__(512, 1) k_mma_xw(
    const __half* __restrict__ Abase,  // + z*strideA
    const __half* __restrict__ Wg,     // + (z*NLAY+l)*DD*DDP
    __half*       __restrict__ Cbase,  // + z*MM*DDP, stride DDP
    int M, long long strideA, int layer)
{
    const int z = blockIdx.z;
    const __half* A  = Abase + (size_t)z*strideA;
    const __half* Bt = Wg + ((size_t)z*NLAY + layer)*DD*DDP;
    __half* C = Cbase + (size_t)z*MM*DDP;

    extern __shared__ __align__(16) __half smh[];
    __half* sAb[2] = { smh,            smh + R_SZH };
    __half* sBb[2] = { smh + 2*R_SZH,  smh + 3*R_SZH };

    const int tid  = threadIdx.x;
    const int lane = tid & 31;
    const int wid  = tid >> 5;
    const int gr   = lane >> 2;
    const int kq   = lane & 3;
    const int wm   = wid & 3;
    const int wn   = wid >> 2;
    const int row0 = blockIdx.y * 128;
    const int col0 = blockIdx.x * 128;

    const int sr = tid >> 2;
    const int sg = tid & 3;

    const int arow_l = ((lane >> 3) & 1)*8 + (lane & 7);
    const int acol_l = (lane >> 4)*8;
    const int brow_l = (lane >> 4)*8 + (lane & 7);
    const int bcol_l = ((lane >> 3) & 1)*8;
    uint32_t aoff[2], boff[2];
    #pragma unroll
    for (int mi = 0; mi < 2; mi++)
        aoff[mi] = ((wm*32 + mi*16 + arow_l)*RA_LD + acol_l)*2;
    #pragma unroll
    for (int pr = 0; pr < 2; pr++)
        boff[pr] = ((wn*32 + pr*16 + brow_l)*RA_LD + bcol_l)*2;
    uint32_t sAu[2] = { s2u(sAb[0]), s2u(sAb[1]) };
    uint32_t sBu[2] = { s2u(sBb[0]), s2u(sBb[1]) };

    float acc[2][4][4];
    #pragma unroll
    for (int i = 0; i < 2; i++)
        #pragma unroll
        for (int j = 0; j < 4; j++)
            #pragma unroll
            for (int u = 0; u < 4; u++) acc[i][j][u] = 0.f;

    int arow = row0 + sr; if (arow >= M)  arow = M - 1;
    int brow = col0 + sr; if (brow >= DD) brow = DD - 1;
    const __half* agp = A  + (size_t)arow*DDP + sg*16;
    const __half* bgp = Bt + (size_t)brow*DDP + sg*16;
    const uint32_t sAoff = (sr*RA_LD + sg*16)*2;

    auto ldchunk = [&](int k0, int buf) {
        cp16(sAu[buf] + sAoff,      agp + k0);
        cp16(sAu[buf] + sAoff + 16, agp + k0 + 8);
        cp16(sBu[buf] + sAoff,      bgp + k0);
        cp16(sBu[buf] + sAoff + 16, bgp + k0 + 8);
        CP_COMMIT();
    };
    auto compute = [&](int buf) {
        #pragma unroll
        for (int ks = 0; ks < KC/16; ks++) {
            uint32_t af[2][4], bf[2][4];
            ldsm4(af[0], sAu[buf] + aoff[0] + ks*32);
            ldsm4(af[1], sAu[buf] + aoff[1] + ks*32);
            ldsm4(bf[0], sBu[buf] + boff[0] + ks*32);
            ldsm4(bf[1], sBu[buf] + boff[1] + ks*32);
            #pragma unroll
            for (int mi = 0; mi < 2; mi++) {
                mma_f16(acc[mi][0], af[mi], &bf[0][0]);
                mma_f16(acc[mi][1], af[mi], &bf[0][2]);
                mma_f16(acc[mi][2], af[mi], &bf[1][0]);
                mma_f16(acc[mi][3], af[mi], &bf[1][2]);
            }
        }
    };

    ldchunk(0, 0);
    CP_WAIT0();
    __syncthreads();
    #pragma unroll 1
    for (int ch = 0; ch < DDP/KC; ch++) {      // 9 chunks, pad contributes 0
        if (ch + 1 < DDP/KC) ldchunk((ch + 1)*KC, (ch + 1) & 1);
        compute(ch & 1);
        if (ch + 1 < DDP/KC) {
            CP_WAIT0();
            __syncthreads();
        }
    }

    #pragma unroll
    for (int mi = 0; mi < 2; mi++) {
        #pragma unroll
        for (int h = 0; h < 2; h++) {
            int gm = row0 + wm*32 + mi*16 + gr + h*8;
            if (gm >= M) continue;
            #pragma unroll
            for (int ni = 0; ni < 4; ni++) {
                int gn = col0 + wn*32 + ni*8 + kq*2;
                if (gn < DD) {
                    *(uint32_t*)(C + (size_t)gm*DDP + gn) =
                        pack_h2(acc[mi][ni][2*h], acc[mi][ni][2*h + 1]);
                }
            }
        }
    }
}

// ---------------------------------------------------------------------------
// Sparse GCN aggregation, fp16 h input (vectorized half2), 3 classes grid.z.
// layer 0: fp16 k-padded output (pad zeroed); layer 1: fp32 output.
// ---------------------------------------------------------------------------
#define NH2 (DD/2)     // 264 half2 per row

__global__ void __launch_bounds__(256) k_spmm(
    const __half* __restrict__ hbase,
    float*  __restrict__ xbF,
    __half* __restrict__ xbH,
    const float* __restrict__ deg,
    const float* __restrict__ bgcn,
    int layer)
{
    int dst = blockIdx.x;
    int b   = blockIdx.y;
    int cls = blockIdx.z;
    int cb  = cls*BB + b;
    int tid = threadIdx.x;

    const float* bias = bgcn + (size_t)(cls*NLAY + layer)*DD;
    const __half* hb  = hbase + ((size_t)cls*MM + (size_t)b*NN1)*DDP;

    const int* off = g_off + cb*(NN1+1);
    int e0 = off[dst], e1 = off[dst+1];
    const int*   es = g_esrc  + cb*EE;
    const float* ec = g_ecoef + cb*EE;

    int j0 = tid, j1 = tid + 256;          // half2 indices, j < 264
    float2 a0 = {0.f, 0.f}, a1 = {0.f, 0.f};

    for (int e = e0; e < e1; e++) {
        int   src = es[e];
        float w   = ec[e];
        const __half2* hr = (const __half2*)(hb + (size_t)src*DDP);
        float2 x = __half22float2(hr[j0]);
        a0.x += w * x.x;
        a0.y += w * x.y;
        if (j1 < NH2) {
            float2 y = __half22float2(hr[j1]);
            a1.x += w * y.x;
            a1.y += w * y.y;
        }
    }

    float dinv = 1.f / deg[cb*NN1 + dst];
    const __half2* hd = (const __half2*)(hb + (size_t)dst*DDP);

    float2 s0 = __half22float2(hd[j0]);
    float v0x = a0.x + s0.x*dinv + bias[2*j0];
    float v0y = a0.y + s0.y*dinv + bias[2*j0 + 1];
    float v1x = 0.f, v1y = 0.f;
    if (j1 < NH2) {
        float2 s1 = __half22float2(hd[j1]);
        v1x = a1.x + s1.x*dinv + bias[2*j1];
        v1y = a1.y + s1.y*dinv + bias[2*j1 + 1];
    }

    if (layer == 0) {
        __half* xo = xbH + ((size_t)cls*MM + (size_t)b*NN1 + dst)*DDP;
        *(uint32_t*)(xo + 2*j0) = pack_h2(v0x, v0y);
        if (j1 < NH2) *(uint32_t*)(xo + 2*j1) = pack_h2(v1x, v1y);
        if (tid < (DDP - DD)/2)                   // zero pad cols [528,576)
            *(uint32_t*)(xo + DD + 2*tid) = 0u;
    } else {
        float* xo = xbF + ((size_t)cls*MM + (size_t)b*NN1 + dst)*DD;
        *(float2*)(xo + 2*j0) = make_float2(v0x, v0y);
        if (j1 < NH2) *(float2*)(xo + 2*j1) = make_float2(v1x, v1y);
    }
}

// ---------------------------------------------------------------------------
// Collapsed head/tail + logits
// ---------------------------------------------------------------------------
__global__ void k_ho(const float* __restrict__ W_head, const float* __restrict__ W_tail,
                     const float* __restrict__ W_out,
                     const float* __restrict__ b_head, const float* __restrict__ b_tail,
                     float* __restrict__ Who, float* __restrict__ Wto,
                     float* __restrict__ bho, float* __restrict__ bto) {
    int t = blockIdx.x * blockDim.x + threadIdx.x;
    if (t < 2*DD*3) {
        int which = t / (DD*3), rc = t % (DD*3), r = rc / 3, c = rc % 3;
        const float* W = which ? W_tail : W_head;
        float acc = 0.f;
        for (int j = 0; j < DD; j++) acc += W[r*DD + j] * W_out[j*3 + c];
        (which ? Wto : Who)[r*3 + c] = acc;
    } else if (t < 2*DD*3 + 6) {
        int u = t - 2*DD*3, which = u / 3, c = u % 3;
        const float* bb = which ? b_tail : b_head;
        float acc = 0.f;
        for (int j = 0; j < DD; j++) acc += bb[j] * W_out[j*3 + c];
        (which ? bto : bho)[c] = acc;
    }
}

__global__ void k_hw(const float* __restrict__ xbc,
                     const float* __restrict__ Who, const float* __restrict__ Wto,
                     const float* __restrict__ bho, const float* __restrict__ bto,
                     float* __restrict__ hW, float* __restrict__ hT) {
    int t = blockIdx.x * blockDim.x + threadIdx.x;
    if (t >= 2*BB*NN1*3) return;
    int which = t / (BB*NN1*3);
    int rem = t % (BB*NN1*3);
    int bi = rem / 3, c = rem % 3;
    const float* r0 = xbc + (size_t)bi*DD;
    const float* r1 = r0 + XSZ;
    const float* r2 = r1 + XSZ;
    const float* W  = which ? Wto : Who;
    float acc = 0.f;
    for (int k = 0; k < DD; k++) acc += (r0[k] + r1[k] + r2[k]) * W[k*3 + c];
    acc = acc * (1.f/3.f) + (which ? bto[c] : bho[c]);
    (which ? hT : hW)[bi*3 + c] = acc;
}

__global__ void k_logits(const int* __restrict__ cands,
                         const float* __restrict__ hW, const float* __restrict__ hT,
                         const float* __restrict__ b_out,
                         float* __restrict__ out) {
    int t = blockIdx.x * blockDim.x + threadIdx.x;
    const int TOT = BB*NN1*(NN1-1)*3;
    if (t >= TOT) return;
    int c = t % 3;
    int j = (t / 3) & 255;
    int i = (t / (3*256)) % NN1;
    int b = t / (3*256*NN1);
    int m = cands[((long long)(b*NN1 + i))*NN1 + j + 1];
    float v = b_out[c];
    if (m) v += hW[(b*NN1 + i)*3 + c] + hT[(b*NN1 + j + 1)*3 + c];
    out[t] = v;
}

// ---------------------------------------------------------------------------
// Launch
// ---------------------------------------------------------------------------
extern "C" void kernel_launch(void* const* d_in, const int* in_sizes, int n_in,
                              void* d_out, int out_size) {
    const float* emb     = (const float*)d_in[0];
    const int*   entIdx  = (const int*)  d_in[1];
    const int*   entLab  = (const int*)  d_in[2];
    const int*   edgeIdx = (const int*)  d_in[3];
    const int*   edgeAttr= (const int*)  d_in[4];
    const int*   cands   = (const int*)  d_in[5];
    const float* W_red   = (const float*)d_in[6];
    const float* b_red   = (const float*)d_in[7];
    const float* tbl     = (const float*)d_in[8];
    const float* W_gcn   = (const float*)d_in[9];
    const float* b_gcn   = (const float*)d_in[10];
    const float* W_head  = (const float*)d_in[11];
    const float* b_head  = (const float*)d_in[12];
    const float* W_tail  = (const float*)d_in[13];
    const float* b_tail  = (const float*)d_in[14];
    const float* W_out   = (const float*)d_in[15];
    const float* b_out   = (const float*)d_in[16];
    float* out = (float*)d_out;

    static float *px0=nullptr, *pxbc, *pdeg,
                 *pWho, *pWto, *pbho, *pbto, *phW, *phT;
    static __half *pWt, *pWg, *pEh, *px0h, *pxb16, *phc;
    static bool attr_set = false;
    if (!px0) {
        cudaGetSymbolAddress((void**)&px0,   g_x0);
        cudaGetSymbolAddress((void**)&px0h,  g_x0h);
        cudaGetSymbolAddress((void**)&phc,   g_hc);
        cudaGetSymbolAddress((void**)&pxb16, g_xb16);
        cudaGetSymbolAddress((void**)&pxbc,  g_xbc);
        cudaGetSymbolAddress((void**)&pdeg,  g_deg);
        cudaGetSymbolAddress((void**)&pWt,   g_Wt);
        cudaGetSymbolAddress((void**)&pWg,   g_Wg);
        cudaGetSymbolAddress((void**)&pEh,   g_embh);
        cudaGetSymbolAddress((void**)&pWho,  g_Who);
        cudaGetSymbolAddress((void**)&pWto,  g_Wto);
        cudaGetSymbolAddress((void**)&pbho,  g_bho);
        cudaGetSymbolAddress((void**)&pbto,  g_bto);
        cudaGetSymbolAddress((void**)&phW,   g_hW);
        cudaGetSymbolAddress((void**)&phT,   g_hT);
    }
    if (!attr_set) {
        cudaFuncSetAttribute(k_mma_red, cudaFuncAttributeMaxDynamicSharedMemorySize, RED_SMEM);
        cudaFuncSetAttribute(k_mma_xw,  cudaFuncAttributeMaxDynamicSharedMemorySize, RED_SMEM);
        attr_set = true;
    }

    auto blocks = [](int n) { return (n + 255) / 256; };

    // init + graph structure (CSR) + fp16 conversions
    k_initx0 <<<blocks(XSZ), 256>>>(px0, entLab, tbl);
    k_fill   <<<blocks(DEGSZ), 256>>>(pdeg, DEGSZ, 1.f);
    k_deg    <<<blocks(BB*EE), 256>>>(pdeg, edgeIdx, edgeAttr);
    k_off    <<<1, 64>>>(pdeg);
    k_scatter<<<blocks(BB*EE), 256>>>(pdeg, edgeIdx, edgeAttr);
    k_eh     <<<blocks(BB*SS*ETRD/4), 256>>>((const float4*)emb, (uint2*)pEh, BB*SS*ETRD/4);
    {
        dim3 bl(32, 32);
        k_th<<<dim3(ETRD/32, HH/32, 1), bl>>>(W_red, pWt, ETRD, HH, ETRD);
        k_th<<<dim3(DDP/32, (DD+31)/32, NCLS*NLAY), bl>>>(W_gcn, pWg, DD, DD, DDP);
    }

    // big GEMM (fp16 mma + LDSM + cp.async) + fused relu/segmax scatter
    {
        dim3 g(HH/128, (BB*SS)/128);   // (4, 256)
        k_mma_red<<<g, 512, RED_SMEM>>>(pEh, pWt, b_red, entIdx, px0);
    }
    // x0 -> fp16 k-padded mirror
    k_x0h<<<blocks(MM*DDP), 256>>>(px0, px0h);

    // GCN: 2 layers, all 3 classes per launch, fp16 h throughout
    {
        dim3 gx((DD + 127)/128, (MM + 127)/128, NCLS);   // (5, 33, 3)
        dim3 gs(NN1, BB, NCLS);
        k_mma_xw<<<gx, 512, RED_SMEM>>>(px0h, pWg, phc, MM, 0LL, 0);
        k_spmm  <<<gs, 256>>>(phc, nullptr, pxb16, pdeg, b_gcn, 0);
        k_mma_xw<<<gx, 512, RED_SMEM>>>(pxb16, pWg, phc, MM, (long long)MM*DDP, 1);
        k_spmm  <<<gs, 256>>>(phc, pxbc, nullptr, pdeg, b_gcn, 1);
    }

    // collapsed head/tail + logits
    k_ho<<<blocks(2*DD*3 + 6), 256>>>(W_head, W_tail, W_out, b_head, b_tail,
                                      pWho, pWto, pbho, pbto);
    k_hw<<<blocks(2*BB*NN1*3), 256>>>(pxbc, pWho, pWto, pbho, pbto, phW, phT);
    k_logits<<<blocks(BB*NN1*(NN1-1)*3), 256>>>(cands, phW, phT, b_out, out);
}

// round 12
// speedup vs baseline: 3.4370x; 1.0319x over previous
#include <cuda_runtime.h>
#include <cuda_fp16.h>
#include <cstdint>

// ---------------------------------------------------------------------------
// Problem constants
// ---------------------------------------------------------------------------
#define BB    16
#define SS    2048
#define NN1   257
#define EE    4096
#define HH    512
#define LDD   16
#define ETRD  768
#define DD    528
#define DDP   576          // k-padded stride for fp16 activations/weights
#define NCLS  3
#define NLAY  2

#define MM    (BB*NN1)     // 4112 rows
#define XSZ   (BB*NN1*DD)
#define DEGSZ (NCLS*BB*NN1)
#define CBSZ  (NCLS*BB)

// ---------------------------------------------------------------------------
// Device scratch
// ---------------------------------------------------------------------------
__device__ float  g_x0 [XSZ];
__device__ __half g_x0h[MM*DDP];           // x0 fp16, k-padded
__device__ __half g_hc [NCLS*MM*DDP];      // h per class, fp16 (pad unread)
__device__ __half g_xb16[NCLS*MM*DDP];     // layer-0 output, fp16 k-padded
__device__ float  g_xbc[NCLS*XSZ];         // layer-1 output (fp32, for k_hw)
__device__ float  g_deg[DEGSZ];
__device__ int    g_off[CBSZ*(NN1+1)];
__device__ int    g_cur[CBSZ*NN1];
__device__ int    g_esrc[CBSZ*EE];
__device__ float  g_ecoef[CBSZ*EE];
__device__ __half g_embh[BB*SS*ETRD];      // emb fp16
__device__ __half g_Wt [HH*ETRD];          // W_red^T (n-major) fp16
__device__ __half g_Wg [NCLS*NLAY*DD*DDP]; // W_gcn^T per (c,l), n-major, k-padded fp16
__device__ float  g_Who[DD*3];
__device__ float  g_Wto[DD*3];
__device__ float  g_bho[3];
__device__ float  g_bto[3];
__device__ float  g_hW [BB*NN1*3];
__device__ float  g_hT [BB*NN1*3];

// ---------------------------------------------------------------------------
// mma / ldmatrix / cp.async helpers (generic PTX, OK for compute_103)
// ---------------------------------------------------------------------------
__device__ __forceinline__ void mma_f16(float* c, const uint32_t* a, const uint32_t* b) {
    asm volatile(
        "mma.sync.aligned.m16n8k16.row.col.f32.f16.f16.f32 "
        "{%0,%1,%2,%3}, {%4,%5,%6,%7}, {%8,%9}, {%0,%1,%2,%3};"
        : "+f"(c[0]), "+f"(c[1]), "+f"(c[2]), "+f"(c[3])
        : "r"(a[0]), "r"(a[1]), "r"(a[2]), "r"(a[3]), "r"(b[0]), "r"(b[1]));
}

__device__ __forceinline__ void ldsm4(uint32_t* r, uint32_t saddr) {
    asm volatile("ldmatrix.sync.aligned.m8n8.x4.shared.b16 {%0,%1,%2,%3}, [%4];"
                 : "=r"(r[0]), "=r"(r[1]), "=r"(r[2]), "=r"(r[3]) : "r"(saddr));
}

__device__ __forceinline__ uint32_t s2u(const void* p) {
    return (uint32_t)__cvta_generic_to_shared(p);
}

__device__ __forceinline__ void cp16(uint32_t s, const void* g) {
    asm volatile("cp.async.cg.shared.global [%0], [%1], 16;" :: "r"(s), "l"(g));
}
#define CP_COMMIT() asm volatile("cp.async.commit_group;" ::: "memory")
#define CP_WAIT0()  asm volatile("cp.async.wait_group 0;"  ::: "memory")

__device__ __forceinline__ uint32_t pack_h2(float x, float y) {
    __half2 h = __floats2half2_rn(x, y);
    return *(uint32_t*)&h;
}

// ---------------------------------------------------------------------------
// Small helper kernels
// ---------------------------------------------------------------------------

// x0 init (zeros + label part) + deg init (1.0f) in one pass
__global__ void k_initx0(float* __restrict__ x0,
                         float* __restrict__ deg,
                         const int* __restrict__ entLab,
                         const float* __restrict__ tbl) {
    int t = blockIdx.x * blockDim.x + threadIdx.x;
    if (t < DEGSZ) deg[t] = 1.f;
    if (t >= XSZ) return;
    int r = t / DD, c = t % DD;
    float v = 0.f;
    if (c < LDD) {
        int i = r % NN1, b = r / NN1;
        if (i == 0) v = tbl[c];
        else {
            int lbl = entLab[b*(NN1-1) + i - 1];
            v = lbl ? tbl[lbl*LDD + c] : 0.f;
        }
    }
    x0[t] = v;
}

// fp32 -> fp16 bulk convert (float4 -> uint2)
__global__ void k_eh(const float4* __restrict__ in, uint2* __restrict__ outp, int n4) {
    int i = blockIdx.x * blockDim.x + threadIdx.x;
    if (i < n4) {
        float4 v = in[i];
        uint2 u;
        u.x = pack_h2(v.x, v.y);
        u.y = pack_h2(v.z, v.w);
        outp[i] = u;
    }
}

// x0 fp32 [MM][DD] -> x0h fp16 [MM][DDP] with zero pad
__global__ void k_x0h(const float* __restrict__ x0, __half* __restrict__ x0h) {
    int t = blockIdx.x * blockDim.x + threadIdx.x;
    if (t >= MM*DDP) return;
    int r = t / DDP, c = t % DDP;
    x0h[t] = (c < DD) ? __float2half_rn(x0[(size_t)r*DD + c]) : __half(0);
}

__global__ void k_deg(float* __restrict__ deg,
                      const int* __restrict__ ei,
                      const int* __restrict__ ea) {
    int t = blockIdx.x * blockDim.x + threadIdx.x;
    if (t >= BB*EE) return;
    int b = t >> 12, e = t & (EE-1);
    int dst = ei[b*2*EE + EE + e];
    int a   = ea[b*EE + e];
    atomicAdd(&deg[(a*BB + b)*NN1 + dst], 1.f);
}

// CSR offsets + cursors: one warp per (class,batch), shfl inclusive scan
__global__ void k_off(const float* __restrict__ deg) {
    int cb   = blockIdx.x;
    int lane = threadIdx.x;
    const float* dg = deg + cb*NN1;
    int* off = g_off + cb*(NN1+1);
    int* cur = g_cur + cb*NN1;
    if (lane == 0) off[0] = 0;
    int carry = 0;
    for (int base = 0; base < NN1; base += 32) {
        int i = base + lane;
        int v = (i < NN1) ? (int)dg[i] - 1 : 0;
        int s = v;
        #pragma unroll
        for (int d = 1; d < 32; d <<= 1) {
            int t = __shfl_up_sync(0xffffffffu, s, d);
            if (lane >= d) s += t;
        }
        if (i < NN1) {
            cur[i]   = carry + s - v;    // exclusive
            off[i+1] = carry + s;        // inclusive
        }
        carry += __shfl_sync(0xffffffffu, s, 31);
    }
}

__global__ void k_scatter(const float* __restrict__ deg,
                          const int* __restrict__ ei,
                          const int* __restrict__ ea) {
    int t = blockIdx.x * blockDim.x + threadIdx.x;
    if (t >= BB*EE) return;
    int b = t >> 12, e = t & (EE-1);
    int src = ei[b*2*EE + e];
    int dst = ei[b*2*EE + EE + e];
    int a   = ea[b*EE + e];
    int cb  = a*BB + b;
    const float* dg = deg + cb*NN1;
    float coef = rsqrtf(dg[src]) * rsqrtf(dg[dst]);
    int pos = atomicAdd(&g_cur[cb*NN1 + dst], 1);
    g_esrc [cb*EE + pos] = src;
    g_ecoef[cb*EE + pos] = coef;
}

// transpose + fp16 convert with k padding: W [K][N] f32 -> Wt [N][KP] fp16
__global__ void k_th(const float* __restrict__ W, __half* __restrict__ Wt,
                     int K, int N, int KP) {
    const float* Wz  = W  + (size_t)blockIdx.z*K*N;
    __half*      Wtz = Wt + (size_t)blockIdx.z*N*KP;
    __shared__ float t[32][33];
    int k = blockIdx.x*32 + threadIdx.y;
    int n = blockIdx.y*32 + threadIdx.x;
    if (k < K && n < N) t[threadIdx.y][threadIdx.x] = Wz[(size_t)k*N + n];
    __syncthreads();
    int no = blockIdx.y*32 + threadIdx.y;
    int ko = blockIdx.x*32 + threadIdx.x;
    if (no < N && ko < KP)
        Wtz[(size_t)no*KP + ko] = (ko < K) ? __float2half_rn(t[threadIdx.x][threadIdx.y])
                                           : __half(0);
}

// ---------------------------------------------------------------------------
// Big fp16 GEMM, cp.async + LDSM: red = emb@W_red (+bias/relu/segmax).
// ---------------------------------------------------------------------------
#define KC    64
#define RA_LD 72
#define R_SZH (128*RA_LD)
#define RED_SMEM (4*R_SZH*2)

__global__ void __launch_bounds__(512, 1) k_mma_red(
    const __half* __restrict__ A,
    const __half* __restrict__ Bt,
    const float*  __restrict__ bias,
    const int*    __restrict__ entIdx,
    float*        __restrict__ x0)
{
    extern __shared__ __align__(16) __half smh[];
    __half* sAb[2] = { smh,            smh + R_SZH };
    __half* sBb[2] = { smh + 2*R_SZH,  smh + 3*R_SZH };

    const int tid  = threadIdx.x;
    const int lane = tid & 31;
    const int wid  = tid >> 5;
    const int gr   = lane >> 2;
    const int kq   = lane & 3;
    const int wm   = wid & 3;
    const int wn   = wid >> 2;
    const int row0 = blockIdx.y * 128;
    const int col0 = blockIdx.x * 128;

    const int sr = tid >> 2;
    const int sg = tid & 3;

    const int arow_l = ((lane >> 3) & 1)*8 + (lane & 7);
    const int acol_l = (lane >> 4)*8;
    const int brow_l = (lane >> 4)*8 + (lane & 7);
    const int bcol_l = ((lane >> 3) & 1)*8;
    uint32_t aoff[2], boff[2];
    #pragma unroll
    for (int mi = 0; mi < 2; mi++)
        aoff[mi] = ((wm*32 + mi*16 + arow_l)*RA_LD + acol_l)*2;
    #pragma unroll
    for (int pr = 0; pr < 2; pr++)
        boff[pr] = ((wn*32 + pr*16 + brow_l)*RA_LD + bcol_l)*2;
    uint32_t sAu[2] = { s2u(sAb[0]), s2u(sAb[1]) };
    uint32_t sBu[2] = { s2u(sBb[0]), s2u(sBb[1]) };

    float acc[2][4][4];
    #pragma unroll
    for (int i = 0; i < 2; i++)
        #pragma unroll
        for (int j = 0; j < 4; j++)
            #pragma unroll
            for (int u = 0; u < 4; u++) acc[i][j][u] = 0.f;

    const __half* agp = A  + (size_t)(row0 + sr)*ETRD + sg*16;
    const __half* bgp = Bt + (size_t)(col0 + sr)*ETRD + sg*16;
    const uint32_t sAoff = (sr*RA_LD + sg*16)*2;

    auto ldchunk = [&](int k0, int buf) {
        cp16(sAu[buf] + sAoff,      agp + k0);
        cp16(sAu[buf] + sAoff + 16, agp + k0 + 8);
        cp16(sBu[buf] + sAoff,      bgp + k0);
        cp16(sBu[buf] + sAoff + 16, bgp + k0 + 8);
        CP_COMMIT();
    };
    auto compute = [&](int buf) {
        #pragma unroll
        for (int ks = 0; ks < KC/16; ks++) {
            uint32_t af[2][4], bf[2][4];
            ldsm4(af[0], sAu[buf] + aoff[0] + ks*32);
            ldsm4(af[1], sAu[buf] + aoff[1] + ks*32);
            ldsm4(bf[0], sBu[buf] + boff[0] + ks*32);
            ldsm4(bf[1], sBu[buf] + boff[1] + ks*32);
            #pragma unroll
            for (int mi = 0; mi < 2; mi++) {
                mma_f16(acc[mi][0], af[mi], &bf[0][0]);
                mma_f16(acc[mi][1], af[mi], &bf[0][2]);
                mma_f16(acc[mi][2], af[mi], &bf[1][0]);
                mma_f16(acc[mi][3], af[mi], &bf[1][2]);
            }
        }
    };

    ldchunk(0, 0);
    CP_WAIT0();
    __syncthreads();
    #pragma unroll 1
    for (int ch = 0; ch < ETRD/KC; ch++) {
        if (ch + 1 < ETRD/KC) ldchunk((ch + 1)*KC, (ch + 1) & 1);
        compute(ch & 1);
        if (ch + 1 < ETRD/KC) {
            CP_WAIT0();
            __syncthreads();
        }
    }

    // Epilogue: fused bias + relu + segment-max scatter (predicated)
    int    nodev[2][2];
    float* basep[2][2];
    #pragma unroll
    for (int mi = 0; mi < 2; mi++)
        #pragma unroll
        for (int h = 0; h < 2; h++) {
            int r  = row0 + wm*32 + mi*16 + gr + h*8;
            int nd = entIdx[r];
            nodev[mi][h] = nd;
            int b = r >> 11;
            basep[mi][h] = x0 + ((size_t)(b*NN1 + nd))*DD + LDD;
        }
    #pragma unroll
    for (int ni = 0; ni < 4; ni++) {
        int c = col0 + wn*32 + ni*8 + kq*2;
        float b0 = __ldg(bias + c), b1 = __ldg(bias + c + 1);
        #pragma unroll
        for (int mi = 0; mi < 2; mi++) {
            #pragma unroll
            for (int h = 0; h < 2; h++) {
                if (nodev[mi][h] == 0) continue;
                float v0 = acc[mi][ni][2*h    ] + b0;
                float v1 = acc[mi][ni][2*h + 1] + b1;
                if (v0 > 0.f) atomicMax((int*)(basep[mi][h] + c),     __float_as_int(v0));
                if (v1 > 0.f) atomicMax((int*)(basep[mi][h] + c + 1), __float_as_int(v1));
            }
        }
    }
}

// ---------------------------------------------------------------------------
// xW GEMM, full cp.async + LDSM, 3 classes via grid.z: h_z = x_z @ W_z.
// fp16 in / fp16 out (stride DDP).
// ---------------------------------------------------------------------------
__global__ void __launch_bounds__(512, 1) k_mma_xw(
    const __half* __restrict__ Abase,
    const __half* __restrict__ Wg,
    __half*       __restrict__ Cbase,
    int M, long long strideA, int layer)
{
    const int z = blockIdx.z;
    const __half* A  = Abase + (size_t)z*strideA;
    const __half* Bt = Wg + ((size_t)z*NLAY + layer)*DD*DDP;
    __half* C = Cbase + (size_t)z*MM*DDP;

    extern __shared__ __align__(16) __half smh[];
    __half* sAb[2] = { smh,            smh + R_SZH };
    __half* sBb[2] = { smh + 2*R_SZH,  smh + 3*R_SZH };

    const int tid  = threadIdx.x;
    const int lane = tid & 31;
    const int wid  = tid >> 5;
    const int gr   = lane >> 2;
    const int kq   = lane & 3;
    const int wm   = wid & 3;
    const int wn   = wid >> 2;
    const int row0 = blockIdx.y * 128;
    const int col0 = blockIdx.x * 128;

    const int sr = tid >> 2;
    const int sg = tid & 3;

    const int arow_l = ((lane >> 3) & 1)*8 + (lane & 7);
    const int acol_l = (lane >> 4)*8;
    const int brow_l = (lane >> 4)*8 + (lane & 7);
    const int bcol_l = ((lane >> 3) & 1)*8;
    uint32_t aoff[2], boff[2];
    #pragma unroll
    for (int mi = 0; mi < 2; mi++)
        aoff[mi] = ((wm*32 + mi*16 + arow_l)*RA_LD + acol_l)*2;
    #pragma unroll
    for (int pr = 0; pr < 2; pr++)
        boff[pr] = ((wn*32 + pr*16 + brow_l)*RA_LD + bcol_l)*2;
    uint32_t sAu[2] = { s2u(sAb[0]), s2u(sAb[1]) };
    uint32_t sBu[2] = { s2u(sBb[0]), s2u(sBb[1]) };

    float acc[2][4][4];
    #pragma unroll
    for (int i = 0; i < 2; i++)
        #pragma unroll
        for (int j = 0; j < 4; j++)
            #pragma unroll
            for (int u = 0; u < 4; u++) acc[i][j][u] = 0.f;

    int arow = row0 + sr; if (arow >= M)  arow = M - 1;
    int brow = col0 + sr; if (brow >= DD) brow = DD - 1;
    const __half* agp = A  + (size_t)arow*DDP + sg*16;
    const __half* bgp = Bt + (size_t)brow*DDP + sg*16;
    const uint32_t sAoff = (sr*RA_LD + sg*16)*2;

    auto ldchunk = [&](int k0, int buf) {
        cp16(sAu[buf] + sAoff,      agp + k0);
        cp16(sAu[buf] + sAoff + 16, agp + k0 + 8);
        cp16(sBu[buf] + sAoff,      bgp + k0);
        cp16(sBu[buf] + sAoff + 16, bgp + k0 + 8);
        CP_COMMIT();
    };
    auto compute = [&](int buf) {
        #pragma unroll
        for (int ks = 0; ks < KC/16; ks++) {
            uint32_t af[2][4], bf[2][4];
            ldsm4(af[0], sAu[buf] + aoff[0] + ks*32);
            ldsm4(af[1], sAu[buf] + aoff[1] + ks*32);
            ldsm4(bf[0], sBu[buf] + boff[0] + ks*32);
            ldsm4(bf[1], sBu[buf] + boff[1] + ks*32);
            #pragma unroll
            for (int mi = 0; mi < 2; mi++) {
                mma_f16(acc[mi][0], af[mi], &bf[0][0]);
                mma_f16(acc[mi][1], af[mi], &bf[0][2]);
                mma_f16(acc[mi][2], af[mi], &bf[1][0]);
                mma_f16(acc[mi][3], af[mi], &bf[1][2]);
            }
        }
    };

    ldchunk(0, 0);
    CP_WAIT0();
    __syncthreads();
    #pragma unroll 1
    for (int ch = 0; ch < DDP/KC; ch++) {      // 9 chunks
        if (ch + 1 < DDP/KC) ldchunk((ch + 1)*KC, (ch + 1) & 1);
        compute(ch & 1);
        if (ch + 1 < DDP/KC) {
            CP_WAIT0();
            __syncthreads();
        }
    }

    #pragma unroll
    for (int mi = 0; mi < 2; mi++) {
        #pragma unroll
        for (int h = 0; h < 2; h++) {
            int gm = row0 + wm*32 + mi*16 + gr + h*8;
            if (gm >= M) continue;
            #pragma unroll
            for (int ni = 0; ni < 4; ni++) {
                int gn = col0 + wn*32 + ni*8 + kq*2;
                if (gn < DD) {
                    *(uint32_t*)(C + (size_t)gm*DDP + gn) =
                        pack_h2(acc[mi][ni][2*h], acc[mi][ni][2*h + 1]);
                }
            }
        }
    }
}

// ---------------------------------------------------------------------------
// Sparse GCN aggregation, fp16 h input (half2), 3 classes grid.z.
// ---------------------------------------------------------------------------
#define NH2 (DD/2)     // 264 half2 per row

__global__ void __launch_bounds__(256) k_spmm(
    const __half* __restrict__ hbase,
    float*  __restrict__ xbF,
    __half* __restrict__ xbH,
    const float* __restrict__ deg,
    const float* __restrict__ bgcn,
    int layer)
{
    int dst = blockIdx.x;
    int b   = blockIdx.y;
    int cls = blockIdx.z;
    int cb  = cls*BB + b;
    int tid = threadIdx.x;

    const float* bias = bgcn + (size_t)(cls*NLAY + layer)*DD;
    const __half* hb  = hbase + ((size_t)cls*MM + (size_t)b*NN1)*DDP;

    const int* off = g_off + cb*(NN1+1);
    int e0 = off[dst], e1 = off[dst+1];
    const int*   es = g_esrc  + cb*EE;
    const float* ec = g_ecoef + cb*EE;

    int j0 = tid, j1 = tid + 256;
    float2 a0 = {0.f, 0.f}, a1 = {0.f, 0.f};

    for (int e = e0; e < e1; e++) {
        int   src = es[e];
        float w   = ec[e];
        const __half2* hr = (const __half2*)(hb + (size_t)src*DDP);
        float2 x = __half22float2(hr[j0]);
        a0.x += w * x.x;
        a0.y += w * x.y;
        if (j1 < NH2) {
            float2 y = __half22float2(hr[j1]);
            a1.x += w * y.x;
            a1.y += w * y.y;
        }
    }

    float dinv = 1.f / deg[cb*NN1 + dst];
    const __half2* hd = (const __half2*)(hb + (size_t)dst*DDP);

    float2 s0 = __half22float2(hd[j0]);
    float v0x = a0.x + s0.x*dinv + bias[2*j0];
    float v0y = a0.y + s0.y*dinv + bias[2*j0 + 1];
    float v1x = 0.f, v1y = 0.f;
    if (j1 < NH2) {
        float2 s1 = __half22float2(hd[j1]);
        v1x = a1.x + s1.x*dinv + bias[2*j1];
        v1y = a1.y + s1.y*dinv + bias[2*j1 + 1];
    }

    if (layer == 0) {
        __half* xo = xbH + ((size_t)cls*MM + (size_t)b*NN1 + dst)*DDP;
        *(uint32_t*)(xo + 2*j0) = pack_h2(v0x, v0y);
        if (j1 < NH2) *(uint32_t*)(xo + 2*j1) = pack_h2(v1x, v1y);
        if (tid < (DDP - DD)/2)
            *(uint32_t*)(xo + DD + 2*tid) = 0u;
    } else {
        float* xo = xbF + ((size_t)cls*MM + (size_t)b*NN1 + dst)*DD;
        *(float2*)(xo + 2*j0) = make_float2(v0x, v0y);
        if (j1 < NH2) *(float2*)(xo + 2*j1) = make_float2(v1x, v1y);
    }
}

// ---------------------------------------------------------------------------
// Collapsed head/tail + logits
// ---------------------------------------------------------------------------
__global__ void k_ho(const float* __restrict__ W_head, const float* __restrict__ W_tail,
                     const float* __restrict__ W_out,
                     const float* __restrict__ b_head, const float* __restrict__ b_tail,
                     float* __restrict__ Who, float* __restrict__ Wto,
                     float* __restrict__ bho, float* __restrict__ bto) {
    int t = blockIdx.x * blockDim.x + threadIdx.x;
    if (t < 2*DD*3) {
        int which = t / (DD*3), rc = t % (DD*3), r = rc / 3, c = rc % 3;
        const float* W = which ? W_tail : W_head;
        float acc = 0.f;
        for (int j = 0; j < DD; j++) acc += W[r*DD + j] * W_out[j*3 + c];
        (which ? Wto : Who)[r*3 + c] = acc;
    } else if (t < 2*DD*3 + 6) {
        int u = t - 2*DD*3, which = u / 3, c = u % 3;
        const float* bb = which ? b_tail : b_head;
        float acc = 0.f;
        for (int j = 0; j < DD; j++) acc += bb[j] * W_out[j*3 + c];
        (which ? bto : bho)[c] = acc;
    }
}

__global__ void k_hw(const float* __restrict__ xbc,
                     const float* __restrict__ Who, const float* __restrict__ Wto,
                     const float* __restrict__ bho, const float* __restrict__ bto,
                     float* __restrict__ hW, float* __restrict__ hT) {
    int t = blockIdx.x * blockDim.x + threadIdx.x;
    if (t >= 2*BB*NN1*3) return;
    int which = t / (BB*NN1*3);
    int rem = t % (BB*NN1*3);
    int bi = rem / 3, c = rem % 3;
    const float* r0 = xbc + (size_t)bi*DD;
    const float* r1 = r0 + XSZ;
    const float* r2 = r1 + XSZ;
    const float* W  = which ? Wto : Who;
    float acc = 0.f;
    for (int k = 0; k < DD; k++) acc += (r0[k] + r1[k] + r2[k]) * W[k*3 + c];
    acc = acc * (1.f/3.f) + (which ? bto[c] : bho[c]);
    (which ? hT : hW)[bi*3 + c] = acc;
}

__global__ void k_logits(const int* __restrict__ cands,
                         const float* __restrict__ hW, const float* __restrict__ hT,
                         const float* __restrict__ b_out,
                         float* __restrict__ out) {
    int t = blockIdx.x * blockDim.x + threadIdx.x;
    const int TOT = BB*NN1*(NN1-1)*3;
    if (t >= TOT) return;
    int c = t % 3;
    int j = (t / 3) & 255;
    int i = (t / (3*256)) % NN1;
    int b = t / (3*256*NN1);
    int m = cands[((long long)(b*NN1 + i))*NN1 + j + 1];
    float v = b_out[c];
    if (m) v += hW[(b*NN1 + i)*3 + c] + hT[(b*NN1 + j + 1)*3 + c];
    out[t] = v;
}

// ---------------------------------------------------------------------------
// Launch
// ---------------------------------------------------------------------------
extern "C" void kernel_launch(void* const* d_in, const int* in_sizes, int n_in,
                              void* d_out, int out_size) {
    const float* emb     = (const float*)d_in[0];
    const int*   entIdx  = (const int*)  d_in[1];
    const int*   entLab  = (const int*)  d_in[2];
    const int*   edgeIdx = (const int*)  d_in[3];
    const int*   edgeAttr= (const int*)  d_in[4];
    const int*   cands   = (const int*)  d_in[5];
    const float* W_red   = (const float*)d_in[6];
    const float* b_red   = (const float*)d_in[7];
    const float* tbl     = (const float*)d_in[8];
    const float* W_gcn   = (const float*)d_in[9];
    const float* b_gcn   = (const float*)d_in[10];
    const float* W_head  = (const float*)d_in[11];
    const float* b_head  = (const float*)d_in[12];
    const float* W_tail  = (const float*)d_in[13];
    const float* b_tail  = (const float*)d_in[14];
    const float* W_out   = (const float*)d_in[15];
    const float* b_out   = (const float*)d_in[16];
    float* out = (float*)d_out;

    static float *px0=nullptr, *pxbc, *pdeg,
                 *pWho, *pWto, *pbho, *pbto, *phW, *phT;
    static __half *pWt, *pWg, *pEh, *px0h, *pxb16, *phc;
    static bool attr_set = false;
    if (!px0) {
        cudaGetSymbolAddress((void**)&px0,   g_x0);
        cudaGetSymbolAddress((void**)&px0h,  g_x0h);
        cudaGetSymbolAddress((void**)&phc,   g_hc);
        cudaGetSymbolAddress((void**)&pxb16, g_xb16);
        cudaGetSymbolAddress((void**)&pxbc,  g_xbc);
        cudaGetSymbolAddress((void**)&pdeg,  g_deg);
        cudaGetSymbolAddress((void**)&pWt,   g_Wt);
        cudaGetSymbolAddress((void**)&pWg,   g_Wg);
        cudaGetSymbolAddress((void**)&pEh,   g_embh);
        cudaGetSymbolAddress((void**)&pWho,  g_Who);
        cudaGetSymbolAddress((void**)&pWto,  g_Wto);
        cudaGetSymbolAddress((void**)&pbho,  g_bho);
        cudaGetSymbolAddress((void**)&pbto,  g_bto);
        cudaGetSymbolAddress((void**)&phW,   g_hW);
        cudaGetSymbolAddress((void**)&phT,   g_hT);
    }
    if (!attr_set) {
        cudaFuncSetAttribute(k_mma_red, cudaFuncAttributeMaxDynamicSharedMemorySize, RED_SMEM);
        cudaFuncSetAttribute(k_mma_xw,  cudaFuncAttributeMaxDynamicSharedMemorySize, RED_SMEM);
        attr_set = true;
    }

    auto blocks = [](int n) { return (n + 255) / 256; };

    // init + graph structure (CSR) + fp16 conversions
    k_initx0 <<<blocks(XSZ), 256>>>(px0, pdeg, entLab, tbl);
    k_deg    <<<blocks(BB*EE), 256>>>(pdeg, edgeIdx, edgeAttr);
    k_off    <<<CBSZ, 32>>>(pdeg);
    k_scatter<<<blocks(BB*EE), 256>>>(pdeg, edgeIdx, edgeAttr);
    k_eh     <<<blocks(BB*SS*ETRD/4), 256>>>((const float4*)emb, (uint2*)pEh, BB*SS*ETRD/4);
    {
        dim3 bl(32, 32);
        k_th<<<dim3(ETRD/32, HH/32, 1), bl>>>(W_red, pWt, ETRD, HH, ETRD);
        k_th<<<dim3(DDP/32, (DD+31)/32, NCLS*NLAY), bl>>>(W_gcn, pWg, DD, DD, DDP);
    }

    // big GEMM (fp16 mma + LDSM + cp.async) + fused relu/segmax scatter
    {
        dim3 g(HH/128, (BB*SS)/128);   // (4, 256)
        k_mma_red<<<g, 512, RED_SMEM>>>(pEh, pWt, b_red, entIdx, px0);
    }
    // x0 -> fp16 k-padded mirror
    k_x0h<<<blocks(MM*DDP), 256>>>(px0, px0h);

    // GCN: 2 layers, all 3 classes per launch, fp16 h throughout
    {
        dim3 gx((DD + 127)/128, (MM + 127)/128, NCLS);   // (5, 33, 3)
        dim3 gs(NN1, BB, NCLS);
        k_mma_xw<<<gx, 512, RED_SMEM>>>(px0h, pWg, phc, MM, 0LL, 0);
        k_spmm  <<<gs, 256>>>(phc, nullptr, pxb16, pdeg, b_gcn, 0);
        k_mma_xw<<<gx, 512, RED_SMEM>>>(pxb16, pWg, phc, MM, (long long)MM*DDP, 1);
        k_spmm  <<<gs, 256>>>(phc, pxbc, nullptr, pdeg, b_gcn, 1);
    }

    // collapsed head/tail + logits
    k_ho<<<blocks(2*DD*3 + 6), 256>>>(W_head, W_tail, W_out, b_head, b_tail,
                                      pWho, pWto, pbho, pbto);
    k_hw<<<blocks(2*BB*NN1*3), 256>>>(pxbc, pWho, pWto, pbho, pbto, phW, phT);
    k_logits<<<blocks(BB*NN1*(NN1-1)*3), 256>>>(cands, phW, phT, b_out, out);
}

// round 13
// speedup vs baseline: 3.6549x; 1.0634x over previous
#include <cuda_runtime.h>
#include <cuda_fp16.h>
#include <cstdint>

// ---------------------------------------------------------------------------
// Problem constants
// ---------------------------------------------------------------------------
#define BB    16
#define SS    2048
#define NN1   257
#define EE    4096
#define HH    512
#define LDD   16
#define ETRD  768
#define DD    528
#define DDP   576          // k-padded stride for fp16 activations/weights
#define NCLS  3
#define NLAY  2

#define MM    (BB*NN1)     // 4112 rows
#define XSZ   (BB*NN1*DD)
#define DEGSZ (NCLS*BB*NN1)
#define CBSZ  (NCLS*BB)
#define HWSZ  (BB*NN1*3)

// ---------------------------------------------------------------------------
// Device scratch
// ---------------------------------------------------------------------------
__device__ float  g_x0 [XSZ];
__device__ __half g_x0h[MM*DDP];           // x0 fp16, k-padded
__device__ __half g_hc [NCLS*MM*DDP];      // h per class, fp16 (pad unread)
__device__ __half g_xb16[NCLS*MM*DDP];     // layer-0 output, fp16 k-padded
__device__ float  g_deg[DEGSZ];
__device__ int    g_off[CBSZ*(NN1+1)];
__device__ int    g_cur[CBSZ*NN1];
__device__ int    g_esrc[CBSZ*EE];
__device__ float  g_ecoef[CBSZ*EE];
__device__ __half g_embh[BB*SS*ETRD];      // emb fp16
__device__ __half g_Wt [HH*ETRD];          // W_red^T (n-major) fp16
__device__ __half g_Wg [NCLS*NLAY*DD*DDP]; // W_gcn^T per (c,l), n-major, k-padded fp16
__device__ float  g_Who[DD*3];
__device__ float  g_Wto[DD*3];
__device__ float  g_bho[3];
__device__ float  g_bto[3];
__device__ float  g_hW [HWSZ];
__device__ float  g_hT [HWSZ];

// ---------------------------------------------------------------------------
// mma / ldmatrix / cp.async helpers (generic PTX, OK for compute_103)
// ---------------------------------------------------------------------------
__device__ __forceinline__ void mma_f16(float* c, const uint32_t* a, const uint32_t* b) {
    asm volatile(
        "mma.sync.aligned.m16n8k16.row.col.f32.f16.f16.f32 "
        "{%0,%1,%2,%3}, {%4,%5,%6,%7}, {%8,%9}, {%0,%1,%2,%3};"
        : "+f"(c[0]), "+f"(c[1]), "+f"(c[2]), "+f"(c[3])
        : "r"(a[0]), "r"(a[1]), "r"(a[2]), "r"(a[3]), "r"(b[0]), "r"(b[1]));
}

__device__ __forceinline__ void ldsm4(uint32_t* r, uint32_t saddr) {
    asm volatile("ldmatrix.sync.aligned.m8n8.x4.shared.b16 {%0,%1,%2,%3}, [%4];"
                 : "=r"(r[0]), "=r"(r[1]), "=r"(r[2]), "=r"(r[3]) : "r"(saddr));
}

__device__ __forceinline__ uint32_t s2u(const void* p) {
    return (uint32_t)__cvta_generic_to_shared(p);
}

__device__ __forceinline__ void cp16(uint32_t s, const void* g) {
    asm volatile("cp.async.cg.shared.global [%0], [%1], 16;" :: "r"(s), "l"(g));
}
#define CP_COMMIT() asm volatile("cp.async.commit_group;" ::: "memory")
#define CP_WAIT0()  asm volatile("cp.async.wait_group 0;"  ::: "memory")

__device__ __forceinline__ uint32_t pack_h2(float x, float y) {
    __half2 h = __floats2half2_rn(x, y);
    return *(uint32_t*)&h;
}

// ---------------------------------------------------------------------------
// Small helper kernels
// ---------------------------------------------------------------------------

// x0 init (zeros + label part) + deg init + hW/hT zero, one pass
__global__ void k_initx0(float* __restrict__ x0,
                         float* __restrict__ deg,
                         float* __restrict__ hW,
                         float* __restrict__ hT,
                         const int* __restrict__ entLab,
                         const float* __restrict__ tbl) {
    int t = blockIdx.x * blockDim.x + threadIdx.x;
    if (t < DEGSZ) deg[t] = 1.f;
    if (t < HWSZ) { hW[t] = 0.f; hT[t] = 0.f; }
    if (t >= XSZ) return;
    int r = t / DD, c = t % DD;
    float v = 0.f;
    if (c < LDD) {
        int i = r % NN1, b = r / NN1;
        if (i == 0) v = tbl[c];
        else {
            int lbl = entLab[b*(NN1-1) + i - 1];
            v = lbl ? tbl[lbl*LDD + c] : 0.f;
        }
    }
    x0[t] = v;
}

// fp32 -> fp16 bulk convert (float4 -> uint2)
__global__ void k_eh(const float4* __restrict__ in, uint2* __restrict__ outp, int n4) {
    int i = blockIdx.x * blockDim.x + threadIdx.x;
    if (i < n4) {
        float4 v = in[i];
        uint2 u;
        u.x = pack_h2(v.x, v.y);
        u.y = pack_h2(v.z, v.w);
        outp[i] = u;
    }
}

// x0 fp32 [MM][DD] -> x0h fp16 [MM][DDP] with zero pad
__global__ void k_x0h(const float* __restrict__ x0, __half* __restrict__ x0h) {
    int t = blockIdx.x * blockDim.x + threadIdx.x;
    if (t >= MM*DDP) return;
    int r = t / DDP, c = t % DDP;
    x0h[t] = (c < DD) ? __float2half_rn(x0[(size_t)r*DD + c]) : __half(0);
}

__global__ void k_deg(float* __restrict__ deg,
                      const int* __restrict__ ei,
                      const int* __restrict__ ea) {
    int t = blockIdx.x * blockDim.x + threadIdx.x;
    if (t >= BB*EE) return;
    int b = t >> 12, e = t & (EE-1);
    int dst = ei[b*2*EE + EE + e];
    int a   = ea[b*EE + e];
    atomicAdd(&deg[(a*BB + b)*NN1 + dst], 1.f);
}

// CSR offsets + cursors: one warp per (class,batch), shfl inclusive scan
__global__ void k_off(const float* __restrict__ deg) {
    int cb   = blockIdx.x;
    int lane = threadIdx.x;
    const float* dg = deg + cb*NN1;
    int* off = g_off + cb*(NN1+1);
    int* cur = g_cur + cb*NN1;
    if (lane == 0) off[0] = 0;
    int carry = 0;
    for (int base = 0; base < NN1; base += 32) {
        int i = base + lane;
        int v = (i < NN1) ? (int)dg[i] - 1 : 0;
        int s = v;
        #pragma unroll
        for (int d = 1; d < 32; d <<= 1) {
            int t = __shfl_up_sync(0xffffffffu, s, d);
            if (lane >= d) s += t;
        }
        if (i < NN1) {
            cur[i]   = carry + s - v;
            off[i+1] = carry + s;
        }
        carry += __shfl_sync(0xffffffffu, s, 31);
    }
}

__global__ void k_scatter(const float* __restrict__ deg,
                          const int* __restrict__ ei,
                          const int* __restrict__ ea) {
    int t = blockIdx.x * blockDim.x + threadIdx.x;
    if (t >= BB*EE) return;
    int b = t >> 12, e = t & (EE-1);
    int src = ei[b*2*EE + e];
    int dst = ei[b*2*EE + EE + e];
    int a   = ea[b*EE + e];
    int cb  = a*BB + b;
    const float* dg = deg + cb*NN1;
    float coef = rsqrtf(dg[src]) * rsqrtf(dg[dst]);
    int pos = atomicAdd(&g_cur[cb*NN1 + dst], 1);
    g_esrc [cb*EE + pos] = src;
    g_ecoef[cb*EE + pos] = coef;
}

// transpose + fp16 convert with k padding: W [K][N] f32 -> Wt [N][KP] fp16
__global__ void k_th(const float* __restrict__ W, __half* __restrict__ Wt,
                     int K, int N, int KP) {
    const float* Wz  = W  + (size_t)blockIdx.z*K*N;
    __half*      Wtz = Wt + (size_t)blockIdx.z*N*KP;
    __shared__ float t[32][33];
    int k = blockIdx.x*32 + threadIdx.y;
    int n = blockIdx.y*32 + threadIdx.x;
    if (k < K && n < N) t[threadIdx.y][threadIdx.x] = Wz[(size_t)k*N + n];
    __syncthreads();
    int no = blockIdx.y*32 + threadIdx.y;
    int ko = blockIdx.x*32 + threadIdx.x;
    if (no < N && ko < KP)
        Wtz[(size_t)no*KP + ko] = (ko < K) ? __float2half_rn(t[threadIdx.x][threadIdx.y])
                                           : __half(0);
}

// ---------------------------------------------------------------------------
// Big fp16 GEMM, cp.async + LDSM: red = emb@W_red (+bias/relu/segmax).
// ---------------------------------------------------------------------------
#define KC    64
#define RA_LD 72
#define R_SZH (128*RA_LD)
#define RED_SMEM (4*R_SZH*2)

__global__ void __launch_bounds__(512, 1) k_mma_red(
    const __half* __restrict__ A,
    const __half* __restrict__ Bt,
    const float*  __restrict__ bias,
    const int*    __restrict__ entIdx,
    float*        __restrict__ x0)
{
    extern __shared__ __align__(16) __half smh[];
    __half* sAb[2] = { smh,            smh + R_SZH };
    __half* sBb[2] = { smh + 2*R_SZH,  smh + 3*R_SZH };

    const int tid  = threadIdx.x;
    const int lane = tid & 31;
    const int wid  = tid >> 5;
    const int gr   = lane >> 2;
    const int kq   = lane & 3;
    const int wm   = wid & 3;
    const int wn   = wid >> 2;
    const int row0 = blockIdx.y * 128;
    const int col0 = blockIdx.x * 128;

    const int sr = tid >> 2;
    const int sg = tid & 3;

    const int arow_l = ((lane >> 3) & 1)*8 + (lane & 7);
    const int acol_l = (lane >> 4)*8;
    const int brow_l = (lane >> 4)*8 + (lane & 7);
    const int bcol_l = ((lane >> 3) & 1)*8;
    uint32_t aoff[2], boff[2];
    #pragma unroll
    for (int mi = 0; mi < 2; mi++)
        aoff[mi] = ((wm*32 + mi*16 + arow_l)*RA_LD + acol_l)*2;
    #pragma unroll
    for (int pr = 0; pr < 2; pr++)
        boff[pr] = ((wn*32 + pr*16 + brow_l)*RA_LD + bcol_l)*2;
    uint32_t sAu[2] = { s2u(sAb[0]), s2u(sAb[1]) };
    uint32_t sBu[2] = { s2u(sBb[0]), s2u(sBb[1]) };

    float acc[2][4][4];
    #pragma unroll
    for (int i = 0; i < 2; i++)
        #pragma unroll
        for (int j = 0; j < 4; j++)
            #pragma unroll
            for (int u = 0; u < 4; u++) acc[i][j][u] = 0.f;

    const __half* agp = A  + (size_t)(row0 + sr)*ETRD + sg*16;
    const __half* bgp = Bt + (size_t)(col0 + sr)*ETRD + sg*16;
    const uint32_t sAoff = (sr*RA_LD + sg*16)*2;

    auto ldchunk = [&](int k0, int buf) {
        cp16(sAu[buf] + sAoff,      agp + k0);
        cp16(sAu[buf] + sAoff + 16, agp + k0 + 8);
        cp16(sBu[buf] + sAoff,      bgp + k0);
        cp16(sBu[buf] + sAoff + 16, bgp + k0 + 8);
        CP_COMMIT();
    };
    auto compute = [&](int buf) {
        #pragma unroll
        for (int ks = 0; ks < KC/16; ks++) {
            uint32_t af[2][4], bf[2][4];
            ldsm4(af[0], sAu[buf] + aoff[0] + ks*32);
            ldsm4(af[1], sAu[buf] + aoff[1] + ks*32);
            ldsm4(bf[0], sBu[buf] + boff[0] + ks*32);
            ldsm4(bf[1], sBu[buf] + boff[1] + ks*32);
            #pragma unroll
            for (int mi = 0; mi < 2; mi++) {
                mma_f16(acc[mi][0], af[mi], &bf[0][0]);
                mma_f16(acc[mi][1], af[mi], &bf[0][2]);
                mma_f16(acc[mi][2], af[mi], &bf[1][0]);
                mma_f16(acc[mi][3], af[mi], &bf[1][2]);
            }
        }
    };

    ldchunk(0, 0);
    CP_WAIT0();
    __syncthreads();
    #pragma unroll 1
    for (int ch = 0; ch < ETRD/KC; ch++) {
        if (ch + 1 < ETRD/KC) ldchunk((ch + 1)*KC, (ch + 1) & 1);
        compute(ch & 1);
        if (ch + 1 < ETRD/KC) {
            CP_WAIT0();
            __syncthreads();
        }
    }

    // Epilogue: fused bias + relu + segment-max scatter (predicated)
    int    nodev[2][2];
    float* basep[2][2];
    #pragma unroll
    for (int mi = 0; mi < 2; mi++)
        #pragma unroll
        for (int h = 0; h < 2; h++) {
            int r  = row0 + wm*32 + mi*16 + gr + h*8;
            int nd = entIdx[r];
            nodev[mi][h] = nd;
            int b = r >> 11;
            basep[mi][h] = x0 + ((size_t)(b*NN1 + nd))*DD + LDD;
        }
    #pragma unroll
    for (int ni = 0; ni < 4; ni++) {
        int c = col0 + wn*32 + ni*8 + kq*2;
        float b0 = __ldg(bias + c), b1 = __ldg(bias + c + 1);
        #pragma unroll
        for (int mi = 0; mi < 2; mi++) {
            #pragma unroll
            for (int h = 0; h < 2; h++) {
                if (nodev[mi][h] == 0) continue;
                float v0 = acc[mi][ni][2*h    ] + b0;
                float v1 = acc[mi][ni][2*h + 1] + b1;
                if (v0 > 0.f) atomicMax((int*)(basep[mi][h] + c),     __float_as_int(v0));
                if (v1 > 0.f) atomicMax((int*)(basep[mi][h] + c + 1), __float_as_int(v1));
            }
        }
    }
}

// ---------------------------------------------------------------------------
// xW GEMM, full cp.async + LDSM, 3 classes via grid.z: h_z = x_z @ W_z.
// fp16 in / fp16 out (stride DDP).
// ---------------------------------------------------------------------------
__global__ void __launch_bounds__(512, 1) k_mma_xw(
    const __half* __restrict__ Abase,
    const __half* __restrict__ Wg,
    __half*       __restrict__ Cbase,
    int M, long long strideA, int layer)
{
    const int z = blockIdx.z;
    const __half* A  = Abase + (size_t)z*strideA;
    const __half* Bt = Wg + ((size_t)z*NLAY + layer)*DD*DDP;
    __half* C = Cbase + (size_t)z*MM*DDP;

    extern __shared__ __align__(16) __half smh[];
    __half* sAb[2] = { smh,            smh + R_SZH };
    __half* sBb[2] = { smh + 2*R_SZH,  smh + 3*R_SZH };

    const int tid  = threadIdx.x;
    const int lane = tid & 31;
    const int wid  = tid >> 5;
    const int gr   = lane >> 2;
    const int kq   = lane & 3;
    const int wm   = wid & 3;
    const int wn   = wid >> 2;
    const int row0 = blockIdx.y * 128;
    const int col0 = blockIdx.x * 128;

    const int sr = tid >> 2;
    const int sg = tid & 3;

    const int arow_l = ((lane >> 3) & 1)*8 + (lane & 7);
    const int acol_l = (lane >> 4)*8;
    const int brow_l = (lane >> 4)*8 + (lane & 7);
    const int bcol_l = ((lane >> 3) & 1)*8;
    uint32_t aoff[2], boff[2];
    #pragma unroll
    for (int mi = 0; mi < 2; mi++)
        aoff[mi] = ((wm*32 + mi*16 + arow_l)*RA_LD + acol_l)*2;
    #pragma unroll
    for (int pr = 0; pr < 2; pr++)
        boff[pr] = ((wn*32 + pr*16 + brow_l)*RA_LD + bcol_l)*2;
    uint32_t sAu[2] = { s2u(sAb[0]), s2u(sAb[1]) };
    uint32_t sBu[2] = { s2u(sBb[0]), s2u(sBb[1]) };

    float acc[2][4][4];
    #pragma unroll
    for (int i = 0; i < 2; i++)
        #pragma unroll
        for (int j = 0; j < 4; j++)
            #pragma unroll
            for (int u = 0; u < 4; u++) acc[i][j][u] = 0.f;

    int arow = row0 + sr; if (arow >= M)  arow = M - 1;
    int brow = col0 + sr; if (brow >= DD) brow = DD - 1;
    const __half* agp = A  + (size_t)arow*DDP + sg*16;
    const __half* bgp = Bt + (size_t)brow*DDP + sg*16;
    const uint32_t sAoff = (sr*RA_LD + sg*16)*2;

    auto ldchunk = [&](int k0, int buf) {
        cp16(sAu[buf] + sAoff,      agp + k0);
        cp16(sAu[buf] + sAoff + 16, agp + k0 + 8);
        cp16(sBu[buf] + sAoff,      bgp + k0);
        cp16(sBu[buf] + sAoff + 16, bgp + k0 + 8);
        CP_COMMIT();
    };
    auto compute = [&](int buf) {
        #pragma unroll
        for (int ks = 0; ks < KC/16; ks++) {
            uint32_t af[2][4], bf[2][4];
            ldsm4(af[0], sAu[buf] + aoff[0] + ks*32);
            ldsm4(af[1], sAu[buf] + aoff[1] + ks*32);
            ldsm4(bf[0], sBu[buf] + boff[0] + ks*32);
            ldsm4(bf[1], sBu[buf] + boff[1] + ks*32);
            #pragma unroll
            for (int mi = 0; mi < 2; mi++) {
                mma_f16(acc[mi][0], af[mi], &bf[0][0]);
                mma_f16(acc[mi][1], af[mi], &bf[0][2]);
                mma_f16(acc[mi][2], af[mi], &bf[1][0]);
                mma_f16(acc[mi][3], af[mi], &bf[1][2]);
            }
        }
    };

    ldchunk(0, 0);
    CP_WAIT0();
    __syncthreads();
    #pragma unroll 1
    for (int ch = 0; ch < DDP/KC; ch++) {      // 9 chunks
        if (ch + 1 < DDP/KC) ldchunk((ch + 1)*KC, (ch + 1) & 1);
        compute(ch & 1);
        if (ch + 1 < DDP/KC) {
            CP_WAIT0();
            __syncthreads();
        }
    }

    #pragma unroll
    for (int mi = 0; mi < 2; mi++) {
        #pragma unroll
        for (int h = 0; h < 2; h++) {
            int gm = row0 + wm*32 + mi*16 + gr + h*8;
            if (gm >= M) continue;
            #pragma unroll
            for (int ni = 0; ni < 4; ni++) {
                int gn = col0 + wn*32 + ni*8 + kq*2;
                if (gn < DD) {
                    *(uint32_t*)(C + (size_t)gm*DDP + gn) =
                        pack_h2(acc[mi][ni][2*h], acc[mi][ni][2*h + 1]);
                }
            }
        }
    }
}

// ---------------------------------------------------------------------------
// Sparse GCN aggregation, fp16 h input (half2), 3 classes grid.z.
// layer 0: fp16 k-padded output.
// layer 1: FUSED head/tail projection — no xb buffer; block-reduces
//          v·Who[:,c], v·Wto[:,c] and atomicAdds (1/3-scaled) into hW/hT.
// ---------------------------------------------------------------------------
#define NH2 (DD/2)     // 264 half2 per row

__global__ void __launch_bounds__(256) k_spmm(
    const __half* __restrict__ hbase,
    __half* __restrict__ xbH,
    const float* __restrict__ deg,
    const float* __restrict__ bgcn,
    const float* __restrict__ Who,
    const float* __restrict__ Wto,
    float* __restrict__ hW,
    float* __restrict__ hT,
    int layer)
{
    int dst = blockIdx.x;
    int b   = blockIdx.y;
    int cls = blockIdx.z;
    int cb  = cls*BB + b;
    int tid = threadIdx.x;

    const float* bias = bgcn + (size_t)(cls*NLAY + layer)*DD;
    const __half* hb  = hbase + ((size_t)cls*MM + (size_t)b*NN1)*DDP;

    const int* off = g_off + cb*(NN1+1);
    int e0 = off[dst], e1 = off[dst+1];
    const int*   es = g_esrc  + cb*EE;
    const float* ec = g_ecoef + cb*EE;

    int j0 = tid, j1 = tid + 256;
    float2 a0 = {0.f, 0.f}, a1 = {0.f, 0.f};

    for (int e = e0; e < e1; e++) {
        int   src = es[e];
        float w   = ec[e];
        const __half2* hr = (const __half2*)(hb + (size_t)src*DDP);
        float2 x = __half22float2(hr[j0]);
        a0.x += w * x.x;
        a0.y += w * x.y;
        if (j1 < NH2) {
            float2 y = __half22float2(hr[j1]);
            a1.x += w * y.x;
            a1.y += w * y.y;
        }
    }

    float dinv = 1.f / deg[cb*NN1 + dst];
    const __half2* hd = (const __half2*)(hb + (size_t)dst*DDP);

    float2 s0 = __half22float2(hd[j0]);
    float v0x = a0.x + s0.x*dinv + bias[2*j0];
    float v0y = a0.y + s0.y*dinv + bias[2*j0 + 1];
    float v1x = 0.f, v1y = 0.f;
    if (j1 < NH2) {
        float2 s1 = __half22float2(hd[j1]);
        v1x = a1.x + s1.x*dinv + bias[2*j1];
        v1y = a1.y + s1.y*dinv + bias[2*j1 + 1];
    }

    if (layer == 0) {
        __half* xo = xbH + ((size_t)cls*MM + (size_t)b*NN1 + dst)*DDP;
        *(uint32_t*)(xo + 2*j0) = pack_h2(v0x, v0y);
        if (j1 < NH2) *(uint32_t*)(xo + 2*j1) = pack_h2(v1x, v1y);
        if (tid < (DDP - DD)/2)
            *(uint32_t*)(xo + DD + 2*tid) = 0u;
        return;
    }

    // layer 1: fused projection. Per-thread partials over its 2 (or 4) cols.
    float lw[3], lt[3];
    #pragma unroll
    for (int c = 0; c < 3; c++) {
        float w = v0x*Who[(2*j0)*3 + c] + v0y*Who[(2*j0 + 1)*3 + c];
        float t = v0x*Wto[(2*j0)*3 + c] + v0y*Wto[(2*j0 + 1)*3 + c];
        if (j1 < NH2) {
            w += v1x*Who[(2*j1)*3 + c] + v1y*Who[(2*j1 + 1)*3 + c];
            t += v1x*Wto[(2*j1)*3 + c] + v1y*Wto[(2*j1 + 1)*3 + c];
        }
        lw[c] = w;
        lt[c] = t;
    }
    // warp reduce
    #pragma unroll
    for (int d = 16; d > 0; d >>= 1) {
        #pragma unroll
        for (int c = 0; c < 3; c++) {
            lw[c] += __shfl_down_sync(0xffffffffu, lw[c], d);
            lt[c] += __shfl_down_sync(0xffffffffu, lt[c], d);
        }
    }
    __shared__ float sred[8][6];
    int warp = tid >> 5, lane = tid & 31;
    if (lane == 0) {
        #pragma unroll
        for (int c = 0; c < 3; c++) {
            sred[warp][c]     = lw[c];
            sred[warp][3 + c] = lt[c];
        }
    }
    __syncthreads();
    if (tid == 0) {
        float sw[3] = {0.f, 0.f, 0.f}, st[3] = {0.f, 0.f, 0.f};
        #pragma unroll
        for (int wgi = 0; wgi < 8; wgi++)
            #pragma unroll
            for (int c = 0; c < 3; c++) {
                sw[c] += sred[wgi][c];
                st[c] += sred[wgi][3 + c];
            }
        int idx = (b*NN1 + dst)*3;
        #pragma unroll
        for (int c = 0; c < 3; c++) {
            atomicAdd(&hW[idx + c], sw[c] * (1.f/3.f));
            atomicAdd(&hT[idx + c], st[c] * (1.f/3.f));
        }
    }
}

// ---------------------------------------------------------------------------
// Collapsed head/tail weights (prep phase)
// ---------------------------------------------------------------------------
__global__ void k_ho(const float* __restrict__ W_head, const float* __restrict__ W_tail,
                     const float* __restrict__ W_out,
                     const float* __restrict__ b_head, const float* __restrict__ b_tail,
                     float* __restrict__ Who, float* __restrict__ Wto,
                     float* __restrict__ bho, float* __restrict__ bto) {
    int t = blockIdx.x * blockDim.x + threadIdx.x;
    if (t < 2*DD*3) {
        int which = t / (DD*3), rc = t % (DD*3), r = rc / 3, c = rc % 3;
        const float* W = which ? W_tail : W_head;
        float acc = 0.f;
        for (int j = 0; j < DD; j++) acc += W[r*DD + j] * W_out[j*3 + c];
        (which ? Wto : Who)[r*3 + c] = acc;
    } else if (t < 2*DD*3 + 6) {
        int u = t - 2*DD*3, which = u / 3, c = u % 3;
        const float* bb = which ? b_tail : b_head;
        float acc = 0.f;
        for (int j = 0; j < DD; j++) acc += bb[j] * W_out[j*3 + c];
        (which ? bto : bho)[c] = acc;
    }
}

// logits: hW/hT are bias-free accumulations; bho/bto added here
__global__ void k_logits(const int* __restrict__ cands,
                         const float* __restrict__ hW, const float* __restrict__ hT,
                         const float* __restrict__ bho, const float* __restrict__ bto,
                         const float* __restrict__ b_out,
                         float* __restrict__ out) {
    int t = blockIdx.x * blockDim.x + threadIdx.x;
    const int TOT = BB*NN1*(NN1-1)*3;
    if (t >= TOT) return;
    int c = t % 3;
    int j = (t / 3) & 255;
    int i = (t / (3*256)) % NN1;
    int b = t / (3*256*NN1);
    int m = cands[((long long)(b*NN1 + i))*NN1 + j + 1];
    float v = b_out[c];
    if (m) v += hW[(b*NN1 + i)*3 + c] + bho[c] + hT[(b*NN1 + j + 1)*3 + c] + bto[c];
    out[t] = v;
}

// ---------------------------------------------------------------------------
// Launch
// ---------------------------------------------------------------------------
extern "C" void kernel_launch(void* const* d_in, const int* in_sizes, int n_in,
                              void* d_out, int out_size) {
    const float* emb     = (const float*)d_in[0];
    const int*   entIdx  = (const int*)  d_in[1];
    const int*   entLab  = (const int*)  d_in[2];
    const int*   edgeIdx = (const int*)  d_in[3];
    const int*   edgeAttr= (const int*)  d_in[4];
    const int*   cands   = (const int*)  d_in[5];
    const float* W_red   = (const float*)d_in[6];
    const float* b_red   = (const float*)d_in[7];
    const float* tbl     = (const float*)d_in[8];
    const float* W_gcn   = (const float*)d_in[9];
    const float* b_gcn   = (const float*)d_in[10];
    const float* W_head  = (const float*)d_in[11];
    const float* b_head  = (const float*)d_in[12];
    const float* W_tail  = (const float*)d_in[13];
    const float* b_tail  = (const float*)d_in[14];
    const float* W_out   = (const float*)d_in[15];
    const float* b_out   = (const float*)d_in[16];
    float* out = (float*)d_out;

    static float *px0=nullptr, *pdeg,
                 *pWho, *pWto, *pbho, *pbto, *phW, *phT;
    static __half *pWt, *pWg, *pEh, *px0h, *pxb16, *phc;
    static bool attr_set = false;
    if (!px0) {
        cudaGetSymbolAddress((void**)&px0,   g_x0);
        cudaGetSymbolAddress((void**)&px0h,  g_x0h);
        cudaGetSymbolAddress((void**)&phc,   g_hc);
        cudaGetSymbolAddress((void**)&pxb16, g_xb16);
        cudaGetSymbolAddress((void**)&pdeg,  g_deg);
        cudaGetSymbolAddress((void**)&pWt,   g_Wt);
        cudaGetSymbolAddress((void**)&pWg,   g_Wg);
        cudaGetSymbolAddress((void**)&pEh,   g_embh);
        cudaGetSymbolAddress((void**)&pWho,  g_Who);
        cudaGetSymbolAddress((void**)&pWto,  g_Wto);
        cudaGetSymbolAddress((void**)&pbho,  g_bho);
        cudaGetSymbolAddress((void**)&pbto,  g_bto);
        cudaGetSymbolAddress((void**)&phW,   g_hW);
        cudaGetSymbolAddress((void**)&phT,   g_hT);
    }
    if (!attr_set) {
        cudaFuncSetAttribute(k_mma_red, cudaFuncAttributeMaxDynamicSharedMemorySize, RED_SMEM);
        cudaFuncSetAttribute(k_mma_xw,  cudaFuncAttributeMaxDynamicSharedMemorySize, RED_SMEM);
        attr_set = true;
    }

    auto blocks = [](int n) { return (n + 255) / 256; };

    // init + graph structure (CSR) + fp16 conversions + collapsed head/tail
    k_initx0 <<<blocks(XSZ), 256>>>(px0, pdeg, phW, phT, entLab, tbl);
    k_deg    <<<blocks(BB*EE), 256>>>(pdeg, edgeIdx, edgeAttr);
    k_off    <<<CBSZ, 32>>>(pdeg);
    k_scatter<<<blocks(BB*EE), 256>>>(pdeg, edgeIdx, edgeAttr);
    k_eh     <<<blocks(BB*SS*ETRD/4), 256>>>((const float4*)emb, (uint2*)pEh, BB*SS*ETRD/4);
    {
        dim3 bl(32, 32);
        k_th<<<dim3(ETRD/32, HH/32, 1), bl>>>(W_red, pWt, ETRD, HH, ETRD);
        k_th<<<dim3(DDP/32, (DD+31)/32, NCLS*NLAY), bl>>>(W_gcn, pWg, DD, DD, DDP);
    }
    k_ho<<<blocks(2*DD*3 + 6), 256>>>(W_head, W_tail, W_out, b_head, b_tail,
                                      pWho, pWto, pbho, pbto);

    // big GEMM (fp16 mma + LDSM + cp.async) + fused relu/segmax scatter
    {
        dim3 g(HH/128, (BB*SS)/128);   // (4, 256)
        k_mma_red<<<g, 512, RED_SMEM>>>(pEh, pWt, b_red, entIdx, px0);
    }
    // x0 -> fp16 k-padded mirror
    k_x0h<<<blocks(MM*DDP), 256>>>(px0, px0h);

    // GCN: 2 layers, all 3 classes per launch; layer 1 fuses head/tail proj
    {
        dim3 gx((DD + 127)/128, (MM + 127)/128, NCLS);   // (5, 33, 3)
        dim3 gs(NN1, BB, NCLS);
        k_mma_xw<<<gx, 512, RED_SMEM>>>(px0h, pWg, phc, MM, 0LL, 0);
        k_spmm  <<<gs, 256>>>(phc, pxb16, pdeg, b_gcn, pWho, pWto, phW, phT, 0);
        k_mma_xw<<<gx, 512, RED_SMEM>>>(pxb16, pWg, phc, MM, (long long)MM*DDP, 1);
        k_spmm  <<<gs, 256>>>(phc, nullptr, pdeg, b_gcn, pWho, pWto, phW, phT, 1);
    }

    // logits
    k_logits<<<blocks(BB*NN1*(NN1-1)*3), 256>>>(cands, phW, phT, pbho, pbto, b_out, out);
}

// round 14
// speedup vs baseline: 3.7543x; 1.0272x over previous
#include <cuda_runtime.h>
#include <cuda_fp16.h>
#include <cstdint>

// ---------------------------------------------------------------------------
// Problem constants
// ---------------------------------------------------------------------------
#define BB    16
#define SS    2048
#define NN1   257
#define EE    4096
#define HH    512
#define LDD   16
#define ETRD  768
#define DD    528
#define DDP   576
#define NCLS  3
#define NLAY  2

#define MM    (BB*NN1)
#define XSZ   (BB*NN1*DD)
#define DEGSZ (NCLS*BB*NN1)
#define CBSZ  (NCLS*BB)
#define HWSZ  (BB*NN1*3)

// ---------------------------------------------------------------------------
// Device scratch
// ---------------------------------------------------------------------------
__device__ float  g_x0 [XSZ];
__device__ __half g_x0h[MM*DDP];
__device__ __half g_hc [NCLS*MM*DDP];
__device__ __half g_xb16[NCLS*MM*DDP];
__device__ float  g_deg[DEGSZ];
__device__ int    g_off[CBSZ*(NN1+1)];
__device__ int    g_cur[CBSZ*NN1];
__device__ int    g_esrc[CBSZ*EE];
__device__ float  g_ecoef[CBSZ*EE];
__device__ __half g_embh[BB*SS*ETRD];
__device__ __half g_Wt [HH*ETRD];
__device__ __half g_Wg [NCLS*NLAY*DD*DDP];
__device__ float  g_Who[DD*3];
__device__ float  g_Wto[DD*3];
__device__ float  g_bho[3];
__device__ float  g_bto[3];
__device__ float  g_hW [HWSZ];
__device__ float  g_hT [HWSZ];

// ---------------------------------------------------------------------------
// mma / ldmatrix / cp.async helpers
// ---------------------------------------------------------------------------
__device__ __forceinline__ void mma_f16(float* c, const uint32_t* a, const uint32_t* b) {
    asm volatile(
        "mma.sync.aligned.m16n8k16.row.col.f32.f16.f16.f32 "
        "{%0,%1,%2,%3}, {%4,%5,%6,%7}, {%8,%9}, {%0,%1,%2,%3};"
        : "+f"(c[0]), "+f"(c[1]), "+f"(c[2]), "+f"(c[3])
        : "r"(a[0]), "r"(a[1]), "r"(a[2]), "r"(a[3]), "r"(b[0]), "r"(b[1]));
}

__device__ __forceinline__ void ldsm4(uint32_t* r, uint32_t saddr) {
    asm volatile("ldmatrix.sync.aligned.m8n8.x4.shared.b16 {%0,%1,%2,%3}, [%4];"
                 : "=r"(r[0]), "=r"(r[1]), "=r"(r[2]), "=r"(r[3]) : "r"(saddr));
}

__device__ __forceinline__ uint32_t s2u(const void* p) {
    return (uint32_t)__cvta_generic_to_shared(p);
}

__device__ __forceinline__ void cp16(uint32_t s, const void* g) {
    asm volatile("cp.async.cg.shared.global [%0], [%1], 16;" :: "r"(s), "l"(g));
}
#define CP_COMMIT() asm volatile("cp.async.commit_group;" ::: "memory")
#define CP_WAIT0()  asm volatile("cp.async.wait_group 0;"  ::: "memory")

__device__ __forceinline__ uint32_t pack_h2(float x, float y) {
    __half2 h = __floats2half2_rn(x, y);
    return *(uint32_t*)&h;
}

// ---------------------------------------------------------------------------
// Small helper kernels
// ---------------------------------------------------------------------------

// deg=1, hW=0, hT=0 (head of CSR side chain)
__global__ void k_initmisc(float* __restrict__ deg,
                           float* __restrict__ hW,
                           float* __restrict__ hT) {
    int t = blockIdx.x * blockDim.x + threadIdx.x;
    if (t < DEGSZ) deg[t] = 1.f;
    if (t < HWSZ) { hW[t] = 0.f; hT[t] = 0.f; }
}

// x0 init (zeros + label part)
__global__ void k_initx0(float* __restrict__ x0,
                         const int* __restrict__ entLab,
                         const float* __restrict__ tbl) {
    int t = blockIdx.x * blockDim.x + threadIdx.x;
    if (t >= XSZ) return;
    int r = t / DD, c = t % DD;
    float v = 0.f;
    if (c < LDD) {
        int i = r % NN1, b = r / NN1;
        if (i == 0) v = tbl[c];
        else {
            int lbl = entLab[b*(NN1-1) + i - 1];
            v = lbl ? tbl[lbl*LDD + c] : 0.f;
        }
    }
    x0[t] = v;
}

__global__ void k_eh(const float4* __restrict__ in, uint2* __restrict__ outp, int n4) {
    int i = blockIdx.x * blockDim.x + threadIdx.x;
    if (i < n4) {
        float4 v = in[i];
        uint2 u;
        u.x = pack_h2(v.x, v.y);
        u.y = pack_h2(v.z, v.w);
        outp[i] = u;
    }
}

__global__ void k_x0h(const float* __restrict__ x0, __half* __restrict__ x0h) {
    int t = blockIdx.x * blockDim.x + threadIdx.x;
    if (t >= MM*DDP) return;
    int r = t / DDP, c = t % DDP;
    x0h[t] = (c < DD) ? __float2half_rn(x0[(size_t)r*DD + c]) : __half(0);
}

__global__ void k_deg(float* __restrict__ deg,
                      const int* __restrict__ ei,
                      const int* __restrict__ ea) {
    int t = blockIdx.x * blockDim.x + threadIdx.x;
    if (t >= BB*EE) return;
    int b = t >> 12, e = t & (EE-1);
    int dst = ei[b*2*EE + EE + e];
    int a   = ea[b*EE + e];
    atomicAdd(&deg[(a*BB + b)*NN1 + dst], 1.f);
}

__global__ void k_off(const float* __restrict__ deg) {
    int cb   = blockIdx.x;
    int lane = threadIdx.x;
    const float* dg = deg + cb*NN1;
    int* off = g_off + cb*(NN1+1);
    int* cur = g_cur + cb*NN1;
    if (lane == 0) off[0] = 0;
    int carry = 0;
    for (int base = 0; base < NN1; base += 32) {
        int i = base + lane;
        int v = (i < NN1) ? (int)dg[i] - 1 : 0;
        int s = v;
        #pragma unroll
        for (int d = 1; d < 32; d <<= 1) {
            int t = __shfl_up_sync(0xffffffffu, s, d);
            if (lane >= d) s += t;
        }
        if (i < NN1) {
            cur[i]   = carry + s - v;
            off[i+1] = carry + s;
        }
        carry += __shfl_sync(0xffffffffu, s, 31);
    }
}

__global__ void k_scatter(const float* __restrict__ deg,
                          const int* __restrict__ ei,
                          const int* __restrict__ ea) {
    int t = blockIdx.x * blockDim.x + threadIdx.x;
    if (t >= BB*EE) return;
    int b = t >> 12, e = t & (EE-1);
    int src = ei[b*2*EE + e];
    int dst = ei[b*2*EE + EE + e];
    int a   = ea[b*EE + e];
    int cb  = a*BB + b;
    const float* dg = deg + cb*NN1;
    float coef = rsqrtf(dg[src]) * rsqrtf(dg[dst]);
    int pos = atomicAdd(&g_cur[cb*NN1 + dst], 1);
    g_esrc [cb*EE + pos] = src;
    g_ecoef[cb*EE + pos] = coef;
}

__global__ void k_th(const float* __restrict__ W, __half* __restrict__ Wt,
                     int K, int N, int KP) {
    const float* Wz  = W  + (size_t)blockIdx.z*K*N;
    __half*      Wtz = Wt + (size_t)blockIdx.z*N*KP;
    __shared__ float t[32][33];
    int k = blockIdx.x*32 + threadIdx.y;
    int n = blockIdx.y*32 + threadIdx.x;
    if (k < K && n < N) t[threadIdx.y][threadIdx.x] = Wz[(size_t)k*N + n];
    __syncthreads();
    int no = blockIdx.y*32 + threadIdx.y;
    int ko = blockIdx.x*32 + threadIdx.x;
    if (no < N && ko < KP)
        Wtz[(size_t)no*KP + ko] = (ko < K) ? __float2half_rn(t[threadIdx.x][threadIdx.y])
                                           : __half(0);
}

// ---------------------------------------------------------------------------
// Big fp16 GEMM, cp.async + LDSM: red = emb@W_red (+bias/relu/segmax).
// ---------------------------------------------------------------------------
#define KC    64
#define RA_LD 72
#define R_SZH (128*RA_LD)
#define RED_SMEM (4*R_SZH*2)

__global__ void __launch_bounds__(512, 1) k_mma_red(
    const __half* __restrict__ A,
    const __half* __restrict__ Bt,
    const float*  __restrict__ bias,
    const int*    __restrict__ entIdx,
    float*        __restrict__ x0)
{
    extern __shared__ __align__(16) __half smh[];
    __half* sAb[2] = { smh,            smh + R_SZH };
    __half* sBb[2] = { smh + 2*R_SZH,  smh + 3*R_SZH };

    const int tid  = threadIdx.x;
    const int lane = tid & 31;
    const int wid  = tid >> 5;
    const int gr   = lane >> 2;
    const int kq   = lane & 3;
    const int wm   = wid & 3;
    const int wn   = wid >> 2;
    const int row0 = blockIdx.y * 128;
    const int col0 = blockIdx.x * 128;

    const int sr = tid >> 2;
    const int sg = tid & 3;

    const int arow_l = ((lane >> 3) & 1)*8 + (lane & 7);
    const int acol_l = (lane >> 4)*8;
    const int brow_l = (lane >> 4)*8 + (lane & 7);
    const int bcol_l = ((lane >> 3) & 1)*8;
    uint32_t aoff[2], boff[2];
    #pragma unroll
    for (int mi = 0; mi < 2; mi++)
        aoff[mi] = ((wm*32 + mi*16 + arow_l)*RA_LD + acol_l)*2;
    #pragma unroll
    for (int pr = 0; pr < 2; pr++)
        boff[pr] = ((wn*32 + pr*16 + brow_l)*RA_LD + bcol_l)*2;
    uint32_t sAu[2] = { s2u(sAb[0]), s2u(sAb[1]) };
    uint32_t sBu[2] = { s2u(sBb[0]), s2u(sBb[1]) };

    float acc[2][4][4];
    #pragma unroll
    for (int i = 0; i < 2; i++)
        #pragma unroll
        for (int j = 0; j < 4; j++)
            #pragma unroll
            for (int u = 0; u < 4; u++) acc[i][j][u] = 0.f;

    const __half* agp = A  + (size_t)(row0 + sr)*ETRD + sg*16;
    const __half* bgp = Bt + (size_t)(col0 + sr)*ETRD + sg*16;
    const uint32_t sAoff = (sr*RA_LD + sg*16)*2;

    auto ldchunk = [&](int k0, int buf) {
        cp16(sAu[buf] + sAoff,      agp + k0);
        cp16(sAu[buf] + sAoff + 16, agp + k0 + 8);
        cp16(sBu[buf] + sAoff,      bgp + k0);
        cp16(sBu[buf] + sAoff + 16, bgp + k0 + 8);
        CP_COMMIT();
    };
    auto compute = [&](int buf) {
        #pragma unroll
        for (int ks = 0; ks < KC/16; ks++) {
            uint32_t af[2][4], bf[2][4];
            ldsm4(af[0], sAu[buf] + aoff[0] + ks*32);
            ldsm4(af[1], sAu[buf] + aoff[1] + ks*32);
            ldsm4(bf[0], sBu[buf] + boff[0] + ks*32);
            ldsm4(bf[1], sBu[buf] + boff[1] + ks*32);
            #pragma unroll
            for (int mi = 0; mi < 2; mi++) {
                mma_f16(acc[mi][0], af[mi], &bf[0][0]);
                mma_f16(acc[mi][1], af[mi], &bf[0][2]);
                mma_f16(acc[mi][2], af[mi], &bf[1][0]);
                mma_f16(acc[mi][3], af[mi], &bf[1][2]);
            }
        }
    };

    ldchunk(0, 0);
    CP_WAIT0();
    __syncthreads();
    #pragma unroll 1
    for (int ch = 0; ch < ETRD/KC; ch++) {
        if (ch + 1 < ETRD/KC) ldchunk((ch + 1)*KC, (ch + 1) & 1);
        compute(ch & 1);
        if (ch + 1 < ETRD/KC) {
            CP_WAIT0();
            __syncthreads();
        }
    }

    int    nodev[2][2];
    float* basep[2][2];
    #pragma unroll
    for (int mi = 0; mi < 2; mi++)
        #pragma unroll
        for (int h = 0; h < 2; h++) {
            int r  = row0 + wm*32 + mi*16 + gr + h*8;
            int nd = entIdx[r];
            nodev[mi][h] = nd;
            int b = r >> 11;
            basep[mi][h] = x0 + ((size_t)(b*NN1 + nd))*DD + LDD;
        }
    #pragma unroll
    for (int ni = 0; ni < 4; ni++) {
        int c = col0 + wn*32 + ni*8 + kq*2;
        float b0 = __ldg(bias + c), b1 = __ldg(bias + c + 1);
        #pragma unroll
        for (int mi = 0; mi < 2; mi++) {
            #pragma unroll
            for (int h = 0; h < 2; h++) {
                if (nodev[mi][h] == 0) continue;
                float v0 = acc[mi][ni][2*h    ] + b0;
                float v1 = acc[mi][ni][2*h + 1] + b1;
                if (v0 > 0.f) atomicMax((int*)(basep[mi][h] + c),     __float_as_int(v0));
                if (v1 > 0.f) atomicMax((int*)(basep[mi][h] + c + 1), __float_as_int(v1));
            }
        }
    }
}

// ---------------------------------------------------------------------------
// xW GEMM, full cp.async + LDSM, 3 classes via grid.z
// ---------------------------------------------------------------------------
__global__ void __launch_bounds__(512, 1) k_mma_xw(
    const __half* __restrict__ Abase,
    const __half* __restrict__ Wg,
    __half*       __restrict__ Cbase,
    int M, long long strideA, int layer)
{
    const int z = blockIdx.z;
    const __half* A  = Abase + (size_t)z*strideA;
    const __half* Bt = Wg + ((size_t)z*NLAY + layer)*DD*DDP;
    __half* C = Cbase + (size_t)z*MM*DDP;

    extern __shared__ __align__(16) __half smh[];
    __half* sAb[2] = { smh,            smh + R_SZH };
    __half* sBb[2] = { smh + 2*R_SZH,  smh + 3*R_SZH };

    const int tid  = threadIdx.x;
    const int lane = tid & 31;
    const int wid  = tid >> 5;
    const int gr   = lane >> 2;
    const int kq   = lane & 3;
    const int wm   = wid & 3;
    const int wn   = wid >> 2;
    const int row0 = blockIdx.y * 128;
    const int col0 = blockIdx.x * 128;

    const int sr = tid >> 2;
    const int sg = tid & 3;

    const int arow_l = ((lane >> 3) & 1)*8 + (lane & 7);
    const int acol_l = (lane >> 4)*8;
    const int brow_l = (lane >> 4)*8 + (lane & 7);
    const int bcol_l = ((lane >> 3) & 1)*8;
    uint32_t aoff[2], boff[2];
    #pragma unroll
    for (int mi = 0; mi < 2; mi++)
        aoff[mi] = ((wm*32 + mi*16 + arow_l)*RA_LD + acol_l)*2;
    #pragma unroll
    for (int pr = 0; pr < 2; pr++)
        boff[pr] = ((wn*32 + pr*16 + brow_l)*RA_LD + bcol_l)*2;
    uint32_t sAu[2] = { s2u(sAb[0]), s2u(sAb[1]) };
    uint32_t sBu[2] = { s2u(sBb[0]), s2u(sBb[1]) };

    float acc[2][4][4];
    #pragma unroll
    for (int i = 0; i < 2; i++)
        #pragma unroll
        for (int j = 0; j < 4; j++)
            #pragma unroll
            for (int u = 0; u < 4; u++) acc[i][j][u] = 0.f;

    int arow = row0 + sr; if (arow >= M)  arow = M - 1;
    int brow = col0 + sr; if (brow >= DD) brow = DD - 1;
    const __half* agp = A  + (size_t)arow*DDP + sg*16;
    const __half* bgp = Bt + (size_t)brow*DDP + sg*16;
    const uint32_t sAoff = (sr*RA_LD + sg*16)*2;

    auto ldchunk = [&](int k0, int buf) {
        cp16(sAu[buf] + sAoff,      agp + k0);
        cp16(sAu[buf] + sAoff + 16, agp + k0 + 8);
        cp16(sBu[buf] + sAoff,      bgp + k0);
        cp16(sBu[buf] + sAoff + 16, bgp + k0 + 8);
        CP_COMMIT();
    };
    auto compute = [&](int buf) {
        #pragma unroll
        for (int ks = 0; ks < KC/16; ks++) {
            uint32_t af[2][4], bf[2][4];
            ldsm4(af[0], sAu[buf] + aoff[0] + ks*32);
            ldsm4(af[1], sAu[buf] + aoff[1] + ks*32);
            ldsm4(bf[0], sBu[buf] + boff[0] + ks*32);
            ldsm4(bf[1], sBu[buf] + boff[1] + ks*32);
            #pragma unroll
            for (int mi = 0; mi < 2; mi++) {
                mma_f16(acc[mi][0], af[mi], &bf[0][0]);
                mma_f16(acc[mi][1], af[mi], &bf[0][2]);
                mma_f16(acc[mi][2], af[mi], &bf[1][0]);
                mma_f16(acc[mi][3], af[mi], &bf[1][2]);
            }
        }
    };

    ldchunk(0, 0);
    CP_WAIT0();
    __syncthreads();
    #pragma unroll 1
    for (int ch = 0; ch < DDP/KC; ch++) {
        if (ch + 1 < DDP/KC) ldchunk((ch + 1)*KC, (ch + 1) & 1);
        compute(ch & 1);
        if (ch + 1 < DDP/KC) {
            CP_WAIT0();
            __syncthreads();
        }
    }

    #pragma unroll
    for (int mi = 0; mi < 2; mi++) {
        #pragma unroll
        for (int h = 0; h < 2; h++) {
            int gm = row0 + wm*32 + mi*16 + gr + h*8;
            if (gm >= M) continue;
            #pragma unroll
            for (int ni = 0; ni < 4; ni++) {
                int gn = col0 + wn*32 + ni*8 + kq*2;
                if (gn < DD) {
                    *(uint32_t*)(C + (size_t)gm*DDP + gn) =
                        pack_h2(acc[mi][ni][2*h], acc[mi][ni][2*h + 1]);
                }
            }
        }
    }
}

// ---------------------------------------------------------------------------
// Sparse GCN aggregation + (layer 1) fused head/tail projection
// ---------------------------------------------------------------------------
#define NH2 (DD/2)

__global__ void __launch_bounds__(256) k_spmm(
    const __half* __restrict__ hbase,
    __half* __restrict__ xbH,
    const float* __restrict__ deg,
    const float* __restrict__ bgcn,
    const float* __restrict__ Who,
    const float* __restrict__ Wto,
    float* __restrict__ hW,
    float* __restrict__ hT,
    int layer)
{
    int dst = blockIdx.x;
    int b   = blockIdx.y;
    int cls = blockIdx.z;
    int cb  = cls*BB + b;
    int tid = threadIdx.x;

    const float* bias = bgcn + (size_t)(cls*NLAY + layer)*DD;
    const __half* hb  = hbase + ((size_t)cls*MM + (size_t)b*NN1)*DDP;

    const int* off = g_off + cb*(NN1+1);
    int e0 = off[dst], e1 = off[dst+1];
    const int*   es = g_esrc  + cb*EE;
    const float* ec = g_ecoef + cb*EE;

    int j0 = tid, j1 = tid + 256;
    float2 a0 = {0.f, 0.f}, a1 = {0.f, 0.f};

    for (int e = e0; e < e1; e++) {
        int   src = es[e];
        float w   = ec[e];
        const __half2* hr = (const __half2*)(hb + (size_t)src*DDP);
        float2 x = __half22float2(hr[j0]);
        a0.x += w * x.x;
        a0.y += w * x.y;
        if (j1 < NH2) {
            float2 y = __half22float2(hr[j1]);
            a1.x += w * y.x;
            a1.y += w * y.y;
        }
    }

    float dinv = 1.f / deg[cb*NN1 + dst];
    const __half2* hd = (const __half2*)(hb + (size_t)dst*DDP);

    float2 s0 = __half22float2(hd[j0]);
    float v0x = a0.x + s0.x*dinv + bias[2*j0];
    float v0y = a0.y + s0.y*dinv + bias[2*j0 + 1];
    float v1x = 0.f, v1y = 0.f;
    if (j1 < NH2) {
        float2 s1 = __half22float2(hd[j1]);
        v1x = a1.x + s1.x*dinv + bias[2*j1];
        v1y = a1.y + s1.y*dinv + bias[2*j1 + 1];
    }

    if (layer == 0) {
        __half* xo = xbH + ((size_t)cls*MM + (size_t)b*NN1 + dst)*DDP;
        *(uint32_t*)(xo + 2*j0) = pack_h2(v0x, v0y);
        if (j1 < NH2) *(uint32_t*)(xo + 2*j1) = pack_h2(v1x, v1y);
        if (tid < (DDP - DD)/2)
            *(uint32_t*)(xo + DD + 2*tid) = 0u;
        return;
    }

    float lw[3], lt[3];
    #pragma unroll
    for (int c = 0; c < 3; c++) {
        float w = v0x*Who[(2*j0)*3 + c] + v0y*Who[(2*j0 + 1)*3 + c];
        float t = v0x*Wto[(2*j0)*3 + c] + v0y*Wto[(2*j0 + 1)*3 + c];
        if (j1 < NH2) {
            w += v1x*Who[(2*j1)*3 + c] + v1y*Who[(2*j1 + 1)*3 + c];
            t += v1x*Wto[(2*j1)*3 + c] + v1y*Wto[(2*j1 + 1)*3 + c];
        }
        lw[c] = w;
        lt[c] = t;
    }
    #pragma unroll
    for (int d = 16; d > 0; d >>= 1) {
        #pragma unroll
        for (int c = 0; c < 3; c++) {
            lw[c] += __shfl_down_sync(0xffffffffu, lw[c], d);
            lt[c] += __shfl_down_sync(0xffffffffu, lt[c], d);
        }
    }
    __shared__ float sred[8][6];
    int warp = tid >> 5, lane = tid & 31;
    if (lane == 0) {
        #pragma unroll
        for (int c = 0; c < 3; c++) {
            sred[warp][c]     = lw[c];
            sred[warp][3 + c] = lt[c];
        }
    }
    __syncthreads();
    if (tid == 0) {
        float sw[3] = {0.f, 0.f, 0.f}, st[3] = {0.f, 0.f, 0.f};
        #pragma unroll
        for (int wgi = 0; wgi < 8; wgi++)
            #pragma unroll
            for (int c = 0; c < 3; c++) {
                sw[c] += sred[wgi][c];
                st[c] += sred[wgi][3 + c];
            }
        int idx = (b*NN1 + dst)*3;
        #pragma unroll
        for (int c = 0; c < 3; c++) {
            atomicAdd(&hW[idx + c], sw[c] * (1.f/3.f));
            atomicAdd(&hT[idx + c], st[c] * (1.f/3.f));
        }
    }
}

// ---------------------------------------------------------------------------
// Collapsed head/tail weights (prep phase)
// ---------------------------------------------------------------------------
__global__ void k_ho(const float* __restrict__ W_head, const float* __restrict__ W_tail,
                     const float* __restrict__ W_out,
                     const float* __restrict__ b_head, const float* __restrict__ b_tail,
                     float* __restrict__ Who, float* __restrict__ Wto,
                     float* __restrict__ bho, float* __restrict__ bto) {
    int t = blockIdx.x * blockDim.x + threadIdx.x;
    if (t < 2*DD*3) {
        int which = t / (DD*3), rc = t % (DD*3), r = rc / 3, c = rc % 3;
        const float* W = which ? W_tail : W_head;
        float acc = 0.f;
        for (int j = 0; j < DD; j++) acc += W[r*DD + j] * W_out[j*3 + c];
        (which ? Wto : Who)[r*3 + c] = acc;
    } else if (t < 2*DD*3 + 6) {
        int u = t - 2*DD*3, which = u / 3, c = u % 3;
        const float* bb = which ? b_tail : b_head;
        float acc = 0.f;
        for (int j = 0; j < DD; j++) acc += bb[j] * W_out[j*3 + c];
        (which ? bto : bho)[c] = acc;
    }
}

__global__ void k_logits(const int* __restrict__ cands,
                         const float* __restrict__ hW, const float* __restrict__ hT,
                         const float* __restrict__ bho, const float* __restrict__ bto,
                         const float* __restrict__ b_out,
                         float* __restrict__ out) {
    int t = blockIdx.x * blockDim.x + threadIdx.x;
    const int TOT = BB*NN1*(NN1-1)*3;
    if (t >= TOT) return;
    int c = t % 3;
    int j = (t / 3) & 255;
    int i = (t / (3*256)) % NN1;
    int b = t / (3*256*NN1);
    int m = cands[((long long)(b*NN1 + i))*NN1 + j + 1];
    float v = b_out[c];
    if (m) v += hW[(b*NN1 + i)*3 + c] + bho[c] + hT[(b*NN1 + j + 1)*3 + c] + bto[c];
    out[t] = v;
}

// ---------------------------------------------------------------------------
// Launch (multi-stream fork/join, graph-capturable)
// ---------------------------------------------------------------------------
extern "C" void kernel_launch(void* const* d_in, const int* in_sizes, int n_in,
                              void* d_out, int out_size) {
    const float* emb     = (const float*)d_in[0];
    const int*   entIdx  = (const int*)  d_in[1];
    const int*   entLab  = (const int*)  d_in[2];
    const int*   edgeIdx = (const int*)  d_in[3];
    const int*   edgeAttr= (const int*)  d_in[4];
    const int*   cands   = (const int*)  d_in[5];
    const float* W_red   = (const float*)d_in[6];
    const float* b_red   = (const float*)d_in[7];
    const float* tbl     = (const float*)d_in[8];
    const float* W_gcn   = (const float*)d_in[9];
    const float* b_gcn   = (const float*)d_in[10];
    const float* W_head  = (const float*)d_in[11];
    const float* b_head  = (const float*)d_in[12];
    const float* W_tail  = (const float*)d_in[13];
    const float* b_tail  = (const float*)d_in[14];
    const float* W_out   = (const float*)d_in[15];
    const float* b_out   = (const float*)d_in[16];
    float* out = (float*)d_out;

    static float *px0=nullptr, *pdeg,
                 *pWho, *pWto, *pbho, *pbto, *phW, *phT;
    static __half *pWt, *pWg, *pEh, *px0h, *pxb16, *phc;
    static cudaStream_t s2 = nullptr, s3 = nullptr;
    static cudaEvent_t evFork = nullptr, evJ2 = nullptr, evJ3 = nullptr;
    static bool attr_set = false;
    if (!px0) {
        cudaGetSymbolAddress((void**)&px0,   g_x0);
        cudaGetSymbolAddress((void**)&px0h,  g_x0h);
        cudaGetSymbolAddress((void**)&phc,   g_hc);
        cudaGetSymbolAddress((void**)&pxb16, g_xb16);
        cudaGetSymbolAddress((void**)&pdeg,  g_deg);
        cudaGetSymbolAddress((void**)&pWt,   g_Wt);
        cudaGetSymbolAddress((void**)&pWg,   g_Wg);
        cudaGetSymbolAddress((void**)&pEh,   g_embh);
        cudaGetSymbolAddress((void**)&pWho,  g_Who);
        cudaGetSymbolAddress((void**)&pWto,  g_Wto);
        cudaGetSymbolAddress((void**)&pbho,  g_bho);
        cudaGetSymbolAddress((void**)&pbto,  g_bto);
        cudaGetSymbolAddress((void**)&phW,   g_hW);
        cudaGetSymbolAddress((void**)&phT,   g_hT);
        cudaStreamCreateWithFlags(&s2, cudaStreamNonBlocking);
        cudaStreamCreateWithFlags(&s3, cudaStreamNonBlocking);
        cudaEventCreateWithFlags(&evFork, cudaEventDisableTiming);
        cudaEventCreateWithFlags(&evJ2,   cudaEventDisableTiming);
        cudaEventCreateWithFlags(&evJ3,   cudaEventDisableTiming);
    }
    if (!attr_set) {
        cudaFuncSetAttribute(k_mma_red, cudaFuncAttributeMaxDynamicSharedMemorySize, RED_SMEM);
        cudaFuncSetAttribute(k_mma_xw,  cudaFuncAttributeMaxDynamicSharedMemorySize, RED_SMEM);
        attr_set = true;
    }

    auto blocks = [](int n) { return (n + 255) / 256; };

    // ---- fork ----
    cudaEventRecord(evFork, 0);
    cudaStreamWaitEvent(s2, evFork, 0);
    cudaStreamWaitEvent(s3, evFork, 0);

    // side stream s2: CSR chain + Wg transpose + collapsed head/tail
    k_initmisc<<<blocks(HWSZ), 256, 0, s2>>>(pdeg, phW, phT);
    k_deg     <<<blocks(BB*EE), 256, 0, s2>>>(pdeg, edgeIdx, edgeAttr);
    k_off     <<<CBSZ, 32, 0, s2>>>(pdeg);
    k_scatter <<<blocks(BB*EE), 256, 0, s2>>>(pdeg, edgeIdx, edgeAttr);
    {
        dim3 bl(32, 32);
        k_th<<<dim3(DDP/32, (DD+31)/32, NCLS*NLAY), bl, 0, s2>>>(W_gcn, pWg, DD, DD, DDP);
    }
    k_ho<<<blocks(2*DD*3 + 6), 256, 0, s2>>>(W_head, W_tail, W_out, b_head, b_tail,
                                             pWho, pWto, pbho, pbto);
    cudaEventRecord(evJ2, s2);

    // side stream s3: x0 init + W_red transpose (needed by mma_red)
    k_initx0<<<blocks(XSZ), 256, 0, s3>>>(px0, entLab, tbl);
    {
        dim3 bl(32, 32);
        k_th<<<dim3(ETRD/32, HH/32, 1), bl, 0, s3>>>(W_red, pWt, ETRD, HH, ETRD);
    }
    cudaEventRecord(evJ3, s3);

    // main stream: emb fp16 conversion (longest prep), then big GEMM
    k_eh<<<blocks(BB*SS*ETRD/4), 256>>>((const float4*)emb, (uint2*)pEh, BB*SS*ETRD/4);
    cudaStreamWaitEvent(0, evJ3, 0);      // join s3 (x0, Wt)
    {
        dim3 g(HH/128, (BB*SS)/128);
        k_mma_red<<<g, 512, RED_SMEM>>>(pEh, pWt, b_red, entIdx, px0);
    }
    k_x0h<<<blocks(MM*DDP), 256>>>(px0, px0h);

    cudaStreamWaitEvent(0, evJ2, 0);      // join s2 (CSR, Wg, Who/Wto, hW/hT)

    // GCN: 2 layers, all 3 classes per launch; layer 1 fuses head/tail proj
    {
        dim3 gx((DD + 127)/128, (MM + 127)/128, NCLS);
        dim3 gs(NN1, BB, NCLS);
        k_mma_xw<<<gx, 512, RED_SMEM>>>(px0h, pWg, phc, MM, 0LL, 0);
        k_spmm  <<<gs, 256>>>(phc, pxb16, pdeg, b_gcn, pWho, pWto, phW, phT, 0);
        k_mma_xw<<<gx, 512, RED_SMEM>>>(pxb16, pWg, phc, MM, (long long)MM*DDP, 1);
        k_spmm  <<<gs, 256>>>(phc, nullptr, pdeg, b_gcn, pWho, pWto, phW, phT, 1);
    }

    // logits
    k_logits<<<blocks(BB*NN1*(NN1-1)*3), 256>>>(cands, phW, phT, pbho, pbto, b_out, out);
}

// round 15
// speedup vs baseline: 4.6140x; 1.2290x over previous
#include <cuda_runtime.h>
#include <cuda_fp16.h>
#include <cstdint>

// ---------------------------------------------------------------------------
// Problem constants
// ---------------------------------------------------------------------------
#define BB    16
#define SS    2048
#define NN1   257
#define EE    4096
#define HH    512
#define LDD   16
#define ETRD  768
#define DD    528
#define DDP   576
#define NCLS  3
#define NLAY  2

#define MM    (BB*NN1)
#define XSZ   (BB*NN1*DD)
#define DEGSZ (NCLS*BB*NN1)
#define CBSZ  (NCLS*BB)
#define HWSZ  (BB*NN1*3)

// ---------------------------------------------------------------------------
// Device scratch
// ---------------------------------------------------------------------------
__device__ float  g_x0 [XSZ];
__device__ __half g_x0h[MM*DDP];
__device__ __half g_hc [NCLS*MM*DDP];
__device__ __half g_xb16[NCLS*MM*DDP];
__device__ float  g_deg[DEGSZ];
__device__ int    g_off[CBSZ*(NN1+1)];
__device__ int    g_cur[CBSZ*NN1];
__device__ int    g_esrc[CBSZ*EE];
__device__ float  g_ecoef[CBSZ*EE];
__device__ __half g_embh[BB*SS*ETRD];
__device__ __half g_Wt [HH*ETRD];
__device__ __half g_Wg [NCLS*NLAY*DD*DDP];
__device__ float  g_Who[DD*3];
__device__ float  g_Wto[DD*3];
__device__ float  g_bho[3];
__device__ float  g_bto[3];
__device__ float  g_hW [HWSZ];
__device__ float  g_hT [HWSZ];

// ---------------------------------------------------------------------------
// mma / ldmatrix / cp.async helpers
// ---------------------------------------------------------------------------
__device__ __forceinline__ void mma_f16(float* c, const uint32_t* a, const uint32_t* b) {
    asm volatile(
        "mma.sync.aligned.m16n8k16.row.col.f32.f16.f16.f32 "
        "{%0,%1,%2,%3}, {%4,%5,%6,%7}, {%8,%9}, {%0,%1,%2,%3};"
        : "+f"(c[0]), "+f"(c[1]), "+f"(c[2]), "+f"(c[3])
        : "r"(a[0]), "r"(a[1]), "r"(a[2]), "r"(a[3]), "r"(b[0]), "r"(b[1]));
}

__device__ __forceinline__ void ldsm4(uint32_t* r, uint32_t saddr) {
    asm volatile("ldmatrix.sync.aligned.m8n8.x4.shared.b16 {%0,%1,%2,%3}, [%4];"
                 : "=r"(r[0]), "=r"(r[1]), "=r"(r[2]), "=r"(r[3]) : "r"(saddr));
}

__device__ __forceinline__ uint32_t s2u(const void* p) {
    return (uint32_t)__cvta_generic_to_shared(p);
}

__device__ __forceinline__ void cp16(uint32_t s, const void* g) {
    asm volatile("cp.async.cg.shared.global [%0], [%1], 16;" :: "r"(s), "l"(g));
}
#define CP_COMMIT() asm volatile("cp.async.commit_group;" ::: "memory")
#define CP_WAIT0()  asm volatile("cp.async.wait_group 0;"  ::: "memory")

__device__ __forceinline__ uint32_t pack_h2(float x, float y) {
    __half2 h = __floats2half2_rn(x, y);
    return *(uint32_t*)&h;
}

// ---------------------------------------------------------------------------
// Small helper kernels
// ---------------------------------------------------------------------------
__global__ void k_initmisc(float* __restrict__ deg,
                           float* __restrict__ hW,
                           float* __restrict__ hT) {
    int t = blockIdx.x * blockDim.x + threadIdx.x;
    if (t < DEGSZ) deg[t] = 1.f;
    if (t < HWSZ) { hW[t] = 0.f; hT[t] = 0.f; }
}

__global__ void k_initx0(float* __restrict__ x0,
                         const int* __restrict__ entLab,
                         const float* __restrict__ tbl) {
    int t = blockIdx.x * blockDim.x + threadIdx.x;
    if (t >= XSZ) return;
    int r = t / DD, c = t % DD;
    float v = 0.f;
    if (c < LDD) {
        int i = r % NN1, b = r / NN1;
        if (i == 0) v = tbl[c];
        else {
            int lbl = entLab[b*(NN1-1) + i - 1];
            v = lbl ? tbl[lbl*LDD + c] : 0.f;
        }
    }
    x0[t] = v;
}

// fp32 -> fp16 bulk convert, with element offset (for split halves)
__global__ void k_eh(const float4* __restrict__ in, uint2* __restrict__ outp, int n4) {
    int i = blockIdx.x * blockDim.x + threadIdx.x;
    if (i < n4) {
        float4 v = in[i];
        uint2 u;
        u.x = pack_h2(v.x, v.y);
        u.y = pack_h2(v.z, v.w);
        outp[i] = u;
    }
}

__global__ void k_x0h(const float* __restrict__ x0, __half* __restrict__ x0h) {
    int t = blockIdx.x * blockDim.x + threadIdx.x;
    if (t >= MM*DDP) return;
    int r = t / DDP, c = t % DDP;
    x0h[t] = (c < DD) ? __float2half_rn(x0[(size_t)r*DD + c]) : __half(0);
}

__global__ void k_deg(float* __restrict__ deg,
                      const int* __restrict__ ei,
                      const int* __restrict__ ea) {
    int t = blockIdx.x * blockDim.x + threadIdx.x;
    if (t >= BB*EE) return;
    int b = t >> 12, e = t & (EE-1);
    int dst = ei[b*2*EE + EE + e];
    int a   = ea[b*EE + e];
    atomicAdd(&deg[(a*BB + b)*NN1 + dst], 1.f);
}

__global__ void k_off(const float* __restrict__ deg) {
    int cb   = blockIdx.x;
    int lane = threadIdx.x;
    const float* dg = deg + cb*NN1;
    int* off = g_off + cb*(NN1+1);
    int* cur = g_cur + cb*NN1;
    if (lane == 0) off[0] = 0;
    int carry = 0;
    for (int base = 0; base < NN1; base += 32) {
        int i = base + lane;
        int v = (i < NN1) ? (int)dg[i] - 1 : 0;
        int s = v;
        #pragma unroll
        for (int d = 1; d < 32; d <<= 1) {
            int t = __shfl_up_sync(0xffffffffu, s, d);
            if (lane >= d) s += t;
        }
        if (i < NN1) {
            cur[i]   = carry + s - v;
            off[i+1] = carry + s;
        }
        carry += __shfl_sync(0xffffffffu, s, 31);
    }
}

__global__ void k_scatter(const float* __restrict__ deg,
                          const int* __restrict__ ei,
                          const int* __restrict__ ea) {
    int t = blockIdx.x * blockDim.x + threadIdx.x;
    if (t >= BB*EE) return;
    int b = t >> 12, e = t & (EE-1);
    int src = ei[b*2*EE + e];
    int dst = ei[b*2*EE + EE + e];
    int a   = ea[b*EE + e];
    int cb  = a*BB + b;
    const float* dg = deg + cb*NN1;
    float coef = rsqrtf(dg[src]) * rsqrtf(dg[dst]);
    int pos = atomicAdd(&g_cur[cb*NN1 + dst], 1);
    g_esrc [cb*EE + pos] = src;
    g_ecoef[cb*EE + pos] = coef;
}

__global__ void k_th(const float* __restrict__ W, __half* __restrict__ Wt,
                     int K, int N, int KP) {
    const float* Wz  = W  + (size_t)blockIdx.z*K*N;
    __half*      Wtz = Wt + (size_t)blockIdx.z*N*KP;
    __shared__ float t[32][33];
    int k = blockIdx.x*32 + threadIdx.y;
    int n = blockIdx.y*32 + threadIdx.x;
    if (k < K && n < N) t[threadIdx.y][threadIdx.x] = Wz[(size_t)k*N + n];
    __syncthreads();
    int no = blockIdx.y*32 + threadIdx.y;
    int ko = blockIdx.x*32 + threadIdx.x;
    if (no < N && ko < KP)
        Wtz[(size_t)no*KP + ko] = (ko < K) ? __float2half_rn(t[threadIdx.x][threadIdx.y])
                                           : __half(0);
}

// ---------------------------------------------------------------------------
// Big fp16 GEMM (with y-base for split launch), cp.async + LDSM
// ---------------------------------------------------------------------------
#define KC    64
#define RA_LD 72
#define R_SZH (128*RA_LD)
#define RED_SMEM (4*R_SZH*2)

__global__ void __launch_bounds__(512, 1) k_mma_red(
    const __half* __restrict__ A,
    const __half* __restrict__ Bt,
    const float*  __restrict__ bias,
    const int*    __restrict__ entIdx,
    float*        __restrict__ x0,
    int yBase)
{
    extern __shared__ __align__(16) __half smh[];
    __half* sAb[2] = { smh,            smh + R_SZH };
    __half* sBb[2] = { smh + 2*R_SZH,  smh + 3*R_SZH };

    const int tid  = threadIdx.x;
    const int lane = tid & 31;
    const int wid  = tid >> 5;
    const int gr   = lane >> 2;
    const int kq   = lane & 3;
    const int wm   = wid & 3;
    const int wn   = wid >> 2;
    const int row0 = (yBase + blockIdx.y) * 128;
    const int col0 = blockIdx.x * 128;

    const int sr = tid >> 2;
    const int sg = tid & 3;

    const int arow_l = ((lane >> 3) & 1)*8 + (lane & 7);
    const int acol_l = (lane >> 4)*8;
    const int brow_l = (lane >> 4)*8 + (lane & 7);
    const int bcol_l = ((lane >> 3) & 1)*8;
    uint32_t aoff[2], boff[2];
    #pragma unroll
    for (int mi = 0; mi < 2; mi++)
        aoff[mi] = ((wm*32 + mi*16 + arow_l)*RA_LD + acol_l)*2;
    #pragma unroll
    for (int pr = 0; pr < 2; pr++)
        boff[pr] = ((wn*32 + pr*16 + brow_l)*RA_LD + bcol_l)*2;
    uint32_t sAu[2] = { s2u(sAb[0]), s2u(sAb[1]) };
    uint32_t sBu[2] = { s2u(sBb[0]), s2u(sBb[1]) };

    float acc[2][4][4];
    #pragma unroll
    for (int i = 0; i < 2; i++)
        #pragma unroll
        for (int j = 0; j < 4; j++)
            #pragma unroll
            for (int u = 0; u < 4; u++) acc[i][j][u] = 0.f;

    const __half* agp = A  + (size_t)(row0 + sr)*ETRD + sg*16;
    const __half* bgp = Bt + (size_t)(col0 + sr)*ETRD + sg*16;
    const uint32_t sAoff = (sr*RA_LD + sg*16)*2;

    auto ldchunk = [&](int k0, int buf) {
        cp16(sAu[buf] + sAoff,      agp + k0);
        cp16(sAu[buf] + sAoff + 16, agp + k0 + 8);
        cp16(sBu[buf] + sAoff,      bgp + k0);
        cp16(sBu[buf] + sAoff + 16, bgp + k0 + 8);
        CP_COMMIT();
    };
    auto compute = [&](int buf) {
        #pragma unroll
        for (int ks = 0; ks < KC/16; ks++) {
            uint32_t af[2][4], bf[2][4];
            ldsm4(af[0], sAu[buf] + aoff[0] + ks*32);
            ldsm4(af[1], sAu[buf] + aoff[1] + ks*32);
            ldsm4(bf[0], sBu[buf] + boff[0] + ks*32);
            ldsm4(bf[1], sBu[buf] + boff[1] + ks*32);
            #pragma unroll
            for (int mi = 0; mi < 2; mi++) {
                mma_f16(acc[mi][0], af[mi], &bf[0][0]);
                mma_f16(acc[mi][1], af[mi], &bf[0][2]);
                mma_f16(acc[mi][2], af[mi], &bf[1][0]);
                mma_f16(acc[mi][3], af[mi], &bf[1][2]);
            }
        }
    };

    ldchunk(0, 0);
    CP_WAIT0();
    __syncthreads();
    #pragma unroll 1
    for (int ch = 0; ch < ETRD/KC; ch++) {
        if (ch + 1 < ETRD/KC) ldchunk((ch + 1)*KC, (ch + 1) & 1);
        compute(ch & 1);
        if (ch + 1 < ETRD/KC) {
            CP_WAIT0();
            __syncthreads();
        }
    }

    int    nodev[2][2];
    float* basep[2][2];
    #pragma unroll
    for (int mi = 0; mi < 2; mi++)
        #pragma unroll
        for (int h = 0; h < 2; h++) {
            int r  = row0 + wm*32 + mi*16 + gr + h*8;
            int nd = entIdx[r];
            nodev[mi][h] = nd;
            int b = r >> 11;
            basep[mi][h] = x0 + ((size_t)(b*NN1 + nd))*DD + LDD;
        }
    #pragma unroll
    for (int ni = 0; ni < 4; ni++) {
        int c = col0 + wn*32 + ni*8 + kq*2;
        float b0 = __ldg(bias + c), b1 = __ldg(bias + c + 1);
        #pragma unroll
        for (int mi = 0; mi < 2; mi++) {
            #pragma unroll
            for (int h = 0; h < 2; h++) {
                if (nodev[mi][h] == 0) continue;
                float v0 = acc[mi][ni][2*h    ] + b0;
                float v1 = acc[mi][ni][2*h + 1] + b1;
                if (v0 > 0.f) atomicMax((int*)(basep[mi][h] + c),     __float_as_int(v0));
                if (v1 > 0.f) atomicMax((int*)(basep[mi][h] + c + 1), __float_as_int(v1));
            }
        }
    }
}

// ---------------------------------------------------------------------------
// xW GEMM, full cp.async + LDSM, 3 classes via grid.z
// ---------------------------------------------------------------------------
__global__ void __launch_bounds__(512, 1) k_mma_xw(
    const __half* __restrict__ Abase,
    const __half* __restrict__ Wg,
    __half*       __restrict__ Cbase,
    int M, long long strideA, int layer)
{
    const int z = blockIdx.z;
    const __half* A  = Abase + (size_t)z*strideA;
    const __half* Bt = Wg + ((size_t)z*NLAY + layer)*DD*DDP;
    __half* C = Cbase + (size_t)z*MM*DDP;

    extern __shared__ __align__(16) __half smh[];
    __half* sAb[2] = { smh,            smh + R_SZH };
    __half* sBb[2] = { smh + 2*R_SZH,  smh + 3*R_SZH };

    const int tid  = threadIdx.x;
    const int lane = tid & 31;
    const int wid  = tid >> 5;
    const int gr   = lane >> 2;
    const int kq   = lane & 3;
    const int wm   = wid & 3;
    const int wn   = wid >> 2;
    const int row0 = blockIdx.y * 128;
    const int col0 = blockIdx.x * 128;

    const int sr = tid >> 2;
    const int sg = tid & 3;

    const int arow_l = ((lane >> 3) & 1)*8 + (lane & 7);
    const int acol_l = (lane >> 4)*8;
    const int brow_l = (lane >> 4)*8 + (lane & 7);
    const int bcol_l = ((lane >> 3) & 1)*8;
    uint32_t aoff[2], boff[2];
    #pragma unroll
    for (int mi = 0; mi < 2; mi++)
        aoff[mi] = ((wm*32 + mi*16 + arow_l)*RA_LD + acol_l)*2;
    #pragma unroll
    for (int pr = 0; pr < 2; pr++)
        boff[pr] = ((wn*32 + pr*16 + brow_l)*RA_LD + bcol_l)*2;
    uint32_t sAu[2] = { s2u(sAb[0]), s2u(sAb[1]) };
    uint32_t sBu[2] = { s2u(sBb[0]), s2u(sBb[1]) };

    float acc[2][4][4];
    #pragma unroll
    for (int i = 0; i < 2; i++)
        #pragma unroll
        for (int j = 0; j < 4; j++)
            #pragma unroll
            for (int u = 0; u < 4; u++) acc[i][j][u] = 0.f;

    int arow = row0 + sr; if (arow >= M)  arow = M - 1;
    int brow = col0 + sr; if (brow >= DD) brow = DD - 1;
    const __half* agp = A  + (size_t)arow*DDP + sg*16;
    const __half* bgp = Bt + (size_t)brow*DDP + sg*16;
    const uint32_t sAoff = (sr*RA_LD + sg*16)*2;

    auto ldchunk = [&](int k0, int buf) {
        cp16(sAu[buf] + sAoff,      agp + k0);
        cp16(sAu[buf] + sAoff + 16, agp + k0 + 8);
        cp16(sBu[buf] + sAoff,      bgp + k0);
        cp16(sBu[buf] + sAoff + 16, bgp + k0 + 8);
        CP_COMMIT();
    };
    auto compute = [&](int buf) {
        #pragma unroll
        for (int ks = 0; ks < KC/16; ks++) {
            uint32_t af[2][4], bf[2][4];
            ldsm4(af[0], sAu[buf] + aoff[0] + ks*32);
            ldsm4(af[1], sAu[buf] + aoff[1] + ks*32);
            ldsm4(bf[0], sBu[buf] + boff[0] + ks*32);
            ldsm4(bf[1], sBu[buf] + boff[1] + ks*32);
            #pragma unroll
            for (int mi = 0; mi < 2; mi++) {
                mma_f16(acc[mi][0], af[mi], &bf[0][0]);
                mma_f16(acc[mi][1], af[mi], &bf[0][2]);
                mma_f16(acc[mi][2], af[mi], &bf[1][0]);
                mma_f16(acc[mi][3], af[mi], &bf[1][2]);
            }
        }
    };

    ldchunk(0, 0);
    CP_WAIT0();
    __syncthreads();
    #pragma unroll 1
    for (int ch = 0; ch < DDP/KC; ch++) {
        if (ch + 1 < DDP/KC) ldchunk((ch + 1)*KC, (ch + 1) & 1);
        compute(ch & 1);
        if (ch + 1 < DDP/KC) {
            CP_WAIT0();
            __syncthreads();
        }
    }

    #pragma unroll
    for (int mi = 0; mi < 2; mi++) {
        #pragma unroll
        for (int h = 0; h < 2; h++) {
            int gm = row0 + wm*32 + mi*16 + gr + h*8;
            if (gm >= M) continue;
            #pragma unroll
            for (int ni = 0; ni < 4; ni++) {
                int gn = col0 + wn*32 + ni*8 + kq*2;
                if (gn < DD) {
                    *(uint32_t*)(C + (size_t)gm*DDP + gn) =
                        pack_h2(acc[mi][ni][2*h], acc[mi][ni][2*h + 1]);
                }
            }
        }
    }
}

// ---------------------------------------------------------------------------
// Sparse GCN aggregation, warp-per-dst (8 dst/block), fp16 h, grid.z classes.
// DDP/2 = 288 = 9*32: each lane owns exactly 9 half2 columns.
// layer 0: fp16 k-padded output (cols >= 264 written as 0)
// layer 1: fused head/tail projection (warp reduce + atomicAdd)
// ---------------------------------------------------------------------------
#define NH2  (DD/2)     // 264
#define NH2P (DDP/2)    // 288

__global__ void __launch_bounds__(256) k_spmm(
    const __half* __restrict__ hbase,
    __half* __restrict__ xbH,
    const float* __restrict__ deg,
    const float* __restrict__ bgcn,
    const float* __restrict__ Who,
    const float* __restrict__ Wto,
    float* __restrict__ hW,
    float* __restrict__ hT,
    int layer)
{
    int wid  = threadIdx.x >> 5;
    int lane = threadIdx.x & 31;
    int dst  = blockIdx.x*8 + wid;
    if (dst >= NN1) return;
    int b   = blockIdx.y;
    int cls = blockIdx.z;
    int cb  = cls*BB + b;

    const float* bias = bgcn + (size_t)(cls*NLAY + layer)*DD;
    const __half* hb  = hbase + ((size_t)cls*MM + (size_t)b*NN1)*DDP;

    const int* off = g_off + cb*(NN1+1);
    int e0 = off[dst], e1 = off[dst+1];
    const int*   es = g_esrc  + cb*EE;
    const float* ec = g_ecoef + cb*EE;

    float2 acc[9];
    #pragma unroll
    for (int it = 0; it < 9; it++) acc[it] = make_float2(0.f, 0.f);

    for (int e = e0; e < e1; e++) {
        int   src = es[e];
        float w   = ec[e];
        const __half2* hr = (const __half2*)(hb + (size_t)src*DDP);
        #pragma unroll
        for (int it = 0; it < 9; it++) {
            int j = lane + it*32;
            if (j < NH2) {
                float2 x = __half22float2(hr[j]);
                acc[it].x += w * x.x;
                acc[it].y += w * x.y;
            }
        }
    }

    float dinv = 1.f / deg[cb*NN1 + dst];
    const __half2* hd = (const __half2*)(hb + (size_t)dst*DDP);

    float2 v[9];
    #pragma unroll
    for (int it = 0; it < 9; it++) {
        int j = lane + it*32;
        if (j < NH2) {
            float2 s = __half22float2(hd[j]);
            float2 bi = *(const float2*)(bias + 2*j);
            v[it].x = acc[it].x + s.x*dinv + bi.x;
            v[it].y = acc[it].y + s.y*dinv + bi.y;
        } else {
            v[it] = make_float2(0.f, 0.f);
        }
    }

    if (layer == 0) {
        __half* xo = xbH + ((size_t)cls*MM + (size_t)b*NN1 + dst)*DDP;
        #pragma unroll
        for (int it = 0; it < 9; it++) {
            int j = lane + it*32;
            *(uint32_t*)(xo + 2*j) = pack_h2(v[it].x, v[it].y);   // j<288 always
        }
        return;
    }

    // layer 1: fused projection, warp-local reduce
    float lw[3] = {0.f, 0.f, 0.f}, lt[3] = {0.f, 0.f, 0.f};
    #pragma unroll
    for (int it = 0; it < 9; it++) {
        int j = lane + it*32;
        if (j < NH2) {
            #pragma unroll
            for (int c = 0; c < 3; c++) {
                lw[c] += v[it].x*Who[(2*j)*3 + c] + v[it].y*Who[(2*j + 1)*3 + c];
                lt[c] += v[it].x*Wto[(2*j)*3 + c] + v[it].y*Wto[(2*j + 1)*3 + c];
            }
        }
    }
    #pragma unroll
    for (int d = 16; d > 0; d >>= 1) {
        #pragma unroll
        for (int c = 0; c < 3; c++) {
            lw[c] += __shfl_down_sync(0xffffffffu, lw[c], d);
            lt[c] += __shfl_down_sync(0xffffffffu, lt[c], d);
        }
    }
    if (lane == 0) {
        int idx = (b*NN1 + dst)*3;
        #pragma unroll
        for (int c = 0; c < 3; c++) {
            atomicAdd(&hW[idx + c], lw[c] * (1.f/3.f));
            atomicAdd(&hT[idx + c], lt[c] * (1.f/3.f));
        }
    }
}

// ---------------------------------------------------------------------------
// Collapsed head/tail weights + logits
// ---------------------------------------------------------------------------
__global__ void k_ho(const float* __restrict__ W_head, const float* __restrict__ W_tail,
                     const float* __restrict__ W_out,
                     const float* __restrict__ b_head, const float* __restrict__ b_tail,
                     float* __restrict__ Who, float* __restrict__ Wto,
                     float* __restrict__ bho, float* __restrict__ bto) {
    int t = blockIdx.x * blockDim.x + threadIdx.x;
    if (t < 2*DD*3) {
        int which = t / (DD*3), rc = t % (DD*3), r = rc / 3, c = rc % 3;
        const float* W = which ? W_tail : W_head;
        float acc = 0.f;
        for (int j = 0; j < DD; j++) acc += W[r*DD + j] * W_out[j*3 + c];
        (which ? Wto : Who)[r*3 + c] = acc;
    } else if (t < 2*DD*3 + 6) {
        int u = t - 2*DD*3, which = u / 3, c = u % 3;
        const float* bb = which ? b_tail : b_head;
        float acc = 0.f;
        for (int j = 0; j < DD; j++) acc += bb[j] * W_out[j*3 + c];
        (which ? bto : bho)[c] = acc;
    }
}

__global__ void k_logits(const int* __restrict__ cands,
                         const float* __restrict__ hW, const float* __restrict__ hT,
                         const float* __restrict__ bho, const float* __restrict__ bto,
                         const float* __restrict__ b_out,
                         float* __restrict__ out) {
    int t = blockIdx.x * blockDim.x + threadIdx.x;
    const int TOT = BB*NN1*(NN1-1)*3;
    if (t >= TOT) return;
    int c = t % 3;
    int j = (t / 3) & 255;
    int i = (t / (3*256)) % NN1;
    int b = t / (3*256*NN1);
    int m = cands[((long long)(b*NN1 + i))*NN1 + j + 1];
    float v = b_out[c];
    if (m) v += hW[(b*NN1 + i)*3 + c] + bho[c] + hT[(b*NN1 + j + 1)*3 + c] + bto[c];
    out[t] = v;
}

// ---------------------------------------------------------------------------
// Launch (multi-stream fork/join, graph-capturable)
// ---------------------------------------------------------------------------
extern "C" void kernel_launch(void* const* d_in, const int* in_sizes, int n_in,
                              void* d_out, int out_size) {
    const float* emb     = (const float*)d_in[0];
    const int*   entIdx  = (const int*)  d_in[1];
    const int*   entLab  = (const int*)  d_in[2];
    const int*   edgeIdx = (const int*)  d_in[3];
    const int*   edgeAttr= (const int*)  d_in[4];
    const int*   cands   = (const int*)  d_in[5];
    const float* W_red   = (const float*)d_in[6];
    const float* b_red   = (const float*)d_in[7];
    const float* tbl     = (const float*)d_in[8];
    const float* W_gcn   = (const float*)d_in[9];
    const float* b_gcn   = (const float*)d_in[10];
    const float* W_head  = (const float*)d_in[11];
    const float* b_head  = (const float*)d_in[12];
    const float* W_tail  = (const float*)d_in[13];
    const float* b_tail  = (const float*)d_in[14];
    const float* W_out   = (const float*)d_in[15];
    const float* b_out   = (const float*)d_in[16];
    float* out = (float*)d_out;

    static float *px0=nullptr, *pdeg,
                 *pWho, *pWto, *pbho, *pbto, *phW, *phT;
    static __half *pWt, *pWg, *pEh, *px0h, *pxb16, *phc;
    static cudaStream_t s2 = nullptr, s3 = nullptr;
    static cudaEvent_t evFork = nullptr, evJ2 = nullptr, evJ3a = nullptr, evJ3b = nullptr;
    static bool attr_set = false;
    if (!px0) {
        cudaGetSymbolAddress((void**)&px0,   g_x0);
        cudaGetSymbolAddress((void**)&px0h,  g_x0h);
        cudaGetSymbolAddress((void**)&phc,   g_hc);
        cudaGetSymbolAddress((void**)&pxb16, g_xb16);
        cudaGetSymbolAddress((void**)&pdeg,  g_deg);
        cudaGetSymbolAddress((void**)&pWt,   g_Wt);
        cudaGetSymbolAddress((void**)&pWg,   g_Wg);
        cudaGetSymbolAddress((void**)&pEh,   g_embh);
        cudaGetSymbolAddress((void**)&pWho,  g_Who);
        cudaGetSymbolAddress((void**)&pWto,  g_Wto);
        cudaGetSymbolAddress((void**)&pbho,  g_bho);
        cudaGetSymbolAddress((void**)&pbto,  g_bto);
        cudaGetSymbolAddress((void**)&phW,   g_hW);
        cudaGetSymbolAddress((void**)&phT,   g_hT);
        cudaStreamCreateWithFlags(&s2, cudaStreamNonBlocking);
        cudaStreamCreateWithFlags(&s3, cudaStreamNonBlocking);
        cudaEventCreateWithFlags(&evFork, cudaEventDisableTiming);
        cudaEventCreateWithFlags(&evJ2,   cudaEventDisableTiming);
        cudaEventCreateWithFlags(&evJ3a,  cudaEventDisableTiming);
        cudaEventCreateWithFlags(&evJ3b,  cudaEventDisableTiming);
    }
    if (!attr_set) {
        cudaFuncSetAttribute(k_mma_red, cudaFuncAttributeMaxDynamicSharedMemorySize, RED_SMEM);
        cudaFuncSetAttribute(k_mma_xw,  cudaFuncAttributeMaxDynamicSharedMemorySize, RED_SMEM);
        attr_set = true;
    }

    auto blocks = [](int n) { return (n + 255) / 256; };
    const int EH_TOT4  = BB*SS*ETRD/4;      // float4 count
    const int EH_HALF4 = EH_TOT4/2;

    // ---- fork ----
    cudaEventRecord(evFork, 0);
    cudaStreamWaitEvent(s2, evFork, 0);
    cudaStreamWaitEvent(s3, evFork, 0);

    // s2: CSR chain + Wg transpose + collapsed head/tail
    k_initmisc<<<blocks(HWSZ), 256, 0, s2>>>(pdeg, phW, phT);
    k_deg     <<<blocks(BB*EE), 256, 0, s2>>>(pdeg, edgeIdx, edgeAttr);
    k_off     <<<CBSZ, 32, 0, s2>>>(pdeg);
    k_scatter <<<blocks(BB*EE), 256, 0, s2>>>(pdeg, edgeIdx, edgeAttr);
    {
        dim3 bl(32, 32);
        k_th<<<dim3(DDP/32, (DD+31)/32, NCLS*NLAY), bl, 0, s2>>>(W_gcn, pWg, DD, DD, DDP);
    }
    k_ho<<<blocks(2*DD*3 + 6), 256, 0, s2>>>(W_head, W_tail, W_out, b_head, b_tail,
                                             pWho, pWto, pbho, pbto);
    cudaEventRecord(evJ2, s2);

    // s3: x0 init + W_red transpose (gates first GEMM half) then emb half 2
    k_initx0<<<blocks(XSZ), 256, 0, s3>>>(px0, entLab, tbl);
    {
        dim3 bl(32, 32);
        k_th<<<dim3(ETRD/32, HH/32, 1), bl, 0, s3>>>(W_red, pWt, ETRD, HH, ETRD);
    }
    cudaEventRecord(evJ3a, s3);
    k_eh<<<blocks(EH_HALF4), 256, 0, s3>>>((const float4*)emb + EH_HALF4,
                                           (uint2*)pEh + EH_HALF4, EH_HALF4);
    cudaEventRecord(evJ3b, s3);

    // main: emb half 1 convert -> first GEMM half; second half after join
    k_eh<<<blocks(EH_HALF4), 256>>>((const float4*)emb, (uint2*)pEh, EH_HALF4);
    cudaStreamWaitEvent(0, evJ3a, 0);     // x0 + Wt ready
    {
        dim3 g(HH/128, 128);              // y-blocks [0,128) -> rows [0,16384)
        k_mma_red<<<g, 512, RED_SMEM>>>(pEh, pWt, b_red, entIdx, px0, 0);
    }
    cudaStreamWaitEvent(0, evJ3b, 0);     // emb half 2 converted
    {
        dim3 g(HH/128, 128);              // y-blocks [128,256)
        k_mma_red<<<g, 512, RED_SMEM>>>(pEh, pWt, b_red, entIdx, px0, 128);
    }
    k_x0h<<<blocks(MM*DDP), 256>>>(px0, px0h);

    cudaStreamWaitEvent(0, evJ2, 0);      // CSR, Wg, Who/Wto, hW/hT ready

    // GCN: 2 layers, all 3 classes per launch; layer 1 fuses head/tail proj
    {
        dim3 gx((DD + 127)/128, (MM + 127)/128, NCLS);
        dim3 gs((NN1 + 7)/8, BB, NCLS);   // warp-per-dst spmm
        k_mma_xw<<<gx, 512, RED_SMEM>>>(px0h, pWg, phc, MM, 0LL, 0);
        k_spmm  <<<gs, 256>>>(phc, pxb16, pdeg, b_gcn, pWho, pWto, phW, phT, 0);
        k_mma_xw<<<gx, 512, RED_SMEM>>>(pxb16, pWg, phc, MM, (long long)MM*DDP, 1);
        k_spmm  <<<gs, 256>>>(phc, nullptr, pdeg, b_gcn, pWho, pWto, phW, phT, 1);
    }

    // logits
    k_logits<<<blocks(BB*NN1*(NN1-1)*3), 256>>>(cands, phW, phT, pbho, pbto, b_out, out);
}